// round 7
// baseline (speedup 1.0000x reference)
#include <cuda_runtime.h>
#include <cuda_fp16.h>
#include <math.h>
#include <stdint.h>

// Problem dims
#define I_IMG 32
#define C_CAP 32
#define Q_RGN 36
#define L_MAX 50
#define D_EMB 1024
#define M_TOT (C_CAP * I_IMG * Q_RGN)          // 36864
#define ELEMS ((size_t)M_TOT * D_EMB)          // 37,748,736
#define W_ELEMS (D_EMB * D_EMB)

// ---------------- scratch (device globals; allocation-free) ----------------
__device__ __align__(256) __half g_weiH[ELEMS];
__device__ __align__(256) __half g_weiL[ELEMS];
__device__ __align__(256) __half g_xH[ELEMS];
__device__ __align__(256) __half g_xL[ELEMS];
__device__ __align__(256) __half g_hH[ELEMS];
__device__ __align__(256) __half g_hL[ELEMS];
__device__ __align__(256) __half g_wH[4][W_ELEMS];
__device__ __align__(256) __half g_wL[4][W_ELEMS];

__device__ __forceinline__ void split_h(float x, __half& h, __half& l) {
    h = __float2half_rn(x);
    l = __float2half_rn(x - __half2float(h));
}

// ---------------------------------------------------------------------------
// K1: per-(c,i) fused attention -> wei (fp16 hi/lo).  288 threads.
// Stage 1 register-blocked (2l x 4q, float4 LDS); stage 3 smem-tiled.
// ---------------------------------------------------------------------------
__global__ __launch_bounds__(288) void attn_wei_kernel(
    const float* __restrict__ rgn, const float* __restrict__ wrd,
    const int* __restrict__ lens,
    __half* __restrict__ weiH, __half* __restrict__ weiL)
{
    const int i = blockIdx.x;
    const int c = blockIdx.y;
    const int tid = threadIdx.x;

    // float4 LDS requires 16B base alignment (smem arrays default to 4B!)
    __shared__ __align__(16) float sW[L_MAX][40];
    __shared__ __align__(16) float sR[Q_RGN][40];
    __shared__ __align__(16) float sS[L_MAX][Q_RGN + 1];
    __shared__ __align__(16) float sWd[L_MAX][68];

    const float* wrdC = wrd + (size_t)c * L_MAX * D_EMB;
    const float* rgnI = rgn + (size_t)i * Q_RGN * D_EMB;

    // ---- stage 1: s[l][q] = wrd[c,l,:] . rgn[i,q,:], 2l x 4q per thread ----
    const bool act = tid < 225;                 // 25 l-tiles x 9 q-tiles
    const int lt = tid / 9, qt = tid - 9 * (tid / 9);
    float acc[2][4];
#pragma unroll
    for (int a = 0; a < 2; a++)
#pragma unroll
        for (int b = 0; b < 4; b++) acc[a][b] = 0.f;

    for (int d0 = 0; d0 < D_EMB; d0 += 32) {
        __syncthreads();
        for (int f = tid; f < L_MAX * 32; f += 288) {
            int r = f >> 5, dd = f & 31;
            sW[r][dd] = wrdC[r * D_EMB + d0 + dd];
        }
        for (int f = tid; f < Q_RGN * 32; f += 288) {
            int r = f >> 5, dd = f & 31;
            sR[r][dd] = rgnI[r * D_EMB + d0 + dd];
        }
        __syncthreads();
        if (act) {
#pragma unroll
            for (int dd4 = 0; dd4 < 8; dd4++) {
                float4 w0 = *(const float4*)&sW[2 * lt][dd4 * 4];
                float4 w1 = *(const float4*)&sW[2 * lt + 1][dd4 * 4];
#pragma unroll
                for (int j = 0; j < 4; j++) {
                    float4 rv = *(const float4*)&sR[4 * qt + j][dd4 * 4];
                    acc[0][j] += w0.x * rv.x + w0.y * rv.y + w0.z * rv.z + w0.w * rv.w;
                    acc[1][j] += w1.x * rv.x + w1.y * rv.y + w1.z * rv.z + w1.w * rv.w;
                }
            }
        }
    }
    __syncthreads();

    if (act) {
#pragma unroll
        for (int a = 0; a < 2; a++)
#pragma unroll
            for (int b = 0; b < 4; b++) {
                float v = acc[a][b];
                sS[2 * lt + a][4 * qt + b] = (v >= 0.f) ? v : 0.1f * v;
            }
    }
    __syncthreads();

    // L2-normalize each l row over q
    if (tid < L_MAX) {
        float ss = 0.f;
        for (int q = 0; q < Q_RGN; q++) { float v = sS[tid][q]; ss += v * v; }
        float inv = 1.f / fmaxf(sqrtf(ss), 1e-12f);
        for (int q = 0; q < Q_RGN; q++) sS[tid][q] *= inv;
    }
    __syncthreads();

    const int len = lens[c];

    // masked softmax over l (temperature 9), per q column
    if (tid < Q_RGN) {
        float mx = -1e30f;
        for (int l = 0; l < len; l++) mx = fmaxf(mx, sS[l][tid]);
        float sum = 0.f;
        for (int l = 0; l < len; l++) sum += expf(9.f * (sS[l][tid] - mx));
        float invs = 1.f / sum;
        for (int l = 0; l < len; l++)
            sS[l][tid] = expf(9.f * (sS[l][tid] - mx)) * invs;
    }
    __syncthreads();

    // ---- stage 3: wei[q][d] = sum_l attn[l][q] * wrd[l][d], smem-tiled ----
    const int q3 = tid >> 3;              // 0..35
    const int d8 = (tid & 7) * 8;
    const size_t obase = ((size_t)(c * I_IMG + i)) * Q_RGN * D_EMB;

    for (int d0 = 0; d0 < D_EMB; d0 += 64) {
        __syncthreads();
        for (int f = tid; f < L_MAX * 64; f += 288) {
            int r = f >> 6, dd = f & 63;
            sWd[r][dd] = wrdC[r * D_EMB + d0 + dd];
        }
        __syncthreads();
        float a[8];
#pragma unroll
        for (int j = 0; j < 8; j++) a[j] = 0.f;
        for (int l = 0; l < len; l++) {
            float s = sS[l][q3];
            float4 w0 = *(const float4*)&sWd[l][d8];
            float4 w1 = *(const float4*)&sWd[l][d8 + 4];
            a[0] += s * w0.x; a[1] += s * w0.y; a[2] += s * w0.z; a[3] += s * w0.w;
            a[4] += s * w1.x; a[5] += s * w1.y; a[6] += s * w1.z; a[7] += s * w1.w;
        }
        union { uint4 u; __half h[8]; } uh, ul;
#pragma unroll
        for (int j = 0; j < 8; j++) split_h(a[j], uh.h[j], ul.h[j]);
        size_t off = obase + (size_t)q3 * D_EMB + d0 + d8;
        *(uint4*)(weiH + off) = uh.u;
        *(uint4*)(weiL + off) = ul.u;
    }
}

// ---------------------------------------------------------------------------
// weight split: fp32 -> fp16 hi/lo
// ---------------------------------------------------------------------------
__global__ __launch_bounds__(256) void split_kernel(
    const float* __restrict__ s, __half* __restrict__ h,
    __half* __restrict__ l, int n)
{
    int i = blockIdx.x * 256 + threadIdx.x;
    if (i < n) {
        __half hh, ll;
        split_h(s[i], hh, ll);
        h[i] = hh; l[i] = ll;
    }
}

// ---------------------------------------------------------------------------
// HMMA GEMM infrastructure (fp16x2 compensated, 3 products, fp32 accum)
// ---------------------------------------------------------------------------
#define BK 32
#define TILE_B 8192                 // 128 rows x 64 bytes
#define NSTAGE 3
#define NITER (D_EMB / BK)          // 32

__device__ __forceinline__ uint32_t smem_u32(const void* p) {
    uint32_t a;
    asm("{ .reg .u64 t; cvta.to.shared.u64 t, %1; cvt.u32.u64 %0, t; }"
        : "=r"(a) : "l"(p));
    return a;
}
__device__ __forceinline__ uint32_t sm_addr(uint32_t base, int row, int c16) {
    return base + row * 64 + (((uint32_t)(c16 ^ ((row >> 1) & 3))) << 4);
}
__device__ __forceinline__ void load_tile(
    const __half* __restrict__ g, int row0, int kcol0, uint32_t sb, int tid)
{
#pragma unroll
    for (int j = 0; j < 2; j++) {
        int id = tid + 256 * j;        // 0..511
        int r = id >> 2, c = id & 3;
        const void* gp = g + (size_t)(row0 + r) * D_EMB + kcol0 + c * 8;
        uint32_t sa = sm_addr(sb, r, c);
        asm volatile("cp.async.cg.shared.global [%0], [%1], 16;" :: "r"(sa), "l"(gp));
    }
}

#define LDSM_X4(R, addr) \
    asm volatile("ldmatrix.sync.aligned.m8n8.x4.shared.b16 {%0,%1,%2,%3}, [%4];" \
        : "=r"((R)[0]), "=r"((R)[1]), "=r"((R)[2]), "=r"((R)[3]) : "r"(addr))
#define MMA(C, A, B) \
    asm volatile("mma.sync.aligned.m16n8k16.row.col.f32.f16.f16.f32 " \
        "{%0,%1,%2,%3}, {%4,%5,%6,%7}, {%8,%9}, {%0,%1,%2,%3};" \
        : "+f"((C)[0]), "+f"((C)[1]), "+f"((C)[2]), "+f"((C)[3]) \
        : "r"((A)[0]), "r"((A)[1]), "r"((A)[2]), "r"((A)[3]), "r"((B)[0]), "r"((B)[1]))

// load all B fragments for one weight stream (hi+lo) at one ks, then MMA
#define B_FRAGS_MMA(c_acc, aH, aL, tileH, tileL) do {                          \
    uint32_t bH[8][2], bL[8][2];                                               \
    _Pragma("unroll")                                                          \
    for (int p = 0; p < 4; p++) {                                              \
        uint32_t r[4];                                                         \
        LDSM_X4(r, sm_addr(tileH, wn * 64 + p * 16 + b_ro, ks * 2 + b_co));    \
        bH[2*p][0] = r[0]; bH[2*p][1] = r[1];                                  \
        bH[2*p+1][0] = r[2]; bH[2*p+1][1] = r[3];                              \
        LDSM_X4(r, sm_addr(tileL, wn * 64 + p * 16 + b_ro, ks * 2 + b_co));    \
        bL[2*p][0] = r[0]; bL[2*p][1] = r[1];                                  \
        bL[2*p+1][0] = r[2]; bL[2*p+1][1] = r[3];                              \
    }                                                                          \
    _Pragma("unroll")                                                          \
    for (int mi = 0; mi < 2; mi++)                                             \
        _Pragma("unroll")                                                      \
        for (int nj = 0; nj < 8; nj++) {                                       \
            MMA(c_acc[mi][nj], aH[mi], bH[nj]);                                \
            MMA(c_acc[mi][nj], aH[mi], bL[nj]);                                \
            MMA(c_acc[mi][nj], aL[mi], bH[nj]);                                \
        }                                                                      \
} while (0)

// ---------------------------------------------------------------------------
// Dual GEMM + FiLM: computes sc = wei@w_scale^T+b_sc, sh = wei@w_shift^T+b_sh,
// then x = rgn*tanh(sc) + sh, split fp16 hi/lo to xH/xL.
// ---------------------------------------------------------------------------
#define DSTAGE_B (6 * TILE_B)              // Ah, Al, BscH, BscL, BshH, BshL
#define DSMEM (NSTAGE * DSTAGE_B)          // 144 KB

__global__ __launch_bounds__(256, 1) void gemm_dual_film(
    const __half* __restrict__ Ah, const __half* __restrict__ Al,
    const __half* __restrict__ BscH, const __half* __restrict__ BscL,
    const __half* __restrict__ BshH, const __half* __restrict__ BshL,
    const float* __restrict__ bias_sc, const float* __restrict__ bias_sh,
    const float* __restrict__ rgn,
    __half* __restrict__ outH, __half* __restrict__ outL)
{
    extern __shared__ __align__(1024) uint8_t dsm[];
    const uint32_t sb = smem_u32(dsm);

    const int tid = threadIdx.x;
    const int wid = tid >> 5;
    const int lid = tid & 31;
    const int wm = wid & 3;
    const int wn = wid >> 2;
    const int m0 = blockIdx.y * 128;
    const int n0 = blockIdx.x * 128;

    const int a_ro = lid & 15;
    const int a_co = lid >> 4;
    const int b_ro = ((lid >> 4) & 1) * 8 + (lid & 7);
    const int b_co = (lid >> 3) & 1;

    float csc[2][8][4], csh[2][8][4];
#pragma unroll
    for (int a = 0; a < 2; a++)
#pragma unroll
        for (int b = 0; b < 8; b++)
#pragma unroll
            for (int d = 0; d < 4; d++) { csc[a][b][d] = 0.f; csh[a][b][d] = 0.f; }

#pragma unroll
    for (int s = 0; s < 2; s++) {
        uint32_t st = sb + s * DSTAGE_B;
        load_tile(Ah,   m0, s * BK, st + 0 * TILE_B, tid);
        load_tile(Al,   m0, s * BK, st + 1 * TILE_B, tid);
        load_tile(BscH, n0, s * BK, st + 2 * TILE_B, tid);
        load_tile(BscL, n0, s * BK, st + 3 * TILE_B, tid);
        load_tile(BshH, n0, s * BK, st + 4 * TILE_B, tid);
        load_tile(BshL, n0, s * BK, st + 5 * TILE_B, tid);
        asm volatile("cp.async.commit_group;");
    }

    int stage = 0;
    for (int i = 0; i < NITER; i++) {
        asm volatile("cp.async.wait_group 1;");
        __syncthreads();

        if (i + 2 < NITER) {
            uint32_t st = sb + ((stage + 2) % NSTAGE) * DSTAGE_B;
            int kc = (i + 2) * BK;
            load_tile(Ah,   m0, kc, st + 0 * TILE_B, tid);
            load_tile(Al,   m0, kc, st + 1 * TILE_B, tid);
            load_tile(BscH, n0, kc, st + 2 * TILE_B, tid);
            load_tile(BscL, n0, kc, st + 3 * TILE_B, tid);
            load_tile(BshH, n0, kc, st + 4 * TILE_B, tid);
            load_tile(BshL, n0, kc, st + 5 * TILE_B, tid);
        }
        asm volatile("cp.async.commit_group;");

        uint32_t stA = sb + stage * DSTAGE_B;
#pragma unroll
        for (int ks = 0; ks < 2; ks++) {
            uint32_t aH[2][4], aL[2][4];
#pragma unroll
            for (int mi = 0; mi < 2; mi++) {
                LDSM_X4(aH[mi], sm_addr(stA + 0 * TILE_B, wm * 32 + mi * 16 + a_ro, ks * 2 + a_co));
                LDSM_X4(aL[mi], sm_addr(stA + 1 * TILE_B, wm * 32 + mi * 16 + a_ro, ks * 2 + a_co));
            }
            B_FRAGS_MMA(csc, aH, aL, stA + 2 * TILE_B, stA + 3 * TILE_B);
            B_FRAGS_MMA(csh, aH, aL, stA + 4 * TILE_B, stA + 5 * TILE_B);
        }
        stage = (stage + 1) % NSTAGE;
    }

    // epilogue: x = rgn * tanh(sc + b_sc) + (sh + b_sh)
    const int nbase = n0 + wn * 64;
    const int mbase = m0 + wm * 32;
    const int cph = (lid & 3) * 2;

    float2 bscv[8], bshv[8];
#pragma unroll
    for (int nj = 0; nj < 8; nj++) {
        bscv[nj] = *(const float2*)(bias_sc + nbase + nj * 8 + cph);
        bshv[nj] = *(const float2*)(bias_sh + nbase + nj * 8 + cph);
    }

#pragma unroll
    for (int mi = 0; mi < 2; mi++) {
#pragma unroll
        for (int hf = 0; hf < 2; hf++) {
            const int m = mbase + mi * 16 + hf * 8 + (lid >> 2);
            const int t = m / Q_RGN;
            const int q = m - t * Q_RGN;
            const int i_img = t & (I_IMG - 1);
            const float* rp = rgn + ((size_t)(i_img * Q_RGN + q)) * D_EMB + nbase + cph;
            size_t ob = (size_t)m * D_EMB + nbase + cph;
#pragma unroll
            for (int nj = 0; nj < 8; nj++) {
                float2 rv = *(const float2*)(rp + nj * 8);
                float sc0 = tanhf(csc[mi][nj][hf * 2 + 0] + bscv[nj].x);
                float sc1 = tanhf(csc[mi][nj][hf * 2 + 1] + bscv[nj].y);
                float x0 = rv.x * sc0 + (csh[mi][nj][hf * 2 + 0] + bshv[nj].x);
                float x1 = rv.y * sc1 + (csh[mi][nj][hf * 2 + 1] + bshv[nj].y);
                __half h0, l0, h1, l1;
                split_h(x0, h0, l0); split_h(x1, h1, l1);
                *(__half2*)(outH + ob + nj * 8) = __halves2half2(h0, h1);
                *(__half2*)(outL + ob + nj * 8) = __halves2half2(l0, l1);
            }
        }
    }
}

// ---------------------------------------------------------------------------
// Single GEMM (RELU -> fp16 hi/lo, FINAL -> fp32 + rgn + transpose)
// ---------------------------------------------------------------------------
#define EPI_RELU 2
#define EPI_FINAL 3
#define SSTAGE_B (4 * TILE_B)
#define SSMEM (NSTAGE * SSTAGE_B)          // 96 KB

template <int EPI>
__global__ __launch_bounds__(256, 1) void gemm_hmma(
    const __half* __restrict__ Ah, const __half* __restrict__ Al,
    const __half* __restrict__ Bh, const __half* __restrict__ Bl,
    const float* __restrict__ bias,
    const float* __restrict__ rgn,
    float* __restrict__ outF,
    __half* __restrict__ outH, __half* __restrict__ outL)
{
    extern __shared__ __align__(1024) uint8_t dsm[];
    const uint32_t sb = smem_u32(dsm);

    const int tid = threadIdx.x;
    const int wid = tid >> 5;
    const int lid = tid & 31;
    const int wm = wid & 3;
    const int wn = wid >> 2;
    const int m0 = blockIdx.y * 128;
    const int n0 = blockIdx.x * 128;

    const int a_ro = lid & 15;
    const int a_co = lid >> 4;
    const int b_ro = ((lid >> 4) & 1) * 8 + (lid & 7);
    const int b_co = (lid >> 3) & 1;

    float c[2][8][4];
#pragma unroll
    for (int a = 0; a < 2; a++)
#pragma unroll
        for (int b = 0; b < 8; b++)
#pragma unroll
            for (int d = 0; d < 4; d++) c[a][b][d] = 0.f;

#pragma unroll
    for (int s = 0; s < 2; s++) {
        uint32_t st = sb + s * SSTAGE_B;
        load_tile(Ah, m0, s * BK, st + 0 * TILE_B, tid);
        load_tile(Al, m0, s * BK, st + 1 * TILE_B, tid);
        load_tile(Bh, n0, s * BK, st + 2 * TILE_B, tid);
        load_tile(Bl, n0, s * BK, st + 3 * TILE_B, tid);
        asm volatile("cp.async.commit_group;");
    }

    int stage = 0;
    for (int i = 0; i < NITER; i++) {
        asm volatile("cp.async.wait_group 1;");
        __syncthreads();

        if (i + 2 < NITER) {
            uint32_t st = sb + ((stage + 2) % NSTAGE) * SSTAGE_B;
            int kc = (i + 2) * BK;
            load_tile(Ah, m0, kc, st + 0 * TILE_B, tid);
            load_tile(Al, m0, kc, st + 1 * TILE_B, tid);
            load_tile(Bh, n0, kc, st + 2 * TILE_B, tid);
            load_tile(Bl, n0, kc, st + 3 * TILE_B, tid);
        }
        asm volatile("cp.async.commit_group;");

        uint32_t stA = sb + stage * SSTAGE_B;
#pragma unroll
        for (int ks = 0; ks < 2; ks++) {
            uint32_t aH[2][4], aL[2][4];
#pragma unroll
            for (int mi = 0; mi < 2; mi++) {
                LDSM_X4(aH[mi], sm_addr(stA + 0 * TILE_B, wm * 32 + mi * 16 + a_ro, ks * 2 + a_co));
                LDSM_X4(aL[mi], sm_addr(stA + 1 * TILE_B, wm * 32 + mi * 16 + a_ro, ks * 2 + a_co));
            }
            B_FRAGS_MMA(c, aH, aL, stA + 2 * TILE_B, stA + 3 * TILE_B);
        }
        stage = (stage + 1) % NSTAGE;
    }

    const int nbase = n0 + wn * 64;
    const int mbase = m0 + wm * 32;
    const int cph = (lid & 3) * 2;

    float2 bv[8];
#pragma unroll
    for (int nj = 0; nj < 8; nj++)
        bv[nj] = *(const float2*)(bias + nbase + nj * 8 + cph);

#pragma unroll
    for (int mi = 0; mi < 2; mi++) {
#pragma unroll
        for (int hf = 0; hf < 2; hf++) {
            const int m = mbase + mi * 16 + hf * 8 + (lid >> 2);
            const int t = m / Q_RGN;
            const int q = m - t * Q_RGN;
            const int i_img = t & (I_IMG - 1);
            const int cc = t >> 5;

            if (EPI == EPI_RELU) {
                size_t ob = (size_t)m * D_EMB + nbase + cph;
#pragma unroll
                for (int nj = 0; nj < 8; nj++) {
                    float x0 = fmaxf(c[mi][nj][hf * 2 + 0] + bv[nj].x, 0.f);
                    float x1 = fmaxf(c[mi][nj][hf * 2 + 1] + bv[nj].y, 0.f);
                    __half h0, l0, h1, l1;
                    split_h(x0, h0, l0); split_h(x1, h1, l1);
                    *(__half2*)(outH + ob + nj * 8) = __halves2half2(h0, h1);
                    *(__half2*)(outL + ob + nj * 8) = __halves2half2(l0, l1);
                }
            } else {  // EPI_FINAL
                const float* rp = rgn + ((size_t)(i_img * Q_RGN + q)) * D_EMB + nbase + cph;
                float* op = outF + (((size_t)(i_img * C_CAP + cc)) * Q_RGN + q) * D_EMB + nbase + cph;
#pragma unroll
                for (int nj = 0; nj < 8; nj++) {
                    float2 rv = *(const float2*)(rp + nj * 8);
                    float2 o;
                    o.x = c[mi][nj][hf * 2 + 0] + bv[nj].x + rv.x;
                    o.y = c[mi][nj][hf * 2 + 1] + bv[nj].y + rv.y;
                    *(float2*)(op + nj * 8) = o;
                }
            }
        }
    }
}

// ---------------------------------------------------------------------------
extern "C" void kernel_launch(void* const* d_in, const int* in_sizes, int n_in,
                              void* d_out, int out_size)
{
    const float* rgn     = (const float*)d_in[0];
    const float* wrd     = (const float*)d_in[2];
    const int*   lens    = (const int*)d_in[4];
    const float* w_scale = (const float*)d_in[5];
    const float* b_scale = (const float*)d_in[6];
    const float* w_shift = (const float*)d_in[7];
    const float* b_shift = (const float*)d_in[8];
    const float* w1      = (const float*)d_in[9];
    const float* b1      = (const float*)d_in[10];
    const float* w2      = (const float*)d_in[11];
    const float* b2      = (const float*)d_in[12];
    float* out = (float*)d_out;

    __half *weiH, *weiL, *xH, *xL, *hH, *hL, *wH, *wL;
    cudaGetSymbolAddress((void**)&weiH, g_weiH);
    cudaGetSymbolAddress((void**)&weiL, g_weiL);
    cudaGetSymbolAddress((void**)&xH,   g_xH);
    cudaGetSymbolAddress((void**)&xL,   g_xL);
    cudaGetSymbolAddress((void**)&hH,   g_hH);
    cudaGetSymbolAddress((void**)&hL,   g_hL);
    cudaGetSymbolAddress((void**)&wH,   g_wH);
    cudaGetSymbolAddress((void**)&wL,   g_wL);

    cudaFuncSetAttribute(gemm_dual_film,       cudaFuncAttributeMaxDynamicSharedMemorySize, DSMEM);
    cudaFuncSetAttribute(gemm_hmma<EPI_RELU>,  cudaFuncAttributeMaxDynamicSharedMemorySize, SSMEM);
    cudaFuncSetAttribute(gemm_hmma<EPI_FINAL>, cudaFuncAttributeMaxDynamicSharedMemorySize, SSMEM);

    // launches 0-3: weight splits (so ncu -s 5 lands on a GEMM)
    const float* ws[4] = { w_scale, w_shift, w1, w2 };
    for (int k = 0; k < 4; k++)
        split_kernel<<<(W_ELEMS + 255) / 256, 256>>>(ws[k], wH + (size_t)k * W_ELEMS,
                                                     wL + (size_t)k * W_ELEMS, W_ELEMS);

    // launch 4: attention + weighted context -> wei hi/lo
    attn_wei_kernel<<<dim3(I_IMG, C_CAP), 288>>>(rgn, wrd, lens, weiH, weiL);

    dim3 ggrid(D_EMB / 128, M_TOT / 128);   // (8, 288)

    // launch 5: dual GEMM (scale+shift) + FiLM -> x hi/lo
    gemm_dual_film<<<ggrid, 256, DSMEM>>>(
        weiH, weiL,
        wH + 0 * (size_t)W_ELEMS, wL + 0 * (size_t)W_ELEMS,
        wH + 1 * (size_t)W_ELEMS, wL + 1 * (size_t)W_ELEMS,
        b_scale, b_shift, rgn, xH, xL);
    // launch 6: h = relu(x @ w1^T + b1) -> h hi/lo
    gemm_hmma<EPI_RELU><<<ggrid, 256, SSMEM>>>(
        xH, xL, wH + 2 * (size_t)W_ELEMS, wL + 2 * (size_t)W_ELEMS,
        b1, nullptr, nullptr, hH, hL);
    // launch 7: out = (h @ w2^T + b2) + rgn, transposed (c,i)->(i,c)
    gemm_hmma<EPI_FINAL><<<ggrid, 256, SSMEM>>>(
        hH, hL, wH + 3 * (size_t)W_ELEMS, wL + 3 * (size_t)W_ELEMS,
        b2, rgn, out, nullptr, nullptr);
}

// round 8
// speedup vs baseline: 1.2341x; 1.2341x over previous
#include <cuda_runtime.h>
#include <cuda_fp16.h>
#include <math.h>
#include <stdint.h>

// Problem dims
#define I_IMG 32
#define C_CAP 32
#define Q_RGN 36
#define L_MAX 50
#define D_EMB 1024
#define M_TOT (C_CAP * I_IMG * Q_RGN)          // 36864
#define ELEMS ((size_t)M_TOT * D_EMB)          // 37,748,736
#define W_ELEMS (D_EMB * D_EMB)

// ---------------- scratch (device globals; allocation-free) ----------------
__device__ __align__(256) __half g_weiH[ELEMS];
__device__ __align__(256) __half g_xH[ELEMS];
__device__ __align__(256) __half g_hH[ELEMS];
__device__ __align__(256) float  g_scal[ELEMS];
__device__ __align__(256) __half g_wH[4][W_ELEMS];
__device__ __align__(256) __half g_wL[4][W_ELEMS];

__device__ __forceinline__ void split_h(float x, __half& h, __half& l) {
    h = __float2half_rn(x);
    l = __float2half_rn(x - __half2float(h));
}

// ---------------------------------------------------------------------------
// K1: per-(c,i) fused attention -> wei (fp16).  288 threads.
// ---------------------------------------------------------------------------
__global__ __launch_bounds__(288) void attn_wei_kernel(
    const float* __restrict__ rgn, const float* __restrict__ wrd,
    const int* __restrict__ lens, __half* __restrict__ weiH)
{
    const int i = blockIdx.x;
    const int c = blockIdx.y;
    const int tid = threadIdx.x;

    __shared__ __align__(16) float sW[L_MAX][40];
    __shared__ __align__(16) float sR[Q_RGN][40];
    __shared__ __align__(16) float sS[L_MAX][Q_RGN + 1];
    __shared__ __align__(16) float sWd[L_MAX][68];

    const float* wrdC = wrd + (size_t)c * L_MAX * D_EMB;
    const float* rgnI = rgn + (size_t)i * Q_RGN * D_EMB;

    // ---- stage 1: s[l][q] = wrd[c,l,:] . rgn[i,q,:], 2l x 4q per thread ----
    const bool act = tid < 225;
    const int lt = tid / 9, qt = tid - 9 * (tid / 9);
    float acc[2][4];
#pragma unroll
    for (int a = 0; a < 2; a++)
#pragma unroll
        for (int b = 0; b < 4; b++) acc[a][b] = 0.f;

    for (int d0 = 0; d0 < D_EMB; d0 += 32) {
        __syncthreads();
        for (int f = tid; f < L_MAX * 32; f += 288) {
            int r = f >> 5, dd = f & 31;
            sW[r][dd] = wrdC[r * D_EMB + d0 + dd];
        }
        for (int f = tid; f < Q_RGN * 32; f += 288) {
            int r = f >> 5, dd = f & 31;
            sR[r][dd] = rgnI[r * D_EMB + d0 + dd];
        }
        __syncthreads();
        if (act) {
#pragma unroll
            for (int dd4 = 0; dd4 < 8; dd4++) {
                float4 w0 = *(const float4*)&sW[2 * lt][dd4 * 4];
                float4 w1 = *(const float4*)&sW[2 * lt + 1][dd4 * 4];
#pragma unroll
                for (int j = 0; j < 4; j++) {
                    float4 rv = *(const float4*)&sR[4 * qt + j][dd4 * 4];
                    acc[0][j] += w0.x * rv.x + w0.y * rv.y + w0.z * rv.z + w0.w * rv.w;
                    acc[1][j] += w1.x * rv.x + w1.y * rv.y + w1.z * rv.z + w1.w * rv.w;
                }
            }
        }
    }
    __syncthreads();

    if (act) {
#pragma unroll
        for (int a = 0; a < 2; a++)
#pragma unroll
            for (int b = 0; b < 4; b++) {
                float v = acc[a][b];
                sS[2 * lt + a][4 * qt + b] = (v >= 0.f) ? v : 0.1f * v;
            }
    }
    __syncthreads();

    if (tid < L_MAX) {
        float ss = 0.f;
        for (int q = 0; q < Q_RGN; q++) { float v = sS[tid][q]; ss += v * v; }
        float inv = 1.f / fmaxf(sqrtf(ss), 1e-12f);
        for (int q = 0; q < Q_RGN; q++) sS[tid][q] *= inv;
    }
    __syncthreads();

    const int len = lens[c];

    if (tid < Q_RGN) {
        float mx = -1e30f;
        for (int l = 0; l < len; l++) mx = fmaxf(mx, sS[l][tid]);
        float sum = 0.f;
        for (int l = 0; l < len; l++) sum += expf(9.f * (sS[l][tid] - mx));
        float invs = 1.f / sum;
        for (int l = 0; l < len; l++)
            sS[l][tid] = expf(9.f * (sS[l][tid] - mx)) * invs;
    }
    __syncthreads();

    // ---- stage 3: wei[q][d] = sum_l attn[l][q] * wrd[l][d], smem-tiled ----
    const int q3 = tid >> 3;
    const int d8 = (tid & 7) * 8;
    const size_t obase = ((size_t)(c * I_IMG + i)) * Q_RGN * D_EMB;

    for (int d0 = 0; d0 < D_EMB; d0 += 64) {
        __syncthreads();
        for (int f = tid; f < L_MAX * 64; f += 288) {
            int r = f >> 6, dd = f & 63;
            sWd[r][dd] = wrdC[r * D_EMB + d0 + dd];
        }
        __syncthreads();
        float a[8];
#pragma unroll
        for (int j = 0; j < 8; j++) a[j] = 0.f;
        for (int l = 0; l < len; l++) {
            float s = sS[l][q3];
            float4 w0 = *(const float4*)&sWd[l][d8];
            float4 w1 = *(const float4*)&sWd[l][d8 + 4];
            a[0] += s * w0.x; a[1] += s * w0.y; a[2] += s * w0.z; a[3] += s * w0.w;
            a[4] += s * w1.x; a[5] += s * w1.y; a[6] += s * w1.z; a[7] += s * w1.w;
        }
        union { uint4 u; __half h[8]; } uh;
#pragma unroll
        for (int j = 0; j < 8; j++) uh.h[j] = __float2half_rn(a[j]);
        *(uint4*)(weiH + obase + (size_t)q3 * D_EMB + d0 + d8) = uh.u;
    }
}

// ---------------------------------------------------------------------------
// weight split: fp32 -> fp16 hi/lo
// ---------------------------------------------------------------------------
__global__ __launch_bounds__(256) void split_kernel(
    const float* __restrict__ s, __half* __restrict__ h,
    __half* __restrict__ l, int n)
{
    int i = blockIdx.x * 256 + threadIdx.x;
    if (i < n) {
        __half hh, ll;
        split_h(s[i], hh, ll);
        h[i] = hh; l[i] = ll;
    }
}

// ---------------------------------------------------------------------------
// HMMA GEMM: D[m,n] = epi( sum_k A[m,k] * W[n,k] + bias[n] )
// 2-term compensated: Ah*Bh + Ah*Bl (weights hi/lo, activations fp16).
// 128x128x32 tiles, 3-stage cp.async, mma.m16n8k16.
// ---------------------------------------------------------------------------
#define EPI_TANH 0
#define EPI_FILM 1
#define EPI_RELU 2
#define EPI_FINAL 3

#define BK 32
#define TILE_B 8192                 // 128 rows x 64 bytes
#define STAGE_B (3 * TILE_B)        // Ah, Bh, Bl
#define NSTAGE 3
#define SMEM_DYN (NSTAGE * STAGE_B) // 72 KB
#define NITER (D_EMB / BK)          // 32

__device__ __forceinline__ uint32_t smem_u32(const void* p) {
    uint32_t a;
    asm("{ .reg .u64 t; cvta.to.shared.u64 t, %1; cvt.u32.u64 %0, t; }"
        : "=r"(a) : "l"(p));
    return a;
}
__device__ __forceinline__ uint32_t sm_addr(uint32_t base, int row, int c16) {
    return base + row * 64 + (((uint32_t)(c16 ^ ((row >> 1) & 3))) << 4);
}
__device__ __forceinline__ void load_tile(
    const __half* __restrict__ g, int row0, int kcol0, uint32_t sb, int tid)
{
#pragma unroll
    for (int j = 0; j < 2; j++) {
        int id = tid + 256 * j;        // 0..511
        int r = id >> 2, c = id & 3;
        const void* gp = g + (size_t)(row0 + r) * D_EMB + kcol0 + c * 8;
        uint32_t sa = sm_addr(sb, r, c);
        asm volatile("cp.async.cg.shared.global [%0], [%1], 16;" :: "r"(sa), "l"(gp));
    }
}

#define LDSM_X4(R, addr) \
    asm volatile("ldmatrix.sync.aligned.m8n8.x4.shared.b16 {%0,%1,%2,%3}, [%4];" \
        : "=r"((R)[0]), "=r"((R)[1]), "=r"((R)[2]), "=r"((R)[3]) : "r"(addr))
#define MMA(C, A, B) \
    asm volatile("mma.sync.aligned.m16n8k16.row.col.f32.f16.f16.f32 " \
        "{%0,%1,%2,%3}, {%4,%5,%6,%7}, {%8,%9}, {%0,%1,%2,%3};" \
        : "+f"((C)[0]), "+f"((C)[1]), "+f"((C)[2]), "+f"((C)[3]) \
        : "r"((A)[0]), "r"((A)[1]), "r"((A)[2]), "r"((A)[3]), "r"((B)[0]), "r"((B)[1]))

template <int EPI>
__global__ __launch_bounds__(256, 1) void gemm_hmma(
    const __half* __restrict__ Ah,
    const __half* __restrict__ Bh, const __half* __restrict__ Bl,
    const float* __restrict__ bias,
    const float* __restrict__ scal,      // FILM input
    const float* __restrict__ rgn,       // FILM / FINAL
    float* __restrict__ outF,            // TANH (scal) / FINAL (d_out)
    __half* __restrict__ outH)           // FILM (x) / RELU (h)
{
    extern __shared__ __align__(1024) uint8_t dsm[];
    const uint32_t sb = smem_u32(dsm);

    const int tid = threadIdx.x;
    const int wid = tid >> 5;
    const int lid = tid & 31;
    const int wm = wid & 3;
    const int wn = wid >> 2;
    const int m0 = blockIdx.y * 128;
    const int n0 = blockIdx.x * 128;

    const int a_ro = lid & 15;
    const int a_co = lid >> 4;
    const int b_ro = ((lid >> 4) & 1) * 8 + (lid & 7);
    const int b_co = (lid >> 3) & 1;

    float c[2][8][4];
#pragma unroll
    for (int a = 0; a < 2; a++)
#pragma unroll
        for (int b = 0; b < 8; b++)
#pragma unroll
            for (int d = 0; d < 4; d++) c[a][b][d] = 0.f;

#pragma unroll
    for (int s = 0; s < 2; s++) {
        uint32_t st = sb + s * STAGE_B;
        load_tile(Ah, m0, s * BK, st + 0 * TILE_B, tid);
        load_tile(Bh, n0, s * BK, st + 1 * TILE_B, tid);
        load_tile(Bl, n0, s * BK, st + 2 * TILE_B, tid);
        asm volatile("cp.async.commit_group;");
    }

    int stage = 0;
    for (int i = 0; i < NITER; i++) {
        asm volatile("cp.async.wait_group 1;");
        __syncthreads();

        if (i + 2 < NITER) {
            uint32_t st = sb + ((stage + 2) % NSTAGE) * STAGE_B;
            int kc = (i + 2) * BK;
            load_tile(Ah, m0, kc, st + 0 * TILE_B, tid);
            load_tile(Bh, n0, kc, st + 1 * TILE_B, tid);
            load_tile(Bl, n0, kc, st + 2 * TILE_B, tid);
        }
        asm volatile("cp.async.commit_group;");

        uint32_t stA = sb + stage * STAGE_B;
#pragma unroll
        for (int ks = 0; ks < 2; ks++) {
            uint32_t aH[2][4], bH[8][2], bL[8][2];
#pragma unroll
            for (int mi = 0; mi < 2; mi++)
                LDSM_X4(aH[mi], sm_addr(stA + 0 * TILE_B, wm * 32 + mi * 16 + a_ro, ks * 2 + a_co));
#pragma unroll
            for (int p = 0; p < 4; p++) {
                uint32_t r[4];
                LDSM_X4(r, sm_addr(stA + 1 * TILE_B, wn * 64 + p * 16 + b_ro, ks * 2 + b_co));
                bH[2 * p][0] = r[0]; bH[2 * p][1] = r[1];
                bH[2 * p + 1][0] = r[2]; bH[2 * p + 1][1] = r[3];
                LDSM_X4(r, sm_addr(stA + 2 * TILE_B, wn * 64 + p * 16 + b_ro, ks * 2 + b_co));
                bL[2 * p][0] = r[0]; bL[2 * p][1] = r[1];
                bL[2 * p + 1][0] = r[2]; bL[2 * p + 1][1] = r[3];
            }
#pragma unroll
            for (int mi = 0; mi < 2; mi++)
#pragma unroll
                for (int nj = 0; nj < 8; nj++) {
                    MMA(c[mi][nj], aH[mi], bH[nj]);
                    MMA(c[mi][nj], aH[mi], bL[nj]);
                }
        }
        stage = (stage + 1) % NSTAGE;
    }

    // ---------------- epilogue ----------------
    const int nbase = n0 + wn * 64;
    const int mbase = m0 + wm * 32;
    const int cph = (lid & 3) * 2;

    float2 bv[8];
#pragma unroll
    for (int nj = 0; nj < 8; nj++)
        bv[nj] = *(const float2*)(bias + nbase + nj * 8 + cph);

#pragma unroll
    for (int mi = 0; mi < 2; mi++) {
#pragma unroll
        for (int hf = 0; hf < 2; hf++) {
            const int m = mbase + mi * 16 + hf * 8 + (lid >> 2);
            const int t = m / Q_RGN;
            const int q = m - t * Q_RGN;
            const int i_img = t & (I_IMG - 1);
            const int cc = t >> 5;

            if (EPI == EPI_TANH) {
                float* op = outF + (size_t)m * D_EMB + nbase + cph;
#pragma unroll
                for (int nj = 0; nj < 8; nj++) {
                    float2 o;
                    o.x = tanhf(c[mi][nj][hf * 2 + 0] + bv[nj].x);
                    o.y = tanhf(c[mi][nj][hf * 2 + 1] + bv[nj].y);
                    *(float2*)(op + nj * 8) = o;
                }
            } else if (EPI == EPI_FILM) {
                const float* rp = rgn + ((size_t)(i_img * Q_RGN + q)) * D_EMB + nbase + cph;
                const float* sp = scal + (size_t)m * D_EMB + nbase + cph;
                size_t ob = (size_t)m * D_EMB + nbase + cph;
#pragma unroll
                for (int nj = 0; nj < 8; nj++) {
                    float2 rv = *(const float2*)(rp + nj * 8);
                    float2 sv = *(const float2*)(sp + nj * 8);
                    float x0 = rv.x * sv.x + (c[mi][nj][hf * 2 + 0] + bv[nj].x);
                    float x1 = rv.y * sv.y + (c[mi][nj][hf * 2 + 1] + bv[nj].y);
                    *(__half2*)(outH + ob + nj * 8) =
                        __halves2half2(__float2half_rn(x0), __float2half_rn(x1));
                }
            } else if (EPI == EPI_RELU) {
                size_t ob = (size_t)m * D_EMB + nbase + cph;
#pragma unroll
                for (int nj = 0; nj < 8; nj++) {
                    float x0 = fmaxf(c[mi][nj][hf * 2 + 0] + bv[nj].x, 0.f);
                    float x1 = fmaxf(c[mi][nj][hf * 2 + 1] + bv[nj].y, 0.f);
                    *(__half2*)(outH + ob + nj * 8) =
                        __halves2half2(__float2half_rn(x0), __float2half_rn(x1));
                }
            } else {  // EPI_FINAL: out[(i,c,q),n] = acc + bias + rgn
                const float* rp = rgn + ((size_t)(i_img * Q_RGN + q)) * D_EMB + nbase + cph;
                float* op = outF + (((size_t)(i_img * C_CAP + cc)) * Q_RGN + q) * D_EMB + nbase + cph;
#pragma unroll
                for (int nj = 0; nj < 8; nj++) {
                    float2 rv = *(const float2*)(rp + nj * 8);
                    float2 o;
                    o.x = c[mi][nj][hf * 2 + 0] + bv[nj].x + rv.x;
                    o.y = c[mi][nj][hf * 2 + 1] + bv[nj].y + rv.y;
                    *(float2*)(op + nj * 8) = o;
                }
            }
        }
    }
}

// ---------------------------------------------------------------------------
extern "C" void kernel_launch(void* const* d_in, const int* in_sizes, int n_in,
                              void* d_out, int out_size)
{
    const float* rgn     = (const float*)d_in[0];
    const float* wrd     = (const float*)d_in[2];
    const int*   lens    = (const int*)d_in[4];
    const float* w_scale = (const float*)d_in[5];
    const float* b_scale = (const float*)d_in[6];
    const float* w_shift = (const float*)d_in[7];
    const float* b_shift = (const float*)d_in[8];
    const float* w1      = (const float*)d_in[9];
    const float* b1      = (const float*)d_in[10];
    const float* w2      = (const float*)d_in[11];
    const float* b2      = (const float*)d_in[12];
    float* out = (float*)d_out;

    __half *weiH, *xH, *hH, *wH, *wL;
    float* scal;
    cudaGetSymbolAddress((void**)&weiH, g_weiH);
    cudaGetSymbolAddress((void**)&xH,   g_xH);
    cudaGetSymbolAddress((void**)&hH,   g_hH);
    cudaGetSymbolAddress((void**)&scal, g_scal);
    cudaGetSymbolAddress((void**)&wH,   g_wH);
    cudaGetSymbolAddress((void**)&wL,   g_wL);

    cudaFuncSetAttribute(gemm_hmma<EPI_TANH>,  cudaFuncAttributeMaxDynamicSharedMemorySize, SMEM_DYN);
    cudaFuncSetAttribute(gemm_hmma<EPI_FILM>,  cudaFuncAttributeMaxDynamicSharedMemorySize, SMEM_DYN);
    cudaFuncSetAttribute(gemm_hmma<EPI_RELU>,  cudaFuncAttributeMaxDynamicSharedMemorySize, SMEM_DYN);
    cudaFuncSetAttribute(gemm_hmma<EPI_FINAL>, cudaFuncAttributeMaxDynamicSharedMemorySize, SMEM_DYN);

    // launches 0-3: weight splits
    const float* ws[4] = { w_scale, w_shift, w1, w2 };
    for (int k = 0; k < 4; k++)
        split_kernel<<<(W_ELEMS + 255) / 256, 256>>>(ws[k], wH + (size_t)k * W_ELEMS,
                                                     wL + (size_t)k * W_ELEMS, W_ELEMS);

    // launch 4: attention + weighted context -> wei (fp16)
    attn_wei_kernel<<<dim3(I_IMG, C_CAP), 288>>>(rgn, wrd, lens, weiH);

    dim3 ggrid(D_EMB / 128, M_TOT / 128);   // (8, 288)

    // launch 5: scaling = tanh(wei @ w_scale^T + b_scale) -> scal (fp32)
    gemm_hmma<EPI_TANH><<<ggrid, 256, SMEM_DYN>>>(
        weiH, wH + 0 * (size_t)W_ELEMS, wL + 0 * (size_t)W_ELEMS,
        b_scale, nullptr, nullptr, scal, nullptr);
    // launch 6: x = rgn*scal + (wei @ w_shift^T + b_shift) -> xH
    gemm_hmma<EPI_FILM><<<ggrid, 256, SMEM_DYN>>>(
        weiH, wH + 1 * (size_t)W_ELEMS, wL + 1 * (size_t)W_ELEMS,
        b_shift, scal, rgn, nullptr, xH);
    // launch 7: h = relu(x @ w1^T + b1) -> hH
    gemm_hmma<EPI_RELU><<<ggrid, 256, SMEM_DYN>>>(
        xH, wH + 2 * (size_t)W_ELEMS, wL + 2 * (size_t)W_ELEMS,
        b1, nullptr, nullptr, nullptr, hH);
    // launch 8: out = (h @ w2^T + b2) + rgn, transposed (c,i)->(i,c)
    gemm_hmma<EPI_FINAL><<<ggrid, 256, SMEM_DYN>>>(
        hH, wH + 3 * (size_t)W_ELEMS, wL + 3 * (size_t)W_ELEMS,
        b2, nullptr, rgn, out, nullptr);
}

// round 9
// speedup vs baseline: 1.7792x; 1.4417x over previous
#include <cuda_runtime.h>
#include <cuda_fp16.h>
#include <math.h>
#include <stdint.h>

// Problem dims
#define I_IMG 32
#define C_CAP 32
#define Q_RGN 36
#define L_MAX 50
#define D_EMB 1024
#define M_TOT (C_CAP * I_IMG * Q_RGN)          // 36864
#define ELEMS ((size_t)M_TOT * D_EMB)          // 37,748,736
#define W_ELEMS (D_EMB * D_EMB)

// ---------------- scratch (device globals; allocation-free) ----------------
__device__ __align__(256) __half g_weiH[ELEMS];
__device__ __align__(256) __half g_xH[ELEMS];
__device__ __align__(256) __half g_hH[ELEMS];
__device__ __align__(256) float  g_scal[ELEMS];
__device__ __align__(256) __half g_wH[4][W_ELEMS];

// ---------------------------------------------------------------------------
// K1: per-(c,i) fused attention -> wei (fp16).  288 threads.
// ---------------------------------------------------------------------------
__global__ __launch_bounds__(288) void attn_wei_kernel(
    const float* __restrict__ rgn, const float* __restrict__ wrd,
    const int* __restrict__ lens, __half* __restrict__ weiH)
{
    const int i = blockIdx.x;
    const int c = blockIdx.y;
    const int tid = threadIdx.x;

    __shared__ __align__(16) float sW[L_MAX][40];
    __shared__ __align__(16) float sR[Q_RGN][40];
    __shared__ __align__(16) float sS[L_MAX][Q_RGN + 1];
    __shared__ __align__(16) float sWd[L_MAX][68];

    const float* wrdC = wrd + (size_t)c * L_MAX * D_EMB;
    const float* rgnI = rgn + (size_t)i * Q_RGN * D_EMB;

    // ---- stage 1: s[l][q] = wrd[c,l,:] . rgn[i,q,:], 2l x 4q per thread ----
    const bool act = tid < 225;
    const int lt = tid / 9, qt = tid - 9 * (tid / 9);
    float acc[2][4];
#pragma unroll
    for (int a = 0; a < 2; a++)
#pragma unroll
        for (int b = 0; b < 4; b++) acc[a][b] = 0.f;

    for (int d0 = 0; d0 < D_EMB; d0 += 32) {
        __syncthreads();
        for (int f = tid; f < L_MAX * 32; f += 288) {
            int r = f >> 5, dd = f & 31;
            sW[r][dd] = wrdC[r * D_EMB + d0 + dd];
        }
        for (int f = tid; f < Q_RGN * 32; f += 288) {
            int r = f >> 5, dd = f & 31;
            sR[r][dd] = rgnI[r * D_EMB + d0 + dd];
        }
        __syncthreads();
        if (act) {
#pragma unroll
            for (int dd4 = 0; dd4 < 8; dd4++) {
                float4 w0 = *(const float4*)&sW[2 * lt][dd4 * 4];
                float4 w1 = *(const float4*)&sW[2 * lt + 1][dd4 * 4];
#pragma unroll
                for (int j = 0; j < 4; j++) {
                    float4 rv = *(const float4*)&sR[4 * qt + j][dd4 * 4];
                    acc[0][j] += w0.x * rv.x + w0.y * rv.y + w0.z * rv.z + w0.w * rv.w;
                    acc[1][j] += w1.x * rv.x + w1.y * rv.y + w1.z * rv.z + w1.w * rv.w;
                }
            }
        }
    }
    __syncthreads();

    if (act) {
#pragma unroll
        for (int a = 0; a < 2; a++)
#pragma unroll
            for (int b = 0; b < 4; b++) {
                float v = acc[a][b];
                sS[2 * lt + a][4 * qt + b] = (v >= 0.f) ? v : 0.1f * v;
            }
    }
    __syncthreads();

    if (tid < L_MAX) {
        float ss = 0.f;
        for (int q = 0; q < Q_RGN; q++) { float v = sS[tid][q]; ss += v * v; }
        float inv = 1.f / fmaxf(sqrtf(ss), 1e-12f);
        for (int q = 0; q < Q_RGN; q++) sS[tid][q] *= inv;
    }
    __syncthreads();

    const int len = lens[c];

    if (tid < Q_RGN) {
        float mx = -1e30f;
        for (int l = 0; l < len; l++) mx = fmaxf(mx, sS[l][tid]);
        float sum = 0.f;
        for (int l = 0; l < len; l++) sum += expf(9.f * (sS[l][tid] - mx));
        float invs = 1.f / sum;
        for (int l = 0; l < len; l++)
            sS[l][tid] = expf(9.f * (sS[l][tid] - mx)) * invs;
    }
    __syncthreads();

    // ---- stage 3: wei[q][d] = sum_l attn[l][q] * wrd[l][d], smem-tiled ----
    const int q3 = tid >> 3;
    const int d8 = (tid & 7) * 8;
    const size_t obase = ((size_t)(c * I_IMG + i)) * Q_RGN * D_EMB;

    for (int d0 = 0; d0 < D_EMB; d0 += 64) {
        __syncthreads();
        for (int f = tid; f < L_MAX * 64; f += 288) {
            int r = f >> 6, dd = f & 63;
            sWd[r][dd] = wrdC[r * D_EMB + d0 + dd];
        }
        __syncthreads();
        float a[8];
#pragma unroll
        for (int j = 0; j < 8; j++) a[j] = 0.f;
        for (int l = 0; l < len; l++) {
            float s = sS[l][q3];
            float4 w0 = *(const float4*)&sWd[l][d8];
            float4 w1 = *(const float4*)&sWd[l][d8 + 4];
            a[0] += s * w0.x; a[1] += s * w0.y; a[2] += s * w0.z; a[3] += s * w0.w;
            a[4] += s * w1.x; a[5] += s * w1.y; a[6] += s * w1.z; a[7] += s * w1.w;
        }
        union { uint4 u; __half h[8]; } uh;
#pragma unroll
        for (int j = 0; j < 8; j++) uh.h[j] = __float2half_rn(a[j]);
        *(uint4*)(weiH + obase + (size_t)q3 * D_EMB + d0 + d8) = uh.u;
    }
}

// ---------------------------------------------------------------------------
// weight convert: fp32 -> fp16
// ---------------------------------------------------------------------------
__global__ __launch_bounds__(256) void cvt_kernel(
    const float* __restrict__ s, __half* __restrict__ h, int n4)
{
    int i = blockIdx.x * 256 + threadIdx.x;   // float4 index
    if (i < n4) {
        float4 v = ((const float4*)s)[i];
        union { uint2 u; __half h[4]; } o;
        o.h[0] = __float2half_rn(v.x); o.h[1] = __float2half_rn(v.y);
        o.h[2] = __float2half_rn(v.z); o.h[3] = __float2half_rn(v.w);
        ((uint2*)h)[i] = o.u;
    }
}

// ---------------------------------------------------------------------------
// HMMA GEMM (plain fp16, fp32 accum): D[m,n] = epi( sum_k A[m,k]*W[n,k] + b )
// 128x128x32 tiles, 3-stage cp.async, mma.m16n8k16, 2 CTAs/SM.
// ---------------------------------------------------------------------------
#define EPI_TANH 0
#define EPI_FILM 1
#define EPI_RELU 2
#define EPI_FINAL 3

#define BK 32
#define TILE_B 8192                 // 128 rows x 64 bytes
#define STAGE_B (2 * TILE_B)        // A, B
#define NSTAGE 3
#define SMEM_DYN (NSTAGE * STAGE_B) // 48 KB -> 2 CTAs/SM
#define NITER (D_EMB / BK)          // 32

__device__ __forceinline__ uint32_t smem_u32(const void* p) {
    uint32_t a;
    asm("{ .reg .u64 t; cvta.to.shared.u64 t, %1; cvt.u32.u64 %0, t; }"
        : "=r"(a) : "l"(p));
    return a;
}
__device__ __forceinline__ uint32_t sm_addr(uint32_t base, int row, int c16) {
    return base + row * 64 + (((uint32_t)(c16 ^ ((row >> 1) & 3))) << 4);
}
__device__ __forceinline__ void load_tile(
    const __half* __restrict__ g, int row0, int kcol0, uint32_t sb, int tid)
{
#pragma unroll
    for (int j = 0; j < 2; j++) {
        int id = tid + 256 * j;        // 0..511
        int r = id >> 2, c = id & 3;
        const void* gp = g + (size_t)(row0 + r) * D_EMB + kcol0 + c * 8;
        uint32_t sa = sm_addr(sb, r, c);
        asm volatile("cp.async.cg.shared.global [%0], [%1], 16;" :: "r"(sa), "l"(gp));
    }
}

#define LDSM_X4(R, addr) \
    asm volatile("ldmatrix.sync.aligned.m8n8.x4.shared.b16 {%0,%1,%2,%3}, [%4];" \
        : "=r"((R)[0]), "=r"((R)[1]), "=r"((R)[2]), "=r"((R)[3]) : "r"(addr))
#define MMA(C, A, B) \
    asm volatile("mma.sync.aligned.m16n8k16.row.col.f32.f16.f16.f32 " \
        "{%0,%1,%2,%3}, {%4,%5,%6,%7}, {%8,%9}, {%0,%1,%2,%3};" \
        : "+f"((C)[0]), "+f"((C)[1]), "+f"((C)[2]), "+f"((C)[3]) \
        : "r"((A)[0]), "r"((A)[1]), "r"((A)[2]), "r"((A)[3]), "r"((B)[0]), "r"((B)[1]))

template <int EPI>
__global__ __launch_bounds__(256, 2) void gemm_hmma(
    const __half* __restrict__ Ah, const __half* __restrict__ Bh,
    const float* __restrict__ bias,
    const float* __restrict__ scal,      // FILM input
    const float* __restrict__ rgn,       // FILM / FINAL
    float* __restrict__ outF,            // TANH (scal) / FINAL (d_out)
    __half* __restrict__ outH)           // FILM (x) / RELU (h)
{
    extern __shared__ __align__(1024) uint8_t dsm[];
    const uint32_t sb = smem_u32(dsm);

    const int tid = threadIdx.x;
    const int wid = tid >> 5;
    const int lid = tid & 31;
    const int wm = wid & 3;
    const int wn = wid >> 2;
    const int m0 = blockIdx.y * 128;
    const int n0 = blockIdx.x * 128;

    const int a_ro = lid & 15;
    const int a_co = lid >> 4;
    const int b_ro = ((lid >> 4) & 1) * 8 + (lid & 7);
    const int b_co = (lid >> 3) & 1;

    float c[2][8][4];
#pragma unroll
    for (int a = 0; a < 2; a++)
#pragma unroll
        for (int b = 0; b < 8; b++)
#pragma unroll
            for (int d = 0; d < 4; d++) c[a][b][d] = 0.f;

#pragma unroll
    for (int s = 0; s < 2; s++) {
        uint32_t st = sb + s * STAGE_B;
        load_tile(Ah, m0, s * BK, st + 0 * TILE_B, tid);
        load_tile(Bh, n0, s * BK, st + 1 * TILE_B, tid);
        asm volatile("cp.async.commit_group;");
    }

    int stage = 0;
    for (int i = 0; i < NITER; i++) {
        asm volatile("cp.async.wait_group 1;");
        __syncthreads();

        if (i + 2 < NITER) {
            uint32_t st = sb + ((stage + 2) % NSTAGE) * STAGE_B;
            int kc = (i + 2) * BK;
            load_tile(Ah, m0, kc, st + 0 * TILE_B, tid);
            load_tile(Bh, n0, kc, st + 1 * TILE_B, tid);
        }
        asm volatile("cp.async.commit_group;");

        uint32_t stA = sb + stage * STAGE_B;
#pragma unroll
        for (int ks = 0; ks < 2; ks++) {
            uint32_t aH[2][4], bH[8][2];
#pragma unroll
            for (int mi = 0; mi < 2; mi++)
                LDSM_X4(aH[mi], sm_addr(stA + 0 * TILE_B, wm * 32 + mi * 16 + a_ro, ks * 2 + a_co));
#pragma unroll
            for (int p = 0; p < 4; p++) {
                uint32_t r[4];
                LDSM_X4(r, sm_addr(stA + 1 * TILE_B, wn * 64 + p * 16 + b_ro, ks * 2 + b_co));
                bH[2 * p][0] = r[0]; bH[2 * p][1] = r[1];
                bH[2 * p + 1][0] = r[2]; bH[2 * p + 1][1] = r[3];
            }
#pragma unroll
            for (int mi = 0; mi < 2; mi++)
#pragma unroll
                for (int nj = 0; nj < 8; nj++)
                    MMA(c[mi][nj], aH[mi], bH[nj]);
        }
        stage = (stage + 1) % NSTAGE;
    }

    // ---------------- epilogue ----------------
    const int nbase = n0 + wn * 64;
    const int mbase = m0 + wm * 32;
    const int cph = (lid & 3) * 2;

    float2 bv[8];
#pragma unroll
    for (int nj = 0; nj < 8; nj++)
        bv[nj] = *(const float2*)(bias + nbase + nj * 8 + cph);

#pragma unroll
    for (int mi = 0; mi < 2; mi++) {
#pragma unroll
        for (int hf = 0; hf < 2; hf++) {
            const int m = mbase + mi * 16 + hf * 8 + (lid >> 2);
            const int t = m / Q_RGN;
            const int q = m - t * Q_RGN;
            const int i_img = t & (I_IMG - 1);
            const int cc = t >> 5;

            if (EPI == EPI_TANH) {
                float* op = outF + (size_t)m * D_EMB + nbase + cph;
#pragma unroll
                for (int nj = 0; nj < 8; nj++) {
                    float2 o;
                    o.x = tanhf(c[mi][nj][hf * 2 + 0] + bv[nj].x);
                    o.y = tanhf(c[mi][nj][hf * 2 + 1] + bv[nj].y);
                    *(float2*)(op + nj * 8) = o;
                }
            } else if (EPI == EPI_FILM) {
                const float* rp = rgn + ((size_t)(i_img * Q_RGN + q)) * D_EMB + nbase + cph;
                const float* sp = scal + (size_t)m * D_EMB + nbase + cph;
                size_t ob = (size_t)m * D_EMB + nbase + cph;
#pragma unroll
                for (int nj = 0; nj < 8; nj++) {
                    float2 rv = *(const float2*)(rp + nj * 8);
                    float2 sv = *(const float2*)(sp + nj * 8);
                    float x0 = rv.x * sv.x + (c[mi][nj][hf * 2 + 0] + bv[nj].x);
                    float x1 = rv.y * sv.y + (c[mi][nj][hf * 2 + 1] + bv[nj].y);
                    *(__half2*)(outH + ob + nj * 8) =
                        __halves2half2(__float2half_rn(x0), __float2half_rn(x1));
                }
            } else if (EPI == EPI_RELU) {
                size_t ob = (size_t)m * D_EMB + nbase + cph;
#pragma unroll
                for (int nj = 0; nj < 8; nj++) {
                    float x0 = fmaxf(c[mi][nj][hf * 2 + 0] + bv[nj].x, 0.f);
                    float x1 = fmaxf(c[mi][nj][hf * 2 + 1] + bv[nj].y, 0.f);
                    *(__half2*)(outH + ob + nj * 8) =
                        __halves2half2(__float2half_rn(x0), __float2half_rn(x1));
                }
            } else {  // EPI_FINAL: out[(i,c,q),n] = acc + bias + rgn
                const float* rp = rgn + ((size_t)(i_img * Q_RGN + q)) * D_EMB + nbase + cph;
                float* op = outF + (((size_t)(i_img * C_CAP + cc)) * Q_RGN + q) * D_EMB + nbase + cph;
#pragma unroll
                for (int nj = 0; nj < 8; nj++) {
                    float2 rv = *(const float2*)(rp + nj * 8);
                    float2 o;
                    o.x = c[mi][nj][hf * 2 + 0] + bv[nj].x + rv.x;
                    o.y = c[mi][nj][hf * 2 + 1] + bv[nj].y + rv.y;
                    *(float2*)(op + nj * 8) = o;
                }
            }
        }
    }
}

// ---------------------------------------------------------------------------
extern "C" void kernel_launch(void* const* d_in, const int* in_sizes, int n_in,
                              void* d_out, int out_size)
{
    const float* rgn     = (const float*)d_in[0];
    const float* wrd     = (const float*)d_in[2];
    const int*   lens    = (const int*)d_in[4];
    const float* w_scale = (const float*)d_in[5];
    const float* b_scale = (const float*)d_in[6];
    const float* w_shift = (const float*)d_in[7];
    const float* b_shift = (const float*)d_in[8];
    const float* w1      = (const float*)d_in[9];
    const float* b1      = (const float*)d_in[10];
    const float* w2      = (const float*)d_in[11];
    const float* b2      = (const float*)d_in[12];
    float* out = (float*)d_out;

    __half *weiH, *xH, *hH, *wH;
    float* scal;
    cudaGetSymbolAddress((void**)&weiH, g_weiH);
    cudaGetSymbolAddress((void**)&xH,   g_xH);
    cudaGetSymbolAddress((void**)&hH,   g_hH);
    cudaGetSymbolAddress((void**)&scal, g_scal);
    cudaGetSymbolAddress((void**)&wH,   g_wH);

    cudaFuncSetAttribute(gemm_hmma<EPI_TANH>,  cudaFuncAttributeMaxDynamicSharedMemorySize, SMEM_DYN);
    cudaFuncSetAttribute(gemm_hmma<EPI_FILM>,  cudaFuncAttributeMaxDynamicSharedMemorySize, SMEM_DYN);
    cudaFuncSetAttribute(gemm_hmma<EPI_RELU>,  cudaFuncAttributeMaxDynamicSharedMemorySize, SMEM_DYN);
    cudaFuncSetAttribute(gemm_hmma<EPI_FINAL>, cudaFuncAttributeMaxDynamicSharedMemorySize, SMEM_DYN);

    // launches 0-3: weight converts (fp32 -> fp16)
    const float* ws[4] = { w_scale, w_shift, w1, w2 };
    for (int k = 0; k < 4; k++)
        cvt_kernel<<<(W_ELEMS / 4 + 255) / 256, 256>>>(ws[k], wH + (size_t)k * W_ELEMS,
                                                       W_ELEMS / 4);

    // launch 4: attention + weighted context -> wei (fp16)
    attn_wei_kernel<<<dim3(I_IMG, C_CAP), 288>>>(rgn, wrd, lens, weiH);

    dim3 ggrid(D_EMB / 128, M_TOT / 128);   // (8, 288)

    // launch 5: scaling = tanh(wei @ w_scale^T + b_scale) -> scal (fp32)
    gemm_hmma<EPI_TANH><<<ggrid, 256, SMEM_DYN>>>(
        weiH, wH + 0 * (size_t)W_ELEMS, b_scale, nullptr, nullptr, scal, nullptr);
    // launch 6: x = rgn*scal + (wei @ w_shift^T + b_shift) -> xH
    gemm_hmma<EPI_FILM><<<ggrid, 256, SMEM_DYN>>>(
        weiH, wH + 1 * (size_t)W_ELEMS, b_shift, scal, rgn, nullptr, xH);
    // launch 7: h = relu(x @ w1^T + b1) -> hH
    gemm_hmma<EPI_RELU><<<ggrid, 256, SMEM_DYN>>>(
        xH, wH + 2 * (size_t)W_ELEMS, b1, nullptr, nullptr, nullptr, hH);
    // launch 8: out = (h @ w2^T + b2) + rgn, transposed (c,i)->(i,c)
    gemm_hmma<EPI_FINAL><<<ggrid, 256, SMEM_DYN>>>(
        hH, wH + 3 * (size_t)W_ELEMS, b2, nullptr, rgn, out, nullptr);
}

// round 10
// speedup vs baseline: 3.8540x; 2.1662x over previous
#include <cuda_runtime.h>
#include <cuda_fp16.h>
#include <math.h>
#include <stdint.h>

// Problem dims
#define I_IMG 32
#define C_CAP 32
#define Q_RGN 36
#define L_MAX 50
#define LPAD 64
#define D_EMB 1024
#define MIQ (I_IMG * Q_RGN)                    // 1152 rows per caption
#define M_TOT (C_CAP * MIQ)                    // 36864
#define ELEMS ((size_t)M_TOT * D_EMB)
#define W_ELEMS (D_EMB * D_EMB)

// ---------------- scratch (device globals; allocation-free) ----------------
__device__ __align__(256) __half g_weiH[ELEMS];
__device__ __align__(256) __half g_xH[ELEMS];
__device__ __align__(256) __half g_hH[ELEMS];
__device__ __align__(256) float  g_scal[ELEMS];
__device__ __align__(256) __half g_wH[4][W_ELEMS];
__device__ __align__(256) __half g_rgnH[MIQ * D_EMB];
__device__ __align__(256) __half g_rgnL[MIQ * D_EMB];
__device__ __align__(256) __half g_wrdH[C_CAP * LPAD * D_EMB];
__device__ __align__(256) __half g_wrdL[C_CAP * LPAD * D_EMB];
__device__ __align__(256) __half g_wrdTH[C_CAP * D_EMB * LPAD];
__device__ __align__(256) __half g_wrdTL[C_CAP * D_EMB * LPAD];
__device__ __align__(256) float  g_S[(size_t)C_CAP * MIQ * LPAD];
__device__ __align__(256) __half g_attnH[(size_t)C_CAP * MIQ * LPAD];
__device__ __align__(256) __half g_attnL[(size_t)C_CAP * MIQ * LPAD];

__device__ __forceinline__ void split_h(float x, __half& h, __half& l) {
    h = __float2half_rn(x);
    l = __float2half_rn(x - __half2float(h));
}

// ---------------- common HMMA infrastructure ----------------
__device__ __forceinline__ uint32_t smem_u32(const void* p) {
    uint32_t a;
    asm("{ .reg .u64 t; cvta.to.shared.u64 t, %1; cvt.u32.u64 %0, t; }"
        : "=r"(a) : "l"(p));
    return a;
}
__device__ __forceinline__ uint32_t sm_addr(uint32_t base, int row, int c16) {
    return base + row * 64 + (((uint32_t)(c16 ^ ((row >> 1) & 3))) << 4);
}
// 128-row x 32-col (64B/row) tile, generic leading dim (in halves)
__device__ __forceinline__ void load_t128(
    const __half* __restrict__ g, int ld, int row0, int kcol0, uint32_t sb, int tid)
{
#pragma unroll
    for (int j = 0; j < 2; j++) {
        int id = tid + 256 * j;
        int r = id >> 2, c = id & 3;
        const void* gp = g + (size_t)(row0 + r) * ld + kcol0 + c * 8;
        asm volatile("cp.async.cg.shared.global [%0], [%1], 16;"
                     :: "r"(sm_addr(sb, r, c)), "l"(gp));
    }
}
// 64-row x 32-col tile (256 units; 1 per thread)
__device__ __forceinline__ void load_t64(
    const __half* __restrict__ g, int ld, int row0, int kcol0, uint32_t sb, int tid)
{
    int r = tid >> 2, c = tid & 3;
    const void* gp = g + (size_t)(row0 + r) * ld + kcol0 + c * 8;
    asm volatile("cp.async.cg.shared.global [%0], [%1], 16;"
                 :: "r"(sm_addr(sb, r, c)), "l"(gp));
}

#define LDSM_X4(R, addr) \
    asm volatile("ldmatrix.sync.aligned.m8n8.x4.shared.b16 {%0,%1,%2,%3}, [%4];" \
        : "=r"((R)[0]), "=r"((R)[1]), "=r"((R)[2]), "=r"((R)[3]) : "r"(addr))
#define MMA(C, A, B) \
    asm volatile("mma.sync.aligned.m16n8k16.row.col.f32.f16.f16.f32 " \
        "{%0,%1,%2,%3}, {%4,%5,%6,%7}, {%8,%9}, {%0,%1,%2,%3};" \
        : "+f"((C)[0]), "+f"((C)[1]), "+f"((C)[2]), "+f"((C)[3]) \
        : "r"((A)[0]), "r"((A)[1]), "r"((A)[2]), "r"((A)[3]), "r"((B)[0]), "r"((B)[1]))

// ---------------------------------------------------------------------------
// Prep kernels
// ---------------------------------------------------------------------------
__global__ __launch_bounds__(256) void cvt_kernel(
    const float* __restrict__ s, __half* __restrict__ h, int n4)
{
    int i = blockIdx.x * 256 + threadIdx.x;
    if (i < n4) {
        float4 v = ((const float4*)s)[i];
        union { uint2 u; __half h[4]; } o;
        o.h[0] = __float2half_rn(v.x); o.h[1] = __float2half_rn(v.y);
        o.h[2] = __float2half_rn(v.z); o.h[3] = __float2half_rn(v.w);
        ((uint2*)h)[i] = o.u;
    }
}

__global__ __launch_bounds__(256) void split_rgn_kernel(
    const float* __restrict__ s, __half* __restrict__ h,
    __half* __restrict__ l, int n4)
{
    int i = blockIdx.x * 256 + threadIdx.x;
    if (i < n4) {
        float4 v = ((const float4*)s)[i];
        union { uint2 u; __half h[4]; } oh, ol;
        split_h(v.x, oh.h[0], ol.h[0]); split_h(v.y, oh.h[1], ol.h[1]);
        split_h(v.z, oh.h[2], ol.h[2]); split_h(v.w, oh.h[3], ol.h[3]);
        ((uint2*)h)[i] = oh.u;
        ((uint2*)l)[i] = ol.u;
    }
}

// wrd: (C,50,1024) fp32 -> wrdH/L (C,64,1024) zero-padded + wrdTH/L (C,1024,64)
__global__ __launch_bounds__(256) void wrd_prep_kernel(
    const float* __restrict__ wrd,
    __half* __restrict__ wh, __half* __restrict__ wl,
    __half* __restrict__ wth, __half* __restrict__ wtl)
{
    const int d0 = blockIdx.x * 64;
    const int c = blockIdx.y;
    const int tid = threadIdx.x;
    __shared__ __align__(16) float ts[64][65];

    for (int idx = tid; idx < 64 * 64; idx += 256) {
        int l = idx >> 6, dd = idx & 63;
        float v = (l < L_MAX) ? wrd[((size_t)c * L_MAX + l) * D_EMB + d0 + dd] : 0.f;
        ts[l][dd] = v;
        __half h, lo; split_h(v, h, lo);
        wh[((size_t)c * LPAD + l) * D_EMB + d0 + dd] = h;
        wl[((size_t)c * LPAD + l) * D_EMB + d0 + dd] = lo;
    }
    __syncthreads();
    for (int idx = tid; idx < 64 * 64; idx += 256) {
        int d = idx >> 6, l = idx & 63;
        float v = ts[l][d];
        __half h, lo; split_h(v, h, lo);
        wth[((size_t)c * D_EMB + d0 + d) * LPAD + l] = h;
        wtl[((size_t)c * D_EMB + d0 + d) * LPAD + l] = lo;
    }
}

// ---------------------------------------------------------------------------
// A1: scores  S[c, m=(i,q), l] = leaky( rgn[m,:] . wrd[c,l,:] ), 3-term HMMA.
// grid (9, 32), 256 thr, tiles 128(m) x 64(l) x K1024 (BK32, 3-stage).
// ---------------------------------------------------------------------------
#define A1_STAGE (2 * 8192 + 2 * 4096)     // Ah, Al (128-row), Bh, Bl (64-row)
#define A1_SMEM (3 * A1_STAGE)             // 72 KB

__global__ __launch_bounds__(256, 1) void gemm_score(
    const __half* __restrict__ Rh, const __half* __restrict__ Rl,
    const __half* __restrict__ Wh, const __half* __restrict__ Wl,
    float* __restrict__ S)
{
    extern __shared__ __align__(1024) uint8_t dsm[];
    const uint32_t sb = smem_u32(dsm);
    const int tid = threadIdx.x;
    const int wid = tid >> 5, lid = tid & 31;
    const int wm = wid & 3, wn = wid >> 2;         // 4x32 m, 2x32 l
    const int m0 = blockIdx.x * 128;
    const int c  = blockIdx.y;

    const __half* Bh = Wh + (size_t)c * LPAD * D_EMB;
    const __half* Bl = Wl + (size_t)c * LPAD * D_EMB;

    const int a_ro = lid & 15, a_co = lid >> 4;
    const int b_ro = ((lid >> 4) & 1) * 8 + (lid & 7);
    const int b_co = (lid >> 3) & 1;

    float acc[2][4][4];
#pragma unroll
    for (int a = 0; a < 2; a++)
#pragma unroll
        for (int b = 0; b < 4; b++)
#pragma unroll
            for (int d = 0; d < 4; d++) acc[a][b][d] = 0.f;

#pragma unroll
    for (int s = 0; s < 2; s++) {
        uint32_t st = sb + s * A1_STAGE;
        load_t128(Rh, D_EMB, m0, s * 32, st, tid);
        load_t128(Rl, D_EMB, m0, s * 32, st + 8192, tid);
        load_t64(Bh, D_EMB, 0, s * 32, st + 16384, tid);
        load_t64(Bl, D_EMB, 0, s * 32, st + 20480, tid);
        asm volatile("cp.async.commit_group;");
    }

    int stage = 0;
    for (int i = 0; i < 32; i++) {
        asm volatile("cp.async.wait_group 1;");
        __syncthreads();
        if (i + 2 < 32) {
            uint32_t st = sb + ((stage + 2) % 3) * A1_STAGE;
            int kc = (i + 2) * 32;
            load_t128(Rh, D_EMB, m0, kc, st, tid);
            load_t128(Rl, D_EMB, m0, kc, st + 8192, tid);
            load_t64(Bh, D_EMB, 0, kc, st + 16384, tid);
            load_t64(Bl, D_EMB, 0, kc, st + 20480, tid);
        }
        asm volatile("cp.async.commit_group;");

        uint32_t stA = sb + stage * A1_STAGE;
#pragma unroll
        for (int ks = 0; ks < 2; ks++) {
            uint32_t aH[2][4], aL[2][4], bH[4][2], bL[4][2];
#pragma unroll
            for (int mi = 0; mi < 2; mi++) {
                LDSM_X4(aH[mi], sm_addr(stA, wm * 32 + mi * 16 + a_ro, ks * 2 + a_co));
                LDSM_X4(aL[mi], sm_addr(stA + 8192, wm * 32 + mi * 16 + a_ro, ks * 2 + a_co));
            }
#pragma unroll
            for (int p = 0; p < 2; p++) {
                uint32_t r[4];
                LDSM_X4(r, sm_addr(stA + 16384, wn * 32 + p * 16 + b_ro, ks * 2 + b_co));
                bH[2 * p][0] = r[0]; bH[2 * p][1] = r[1];
                bH[2 * p + 1][0] = r[2]; bH[2 * p + 1][1] = r[3];
                LDSM_X4(r, sm_addr(stA + 20480, wn * 32 + p * 16 + b_ro, ks * 2 + b_co));
                bL[2 * p][0] = r[0]; bL[2 * p][1] = r[1];
                bL[2 * p + 1][0] = r[2]; bL[2 * p + 1][1] = r[3];
            }
#pragma unroll
            for (int mi = 0; mi < 2; mi++)
#pragma unroll
                for (int nj = 0; nj < 4; nj++) {
                    MMA(acc[mi][nj], aH[mi], bH[nj]);
                    MMA(acc[mi][nj], aH[mi], bL[nj]);
                    MMA(acc[mi][nj], aL[mi], bH[nj]);
                }
        }
        stage = (stage + 1) % 3;
    }

    const int cph = (lid & 3) * 2;
#pragma unroll
    for (int mi = 0; mi < 2; mi++)
#pragma unroll
        for (int hf = 0; hf < 2; hf++) {
            int m = m0 + wm * 32 + mi * 16 + hf * 8 + (lid >> 2);
            float* op = S + ((size_t)c * MIQ + m) * LPAD + wn * 32 + cph;
#pragma unroll
            for (int nj = 0; nj < 4; nj++) {
                float v0 = acc[mi][nj][hf * 2 + 0];
                float v1 = acc[mi][nj][hf * 2 + 1];
                float2 o;
                o.x = (v0 >= 0.f) ? v0 : 0.1f * v0;
                o.y = (v1 >= 0.f) ? v1 : 0.1f * v1;
                *(float2*)(op + nj * 8) = o;
            }
        }
}

// ---------------------------------------------------------------------------
// A2: per (c,i): L2-normalize over q, masked softmax over l -> attn fp16 h/l.
// ---------------------------------------------------------------------------
__global__ __launch_bounds__(128) void attn_norm_kernel(
    const float* __restrict__ S, const int* __restrict__ lens,
    __half* __restrict__ attnH, __half* __restrict__ attnL)
{
    const int i = blockIdx.x;
    const int c = blockIdx.y;
    const int tid = threadIdx.x;
    __shared__ __align__(16) float s[Q_RGN][68];
    __shared__ __align__(16) __half ah[Q_RGN * LPAD];
    __shared__ __align__(16) __half al[Q_RGN * LPAD];

    const size_t base = ((size_t)c * MIQ + i * Q_RGN) * LPAD;

    for (int idx = tid; idx < Q_RGN * 16; idx += 128) {
        int q = idx >> 4, f4 = idx & 15;
        float4 v = *(const float4*)(S + base + q * LPAD + f4 * 4);
        *(float4*)&s[q][f4 * 4] = v;
    }
    __syncthreads();

    if (tid < L_MAX) {
        float ss = 0.f;
        for (int q = 0; q < Q_RGN; q++) { float v = s[q][tid]; ss += v * v; }
        float inv = 1.f / fmaxf(sqrtf(ss), 1e-12f);
        for (int q = 0; q < Q_RGN; q++) s[q][tid] *= inv;
    }
    __syncthreads();

    const int len = lens[c];
    if (tid < Q_RGN) {
        float mx = -1e30f;
        for (int l = 0; l < len; l++) mx = fmaxf(mx, s[tid][l]);
        float sum = 0.f;
        for (int l = 0; l < len; l++) sum += expf(9.f * (s[tid][l] - mx));
        float inv = 1.f / sum;
        for (int l = 0; l < LPAD; l++) {
            float a = (l < len) ? expf(9.f * (s[tid][l] - mx)) * inv : 0.f;
            __half h, lo; split_h(a, h, lo);
            ah[tid * LPAD + l] = h;
            al[tid * LPAD + l] = lo;
        }
    }
    __syncthreads();

    for (int u = tid; u < Q_RGN * LPAD / 8; u += 128) {
        *(uint4*)(attnH + base + u * 8) = *(const uint4*)(ah + u * 8);
        *(uint4*)(attnL + base + u * 8) = *(const uint4*)(al + u * 8);
    }
}

// ---------------------------------------------------------------------------
// A3: wei[c, m, d] = sum_l attn[c,m,l] * wrdT[c,d,l], 3-term HMMA, K=64.
// grid (8, 9, 32), tiles 128x128, double-buffered K32 chunks.
// ---------------------------------------------------------------------------
#define A3_STAGE (4 * 8192)                // Ah, Al, Bh, Bl (all 128-row)
#define A3_SMEM (2 * A3_STAGE)             // 64 KB

__global__ __launch_bounds__(256, 2) void gemm_wei(
    const __half* __restrict__ AH, const __half* __restrict__ AL,
    const __half* __restrict__ WTH, const __half* __restrict__ WTL,
    __half* __restrict__ weiH)
{
    extern __shared__ __align__(1024) uint8_t dsm[];
    const uint32_t sb = smem_u32(dsm);
    const int tid = threadIdx.x;
    const int wid = tid >> 5, lid = tid & 31;
    const int wm = wid & 3, wn = wid >> 2;
    const int n0 = blockIdx.x * 128;
    const int m0 = blockIdx.y * 128;
    const int c  = blockIdx.z;

    const __half* Ah = AH + (size_t)c * MIQ * LPAD;
    const __half* Al = AL + (size_t)c * MIQ * LPAD;
    const __half* Bh = WTH + (size_t)c * D_EMB * LPAD;
    const __half* Bl = WTL + (size_t)c * D_EMB * LPAD;

    const int a_ro = lid & 15, a_co = lid >> 4;
    const int b_ro = ((lid >> 4) & 1) * 8 + (lid & 7);
    const int b_co = (lid >> 3) & 1;

    float acc[2][8][4];
#pragma unroll
    for (int a = 0; a < 2; a++)
#pragma unroll
        for (int b = 0; b < 8; b++)
#pragma unroll
            for (int d = 0; d < 4; d++) acc[a][b][d] = 0.f;

#pragma unroll
    for (int s = 0; s < 2; s++) {
        uint32_t st = sb + s * A3_STAGE;
        load_t128(Ah, LPAD, m0, s * 32, st, tid);
        load_t128(Al, LPAD, m0, s * 32, st + 8192, tid);
        load_t128(Bh, LPAD, n0, s * 32, st + 16384, tid);
        load_t128(Bl, LPAD, n0, s * 32, st + 24576, tid);
        asm volatile("cp.async.commit_group;");
    }

#pragma unroll
    for (int i = 0; i < 2; i++) {
        if (i == 0) asm volatile("cp.async.wait_group 1;");
        else        asm volatile("cp.async.wait_group 0;");
        __syncthreads();
        uint32_t stA = sb + i * A3_STAGE;
#pragma unroll
        for (int ks = 0; ks < 2; ks++) {
            uint32_t aH[2][4], aL[2][4], bH[8][2], bL[8][2];
#pragma unroll
            for (int mi = 0; mi < 2; mi++) {
                LDSM_X4(aH[mi], sm_addr(stA, wm * 32 + mi * 16 + a_ro, ks * 2 + a_co));
                LDSM_X4(aL[mi], sm_addr(stA + 8192, wm * 32 + mi * 16 + a_ro, ks * 2 + a_co));
            }
#pragma unroll
            for (int p = 0; p < 4; p++) {
                uint32_t r[4];
                LDSM_X4(r, sm_addr(stA + 16384, wn * 64 + p * 16 + b_ro, ks * 2 + b_co));
                bH[2 * p][0] = r[0]; bH[2 * p][1] = r[1];
                bH[2 * p + 1][0] = r[2]; bH[2 * p + 1][1] = r[3];
                LDSM_X4(r, sm_addr(stA + 24576, wn * 64 + p * 16 + b_ro, ks * 2 + b_co));
                bL[2 * p][0] = r[0]; bL[2 * p][1] = r[1];
                bL[2 * p + 1][0] = r[2]; bL[2 * p + 1][1] = r[3];
            }
#pragma unroll
            for (int mi = 0; mi < 2; mi++)
#pragma unroll
                for (int nj = 0; nj < 8; nj++) {
                    MMA(acc[mi][nj], aH[mi], bH[nj]);
                    MMA(acc[mi][nj], aH[mi], bL[nj]);
                    MMA(acc[mi][nj], aL[mi], bH[nj]);
                }
        }
    }

    const int cph = (lid & 3) * 2;
    const int nbase = n0 + wn * 64;
#pragma unroll
    for (int mi = 0; mi < 2; mi++)
#pragma unroll
        for (int hf = 0; hf < 2; hf++) {
            int m = m0 + wm * 32 + mi * 16 + hf * 8 + (lid >> 2);
            __half* op = weiH + ((size_t)c * MIQ + m) * D_EMB + nbase + cph;
#pragma unroll
            for (int nj = 0; nj < 8; nj++)
                *(__half2*)(op + nj * 8) = __halves2half2(
                    __float2half_rn(acc[mi][nj][hf * 2 + 0]),
                    __float2half_rn(acc[mi][nj][hf * 2 + 1]));
        }
}

// ---------------------------------------------------------------------------
// Main HMMA GEMM (plain fp16): D[m,n] = epi( sum_k A[m,k]*W[n,k] + b )
// ---------------------------------------------------------------------------
#define EPI_TANH 0
#define EPI_FILM 1
#define EPI_RELU 2
#define EPI_FINAL 3

#define G_STAGE (2 * 8192)
#define G_SMEM (3 * G_STAGE)               // 48 KB -> 2 CTAs/SM

template <int EPI>
__global__ __launch_bounds__(256, 2) void gemm_hmma(
    const __half* __restrict__ Ah, const __half* __restrict__ Bh,
    const float* __restrict__ bias,
    const float* __restrict__ scal,
    const float* __restrict__ rgn,
    float* __restrict__ outF,
    __half* __restrict__ outH)
{
    extern __shared__ __align__(1024) uint8_t dsm[];
    const uint32_t sb = smem_u32(dsm);
    const int tid = threadIdx.x;
    const int wid = tid >> 5, lid = tid & 31;
    const int wm = wid & 3, wn = wid >> 2;
    const int m0 = blockIdx.y * 128;
    const int n0 = blockIdx.x * 128;

    const int a_ro = lid & 15, a_co = lid >> 4;
    const int b_ro = ((lid >> 4) & 1) * 8 + (lid & 7);
    const int b_co = (lid >> 3) & 1;

    float c[2][8][4];
#pragma unroll
    for (int a = 0; a < 2; a++)
#pragma unroll
        for (int b = 0; b < 8; b++)
#pragma unroll
            for (int d = 0; d < 4; d++) c[a][b][d] = 0.f;

#pragma unroll
    for (int s = 0; s < 2; s++) {
        uint32_t st = sb + s * G_STAGE;
        load_t128(Ah, D_EMB, m0, s * 32, st, tid);
        load_t128(Bh, D_EMB, n0, s * 32, st + 8192, tid);
        asm volatile("cp.async.commit_group;");
    }

    int stage = 0;
    for (int i = 0; i < 32; i++) {
        asm volatile("cp.async.wait_group 1;");
        __syncthreads();
        if (i + 2 < 32) {
            uint32_t st = sb + ((stage + 2) % 3) * G_STAGE;
            int kc = (i + 2) * 32;
            load_t128(Ah, D_EMB, m0, kc, st, tid);
            load_t128(Bh, D_EMB, n0, kc, st + 8192, tid);
        }
        asm volatile("cp.async.commit_group;");

        uint32_t stA = sb + stage * G_STAGE;
#pragma unroll
        for (int ks = 0; ks < 2; ks++) {
            uint32_t aH[2][4], bH[8][2];
#pragma unroll
            for (int mi = 0; mi < 2; mi++)
                LDSM_X4(aH[mi], sm_addr(stA, wm * 32 + mi * 16 + a_ro, ks * 2 + a_co));
#pragma unroll
            for (int p = 0; p < 4; p++) {
                uint32_t r[4];
                LDSM_X4(r, sm_addr(stA + 8192, wn * 64 + p * 16 + b_ro, ks * 2 + b_co));
                bH[2 * p][0] = r[0]; bH[2 * p][1] = r[1];
                bH[2 * p + 1][0] = r[2]; bH[2 * p + 1][1] = r[3];
            }
#pragma unroll
            for (int mi = 0; mi < 2; mi++)
#pragma unroll
                for (int nj = 0; nj < 8; nj++)
                    MMA(c[mi][nj], aH[mi], bH[nj]);
        }
        stage = (stage + 1) % 3;
    }

    const int nbase = n0 + wn * 64;
    const int mbase = m0 + wm * 32;
    const int cph = (lid & 3) * 2;

    float2 bv[8];
#pragma unroll
    for (int nj = 0; nj < 8; nj++)
        bv[nj] = *(const float2*)(bias + nbase + nj * 8 + cph);

#pragma unroll
    for (int mi = 0; mi < 2; mi++) {
#pragma unroll
        for (int hf = 0; hf < 2; hf++) {
            const int m = mbase + mi * 16 + hf * 8 + (lid >> 2);
            const int t = m / Q_RGN;
            const int q = m - t * Q_RGN;
            const int i_img = t & (I_IMG - 1);
            const int cc = t >> 5;

            if (EPI == EPI_TANH) {
                float* op = outF + (size_t)m * D_EMB + nbase + cph;
#pragma unroll
                for (int nj = 0; nj < 8; nj++) {
                    float2 o;
                    o.x = tanhf(c[mi][nj][hf * 2 + 0] + bv[nj].x);
                    o.y = tanhf(c[mi][nj][hf * 2 + 1] + bv[nj].y);
                    *(float2*)(op + nj * 8) = o;
                }
            } else if (EPI == EPI_FILM) {
                const float* rp = rgn + ((size_t)(i_img * Q_RGN + q)) * D_EMB + nbase + cph;
                const float* sp = scal + (size_t)m * D_EMB + nbase + cph;
                size_t ob = (size_t)m * D_EMB + nbase + cph;
#pragma unroll
                for (int nj = 0; nj < 8; nj++) {
                    float2 rv = *(const float2*)(rp + nj * 8);
                    float2 sv = *(const float2*)(sp + nj * 8);
                    float x0 = rv.x * sv.x + (c[mi][nj][hf * 2 + 0] + bv[nj].x);
                    float x1 = rv.y * sv.y + (c[mi][nj][hf * 2 + 1] + bv[nj].y);
                    *(__half2*)(outH + ob + nj * 8) =
                        __halves2half2(__float2half_rn(x0), __float2half_rn(x1));
                }
            } else if (EPI == EPI_RELU) {
                size_t ob = (size_t)m * D_EMB + nbase + cph;
#pragma unroll
                for (int nj = 0; nj < 8; nj++) {
                    float x0 = fmaxf(c[mi][nj][hf * 2 + 0] + bv[nj].x, 0.f);
                    float x1 = fmaxf(c[mi][nj][hf * 2 + 1] + bv[nj].y, 0.f);
                    *(__half2*)(outH + ob + nj * 8) =
                        __halves2half2(__float2half_rn(x0), __float2half_rn(x1));
                }
            } else {
                const float* rp = rgn + ((size_t)(i_img * Q_RGN + q)) * D_EMB + nbase + cph;
                float* op = outF + (((size_t)(i_img * C_CAP + cc)) * Q_RGN + q) * D_EMB + nbase + cph;
#pragma unroll
                for (int nj = 0; nj < 8; nj++) {
                    float2 rv = *(const float2*)(rp + nj * 8);
                    float2 o;
                    o.x = c[mi][nj][hf * 2 + 0] + bv[nj].x + rv.x;
                    o.y = c[mi][nj][hf * 2 + 1] + bv[nj].y + rv.y;
                    *(float2*)(op + nj * 8) = o;
                }
            }
        }
    }
}

// ---------------------------------------------------------------------------
extern "C" void kernel_launch(void* const* d_in, const int* in_sizes, int n_in,
                              void* d_out, int out_size)
{
    const float* rgn     = (const float*)d_in[0];
    const float* wrd     = (const float*)d_in[2];
    const int*   lens    = (const int*)d_in[4];
    const float* w_scale = (const float*)d_in[5];
    const float* b_scale = (const float*)d_in[6];
    const float* w_shift = (const float*)d_in[7];
    const float* b_shift = (const float*)d_in[8];
    const float* w1      = (const float*)d_in[9];
    const float* b1      = (const float*)d_in[10];
    const float* w2      = (const float*)d_in[11];
    const float* b2      = (const float*)d_in[12];
    float* out = (float*)d_out;

    __half *weiH, *xH, *hH, *wH, *rgnH, *rgnL, *wrdH, *wrdL, *wrdTH, *wrdTL, *attnH, *attnL;
    float *scal, *S;
    cudaGetSymbolAddress((void**)&weiH, g_weiH);
    cudaGetSymbolAddress((void**)&xH,   g_xH);
    cudaGetSymbolAddress((void**)&hH,   g_hH);
    cudaGetSymbolAddress((void**)&scal, g_scal);
    cudaGetSymbolAddress((void**)&wH,   g_wH);
    cudaGetSymbolAddress((void**)&rgnH, g_rgnH);
    cudaGetSymbolAddress((void**)&rgnL, g_rgnL);
    cudaGetSymbolAddress((void**)&wrdH, g_wrdH);
    cudaGetSymbolAddress((void**)&wrdL, g_wrdL);
    cudaGetSymbolAddress((void**)&wrdTH, g_wrdTH);
    cudaGetSymbolAddress((void**)&wrdTL, g_wrdTL);
    cudaGetSymbolAddress((void**)&attnH, g_attnH);
    cudaGetSymbolAddress((void**)&attnL, g_attnL);
    cudaGetSymbolAddress((void**)&S,    g_S);

    cudaFuncSetAttribute(gemm_score, cudaFuncAttributeMaxDynamicSharedMemorySize, A1_SMEM);
    cudaFuncSetAttribute(gemm_wei,   cudaFuncAttributeMaxDynamicSharedMemorySize, A3_SMEM);
    cudaFuncSetAttribute(gemm_hmma<EPI_TANH>,  cudaFuncAttributeMaxDynamicSharedMemorySize, G_SMEM);
    cudaFuncSetAttribute(gemm_hmma<EPI_FILM>,  cudaFuncAttributeMaxDynamicSharedMemorySize, G_SMEM);
    cudaFuncSetAttribute(gemm_hmma<EPI_RELU>,  cudaFuncAttributeMaxDynamicSharedMemorySize, G_SMEM);
    cudaFuncSetAttribute(gemm_hmma<EPI_FINAL>, cudaFuncAttributeMaxDynamicSharedMemorySize, G_SMEM);

    // preps
    split_rgn_kernel<<<(MIQ * D_EMB / 4 + 255) / 256, 256>>>(rgn, rgnH, rgnL, MIQ * D_EMB / 4);
    wrd_prep_kernel<<<dim3(D_EMB / 64, C_CAP), 256>>>(wrd, wrdH, wrdL, wrdTH, wrdTL);
    const float* ws[4] = { w_scale, w_shift, w1, w2 };
    for (int k = 0; k < 4; k++)
        cvt_kernel<<<(W_ELEMS / 4 + 255) / 256, 256>>>(ws[k], wH + (size_t)k * W_ELEMS,
                                                       W_ELEMS / 4);

    // attention on tensor cores
    gemm_score<<<dim3(MIQ / 128, C_CAP), 256, A1_SMEM>>>(rgnH, rgnL, wrdH, wrdL, S);
    attn_norm_kernel<<<dim3(I_IMG, C_CAP), 128>>>(S, lens, attnH, attnL);
    gemm_wei<<<dim3(D_EMB / 128, MIQ / 128, C_CAP), 256, A3_SMEM>>>(
        attnH, attnL, wrdTH, wrdTL, weiH);

    // main GEMM chain
    dim3 ggrid(D_EMB / 128, M_TOT / 128);
    gemm_hmma<EPI_TANH><<<ggrid, 256, G_SMEM>>>(
        weiH, wH + 0 * (size_t)W_ELEMS, b_scale, nullptr, nullptr, scal, nullptr);
    gemm_hmma<EPI_FILM><<<ggrid, 256, G_SMEM>>>(
        weiH, wH + 1 * (size_t)W_ELEMS, b_shift, scal, rgn, nullptr, xH);
    gemm_hmma<EPI_RELU><<<ggrid, 256, G_SMEM>>>(
        xH, wH + 2 * (size_t)W_ELEMS, b1, nullptr, nullptr, nullptr, hH);
    gemm_hmma<EPI_FINAL><<<ggrid, 256, G_SMEM>>>(
        hH, wH + 3 * (size_t)W_ELEMS, b2, nullptr, rgn, out, nullptr);
}

// round 11
// speedup vs baseline: 3.9237x; 1.0181x over previous
#include <cuda_runtime.h>
#include <cuda_fp16.h>
#include <math.h>
#include <stdint.h>

// Problem dims
#define I_IMG 32
#define C_CAP 32
#define Q_RGN 36
#define L_MAX 50
#define LPAD 64
#define D_EMB 1024
#define MIQ (I_IMG * Q_RGN)                    // 1152 rows per caption
#define M_TOT (C_CAP * MIQ)                    // 36864
#define ELEMS ((size_t)M_TOT * D_EMB)
#define W_ELEMS (D_EMB * D_EMB)

// ---------------- scratch (device globals; allocation-free) ----------------
__device__ __align__(256) __half g_weiH[ELEMS];
__device__ __align__(256) __half g_xH[ELEMS];
__device__ __align__(256) __half g_hH[ELEMS];
__device__ __align__(256) __half g_scalH[ELEMS];
__device__ __align__(256) __half g_wH[4][W_ELEMS];
__device__ __align__(256) __half g_rgnH[MIQ * D_EMB];
__device__ __align__(256) __half g_rgnL[MIQ * D_EMB];
__device__ __align__(256) __half g_wrdH[C_CAP * LPAD * D_EMB];
__device__ __align__(256) __half g_wrdL[C_CAP * LPAD * D_EMB];
__device__ __align__(256) __half g_wrdTH[C_CAP * D_EMB * LPAD];
__device__ __align__(256) __half g_wrdTL[C_CAP * D_EMB * LPAD];
__device__ __align__(256) float  g_S[(size_t)C_CAP * MIQ * LPAD];
__device__ __align__(256) __half g_attnH[(size_t)C_CAP * MIQ * LPAD];

__device__ __forceinline__ void split_h(float x, __half& h, __half& l) {
    h = __float2half_rn(x);
    l = __float2half_rn(x - __half2float(h));
}

// ---------------- common HMMA infrastructure ----------------
__device__ __forceinline__ uint32_t smem_u32(const void* p) {
    uint32_t a;
    asm("{ .reg .u64 t; cvta.to.shared.u64 t, %1; cvt.u32.u64 %0, t; }"
        : "=r"(a) : "l"(p));
    return a;
}
__device__ __forceinline__ uint32_t sm_addr(uint32_t base, int row, int c16) {
    return base + row * 64 + (((uint32_t)(c16 ^ ((row >> 1) & 3))) << 4);
}
__device__ __forceinline__ void load_t128(
    const __half* __restrict__ g, int ld, int row0, int kcol0, uint32_t sb, int tid)
{
#pragma unroll
    for (int j = 0; j < 2; j++) {
        int id = tid + 256 * j;
        int r = id >> 2, c = id & 3;
        const void* gp = g + (size_t)(row0 + r) * ld + kcol0 + c * 8;
        asm volatile("cp.async.cg.shared.global [%0], [%1], 16;"
                     :: "r"(sm_addr(sb, r, c)), "l"(gp));
    }
}
__device__ __forceinline__ void load_t64(
    const __half* __restrict__ g, int ld, int row0, int kcol0, uint32_t sb, int tid)
{
    int r = tid >> 2, c = tid & 3;
    const void* gp = g + (size_t)(row0 + r) * ld + kcol0 + c * 8;
    asm volatile("cp.async.cg.shared.global [%0], [%1], 16;"
                 :: "r"(sm_addr(sb, r, c)), "l"(gp));
}

#define LDSM_X4(R, addr) \
    asm volatile("ldmatrix.sync.aligned.m8n8.x4.shared.b16 {%0,%1,%2,%3}, [%4];" \
        : "=r"((R)[0]), "=r"((R)[1]), "=r"((R)[2]), "=r"((R)[3]) : "r"(addr))
#define MMA(C, A, B) \
    asm volatile("mma.sync.aligned.m16n8k16.row.col.f32.f16.f16.f32 " \
        "{%0,%1,%2,%3}, {%4,%5,%6,%7}, {%8,%9}, {%0,%1,%2,%3};" \
        : "+f"((C)[0]), "+f"((C)[1]), "+f"((C)[2]), "+f"((C)[3]) \
        : "r"((A)[0]), "r"((A)[1]), "r"((A)[2]), "r"((A)[3]), "r"((B)[0]), "r"((B)[1]))

// ---------------------------------------------------------------------------
// Prep: one kernel for the 4 weight converts + rgn hi/lo split (task = blockIdx.y)
// ---------------------------------------------------------------------------
__global__ __launch_bounds__(256) void prep_kernel(
    const float* __restrict__ w0, const float* __restrict__ w1,
    const float* __restrict__ w2, const float* __restrict__ w3,
    const float* __restrict__ rgn,
    __half* __restrict__ wH, __half* __restrict__ rgnH, __half* __restrict__ rgnL)
{
    const int task = blockIdx.y;
    const int i = blockIdx.x * 256 + threadIdx.x;
    if (task < 4) {
        if (i < W_ELEMS / 4) {
            const float* s = (task == 0) ? w0 : (task == 1) ? w1 : (task == 2) ? w2 : w3;
            float4 v = ((const float4*)s)[i];
            union { uint2 u; __half h[4]; } o;
            o.h[0] = __float2half_rn(v.x); o.h[1] = __float2half_rn(v.y);
            o.h[2] = __float2half_rn(v.z); o.h[3] = __float2half_rn(v.w);
            ((uint2*)(wH + (size_t)task * W_ELEMS))[i] = o.u;
        }
    } else {
        if (i < MIQ * D_EMB / 4) {
            float4 v = ((const float4*)rgn)[i];
            union { uint2 u; __half h[4]; } oh, ol;
            split_h(v.x, oh.h[0], ol.h[0]); split_h(v.y, oh.h[1], ol.h[1]);
            split_h(v.z, oh.h[2], ol.h[2]); split_h(v.w, oh.h[3], ol.h[3]);
            ((uint2*)rgnH)[i] = oh.u;
            ((uint2*)rgnL)[i] = ol.u;
        }
    }
}

// wrd: (C,50,1024) fp32 -> wrdH/L (C,64,1024) zero-padded + wrdTH/L (C,1024,64)
__global__ __launch_bounds__(256) void wrd_prep_kernel(
    const float* __restrict__ wrd,
    __half* __restrict__ wh, __half* __restrict__ wl,
    __half* __restrict__ wth, __half* __restrict__ wtl)
{
    const int d0 = blockIdx.x * 64;
    const int c = blockIdx.y;
    const int tid = threadIdx.x;
    __shared__ __align__(16) float ts[64][65];

    for (int idx = tid; idx < 64 * 64; idx += 256) {
        int l = idx >> 6, dd = idx & 63;
        float v = (l < L_MAX) ? wrd[((size_t)c * L_MAX + l) * D_EMB + d0 + dd] : 0.f;
        ts[l][dd] = v;
        __half h, lo; split_h(v, h, lo);
        wh[((size_t)c * LPAD + l) * D_EMB + d0 + dd] = h;
        wl[((size_t)c * LPAD + l) * D_EMB + d0 + dd] = lo;
    }
    __syncthreads();
    for (int idx = tid; idx < 64 * 64; idx += 256) {
        int d = idx >> 6, l = idx & 63;
        float v = ts[l][d];
        __half h, lo; split_h(v, h, lo);
        wth[((size_t)c * D_EMB + d0 + d) * LPAD + l] = h;
        wtl[((size_t)c * D_EMB + d0 + d) * LPAD + l] = lo;
    }
}

// ---------------------------------------------------------------------------
// A1: scores  S[c, m=(i,q), l] = leaky( rgn[m,:] . wrd[c,l,:] ), 3-term HMMA.
// ---------------------------------------------------------------------------
#define A1_STAGE (2 * 8192 + 2 * 4096)
#define A1_SMEM (3 * A1_STAGE)             // 72 KB

__global__ __launch_bounds__(256, 1) void gemm_score(
    const __half* __restrict__ Rh, const __half* __restrict__ Rl,
    const __half* __restrict__ Wh, const __half* __restrict__ Wl,
    float* __restrict__ S)
{
    extern __shared__ __align__(1024) uint8_t dsm[];
    const uint32_t sb = smem_u32(dsm);
    const int tid = threadIdx.x;
    const int wid = tid >> 5, lid = tid & 31;
    const int wm = wid & 3, wn = wid >> 2;
    const int m0 = blockIdx.x * 128;
    const int c  = blockIdx.y;

    const __half* Bh = Wh + (size_t)c * LPAD * D_EMB;
    const __half* Bl = Wl + (size_t)c * LPAD * D_EMB;

    const int a_ro = lid & 15, a_co = lid >> 4;
    const int b_ro = ((lid >> 4) & 1) * 8 + (lid & 7);
    const int b_co = (lid >> 3) & 1;

    float acc[2][4][4];
#pragma unroll
    for (int a = 0; a < 2; a++)
#pragma unroll
        for (int b = 0; b < 4; b++)
#pragma unroll
            for (int d = 0; d < 4; d++) acc[a][b][d] = 0.f;

#pragma unroll
    for (int s = 0; s < 2; s++) {
        uint32_t st = sb + s * A1_STAGE;
        load_t128(Rh, D_EMB, m0, s * 32, st, tid);
        load_t128(Rl, D_EMB, m0, s * 32, st + 8192, tid);
        load_t64(Bh, D_EMB, 0, s * 32, st + 16384, tid);
        load_t64(Bl, D_EMB, 0, s * 32, st + 20480, tid);
        asm volatile("cp.async.commit_group;");
    }

    int stage = 0;
    for (int i = 0; i < 32; i++) {
        asm volatile("cp.async.wait_group 1;");
        __syncthreads();
        if (i + 2 < 32) {
            uint32_t st = sb + ((stage + 2) % 3) * A1_STAGE;
            int kc = (i + 2) * 32;
            load_t128(Rh, D_EMB, m0, kc, st, tid);
            load_t128(Rl, D_EMB, m0, kc, st + 8192, tid);
            load_t64(Bh, D_EMB, 0, kc, st + 16384, tid);
            load_t64(Bl, D_EMB, 0, kc, st + 20480, tid);
        }
        asm volatile("cp.async.commit_group;");

        uint32_t stA = sb + stage * A1_STAGE;
#pragma unroll
        for (int ks = 0; ks < 2; ks++) {
            uint32_t aH[2][4], aL[2][4], bH[4][2], bL[4][2];
#pragma unroll
            for (int mi = 0; mi < 2; mi++) {
                LDSM_X4(aH[mi], sm_addr(stA, wm * 32 + mi * 16 + a_ro, ks * 2 + a_co));
                LDSM_X4(aL[mi], sm_addr(stA + 8192, wm * 32 + mi * 16 + a_ro, ks * 2 + a_co));
            }
#pragma unroll
            for (int p = 0; p < 2; p++) {
                uint32_t r[4];
                LDSM_X4(r, sm_addr(stA + 16384, wn * 32 + p * 16 + b_ro, ks * 2 + b_co));
                bH[2 * p][0] = r[0]; bH[2 * p][1] = r[1];
                bH[2 * p + 1][0] = r[2]; bH[2 * p + 1][1] = r[3];
                LDSM_X4(r, sm_addr(stA + 20480, wn * 32 + p * 16 + b_ro, ks * 2 + b_co));
                bL[2 * p][0] = r[0]; bL[2 * p][1] = r[1];
                bL[2 * p + 1][0] = r[2]; bL[2 * p + 1][1] = r[3];
            }
#pragma unroll
            for (int mi = 0; mi < 2; mi++)
#pragma unroll
                for (int nj = 0; nj < 4; nj++) {
                    MMA(acc[mi][nj], aH[mi], bH[nj]);
                    MMA(acc[mi][nj], aH[mi], bL[nj]);
                    MMA(acc[mi][nj], aL[mi], bH[nj]);
                }
        }
        stage = (stage + 1) % 3;
    }

    const int cph = (lid & 3) * 2;
#pragma unroll
    for (int mi = 0; mi < 2; mi++)
#pragma unroll
        for (int hf = 0; hf < 2; hf++) {
            int m = m0 + wm * 32 + mi * 16 + hf * 8 + (lid >> 2);
            float* op = S + ((size_t)c * MIQ + m) * LPAD + wn * 32 + cph;
#pragma unroll
            for (int nj = 0; nj < 4; nj++) {
                float v0 = acc[mi][nj][hf * 2 + 0];
                float v1 = acc[mi][nj][hf * 2 + 1];
                float2 o;
                o.x = (v0 >= 0.f) ? v0 : 0.1f * v0;
                o.y = (v1 >= 0.f) ? v1 : 0.1f * v1;
                *(float2*)(op + nj * 8) = o;
            }
        }
}

// ---------------------------------------------------------------------------
// A2: per (c,i): L2-normalize over q, masked softmax over l -> attn fp16.
// ---------------------------------------------------------------------------
__global__ __launch_bounds__(128) void attn_norm_kernel(
    const float* __restrict__ S, const int* __restrict__ lens,
    __half* __restrict__ attnH)
{
    const int i = blockIdx.x;
    const int c = blockIdx.y;
    const int tid = threadIdx.x;
    __shared__ __align__(16) float s[Q_RGN][68];
    __shared__ __align__(16) __half ah[Q_RGN * LPAD];

    const size_t base = ((size_t)c * MIQ + i * Q_RGN) * LPAD;

    for (int idx = tid; idx < Q_RGN * 16; idx += 128) {
        int q = idx >> 4, f4 = idx & 15;
        float4 v = *(const float4*)(S + base + q * LPAD + f4 * 4);
        *(float4*)&s[q][f4 * 4] = v;
    }
    __syncthreads();

    if (tid < L_MAX) {
        float ss = 0.f;
        for (int q = 0; q < Q_RGN; q++) { float v = s[q][tid]; ss += v * v; }
        float inv = 1.f / fmaxf(sqrtf(ss), 1e-12f);
        for (int q = 0; q < Q_RGN; q++) s[q][tid] *= inv;
    }
    __syncthreads();

    const int len = lens[c];
    if (tid < Q_RGN) {
        float mx = -1e30f;
        for (int l = 0; l < len; l++) mx = fmaxf(mx, s[tid][l]);
        float sum = 0.f;
        for (int l = 0; l < len; l++) sum += expf(9.f * (s[tid][l] - mx));
        float inv = 1.f / sum;
        for (int l = 0; l < LPAD; l++) {
            float a = (l < len) ? expf(9.f * (s[tid][l] - mx)) * inv : 0.f;
            ah[tid * LPAD + l] = __float2half_rn(a);
        }
    }
    __syncthreads();

    for (int u = tid; u < Q_RGN * LPAD / 8; u += 128)
        *(uint4*)(attnH + base + u * 8) = *(const uint4*)(ah + u * 8);
}

// ---------------------------------------------------------------------------
// A3: wei[c,m,d] = sum_l attn[c,m,l]*wrdT[c,d,l]; attn fp16, wrdT hi/lo (2-term).
// ---------------------------------------------------------------------------
#define A3_STAGE (3 * 8192)                // A, Bh, Bl
#define A3_SMEM (2 * A3_STAGE)             // 48 KB -> 2 CTAs/SM

__global__ __launch_bounds__(256, 2) void gemm_wei(
    const __half* __restrict__ AH,
    const __half* __restrict__ WTH, const __half* __restrict__ WTL,
    __half* __restrict__ weiH)
{
    extern __shared__ __align__(1024) uint8_t dsm[];
    const uint32_t sb = smem_u32(dsm);
    const int tid = threadIdx.x;
    const int wid = tid >> 5, lid = tid & 31;
    const int wm = wid & 3, wn = wid >> 2;
    const int n0 = blockIdx.x * 128;
    const int m0 = blockIdx.y * 128;
    const int c  = blockIdx.z;

    const __half* Ah = AH + (size_t)c * MIQ * LPAD;
    const __half* Bh = WTH + (size_t)c * D_EMB * LPAD;
    const __half* Bl = WTL + (size_t)c * D_EMB * LPAD;

    const int a_ro = lid & 15, a_co = lid >> 4;
    const int b_ro = ((lid >> 4) & 1) * 8 + (lid & 7);
    const int b_co = (lid >> 3) & 1;

    float acc[2][8][4];
#pragma unroll
    for (int a = 0; a < 2; a++)
#pragma unroll
        for (int b = 0; b < 8; b++)
#pragma unroll
            for (int d = 0; d < 4; d++) acc[a][b][d] = 0.f;

#pragma unroll
    for (int s = 0; s < 2; s++) {
        uint32_t st = sb + s * A3_STAGE;
        load_t128(Ah, LPAD, m0, s * 32, st, tid);
        load_t128(Bh, LPAD, n0, s * 32, st + 8192, tid);
        load_t128(Bl, LPAD, n0, s * 32, st + 16384, tid);
        asm volatile("cp.async.commit_group;");
    }

#pragma unroll
    for (int i = 0; i < 2; i++) {
        if (i == 0) asm volatile("cp.async.wait_group 1;");
        else        asm volatile("cp.async.wait_group 0;");
        __syncthreads();
        uint32_t stA = sb + i * A3_STAGE;
#pragma unroll
        for (int ks = 0; ks < 2; ks++) {
            uint32_t aH[2][4], bH[8][2], bL[8][2];
#pragma unroll
            for (int mi = 0; mi < 2; mi++)
                LDSM_X4(aH[mi], sm_addr(stA, wm * 32 + mi * 16 + a_ro, ks * 2 + a_co));
#pragma unroll
            for (int p = 0; p < 4; p++) {
                uint32_t r[4];
                LDSM_X4(r, sm_addr(stA + 8192, wn * 64 + p * 16 + b_ro, ks * 2 + b_co));
                bH[2 * p][0] = r[0]; bH[2 * p][1] = r[1];
                bH[2 * p + 1][0] = r[2]; bH[2 * p + 1][1] = r[3];
                LDSM_X4(r, sm_addr(stA + 16384, wn * 64 + p * 16 + b_ro, ks * 2 + b_co));
                bL[2 * p][0] = r[0]; bL[2 * p][1] = r[1];
                bL[2 * p + 1][0] = r[2]; bL[2 * p + 1][1] = r[3];
            }
#pragma unroll
            for (int mi = 0; mi < 2; mi++)
#pragma unroll
                for (int nj = 0; nj < 8; nj++) {
                    MMA(acc[mi][nj], aH[mi], bH[nj]);
                    MMA(acc[mi][nj], aH[mi], bL[nj]);
                }
        }
    }

    const int cph = (lid & 3) * 2;
    const int nbase = n0 + wn * 64;
#pragma unroll
    for (int mi = 0; mi < 2; mi++)
#pragma unroll
        for (int hf = 0; hf < 2; hf++) {
            int m = m0 + wm * 32 + mi * 16 + hf * 8 + (lid >> 2);
            __half* op = weiH + ((size_t)c * MIQ + m) * D_EMB + nbase + cph;
#pragma unroll
            for (int nj = 0; nj < 8; nj++)
                *(__half2*)(op + nj * 8) = __halves2half2(
                    __float2half_rn(acc[mi][nj][hf * 2 + 0]),
                    __float2half_rn(acc[mi][nj][hf * 2 + 1]));
        }
}

// ---------------------------------------------------------------------------
// Main HMMA GEMM (plain fp16): D[m,n] = epi( sum_k A[m,k]*W[n,k] + b )
// ---------------------------------------------------------------------------
#define EPI_TANH 0
#define EPI_FILM 1
#define EPI_RELU 2
#define EPI_FINAL 3

#define G_STAGE (2 * 8192)
#define G_SMEM (3 * G_STAGE)               // 48 KB -> 2 CTAs/SM

template <int EPI>
__global__ __launch_bounds__(256, 2) void gemm_hmma(
    const __half* __restrict__ Ah, const __half* __restrict__ Bh,
    const float* __restrict__ bias,
    const __half* __restrict__ scal,     // FILM input (fp16)
    const float* __restrict__ rgn,
    float* __restrict__ outF,            // FINAL (d_out)
    __half* __restrict__ outH)           // TANH (scal) / FILM (x) / RELU (h)
{
    extern __shared__ __align__(1024) uint8_t dsm[];
    const uint32_t sb = smem_u32(dsm);
    const int tid = threadIdx.x;
    const int wid = tid >> 5, lid = tid & 31;
    const int wm = wid & 3, wn = wid >> 2;
    const int m0 = blockIdx.y * 128;
    const int n0 = blockIdx.x * 128;

    const int a_ro = lid & 15, a_co = lid >> 4;
    const int b_ro = ((lid >> 4) & 1) * 8 + (lid & 7);
    const int b_co = (lid >> 3) & 1;

    float c[2][8][4];
#pragma unroll
    for (int a = 0; a < 2; a++)
#pragma unroll
        for (int b = 0; b < 8; b++)
#pragma unroll
            for (int d = 0; d < 4; d++) c[a][b][d] = 0.f;

#pragma unroll
    for (int s = 0; s < 2; s++) {
        uint32_t st = sb + s * G_STAGE;
        load_t128(Ah, D_EMB, m0, s * 32, st, tid);
        load_t128(Bh, D_EMB, n0, s * 32, st + 8192, tid);
        asm volatile("cp.async.commit_group;");
    }

    int stage = 0;
    for (int i = 0; i < 32; i++) {
        asm volatile("cp.async.wait_group 1;");
        __syncthreads();
        if (i + 2 < 32) {
            uint32_t st = sb + ((stage + 2) % 3) * G_STAGE;
            int kc = (i + 2) * 32;
            load_t128(Ah, D_EMB, m0, kc, st, tid);
            load_t128(Bh, D_EMB, n0, kc, st + 8192, tid);
        }
        asm volatile("cp.async.commit_group;");

        uint32_t stA = sb + stage * G_STAGE;
#pragma unroll
        for (int ks = 0; ks < 2; ks++) {
            uint32_t aH[2][4], bH[8][2];
#pragma unroll
            for (int mi = 0; mi < 2; mi++)
                LDSM_X4(aH[mi], sm_addr(stA, wm * 32 + mi * 16 + a_ro, ks * 2 + a_co));
#pragma unroll
            for (int p = 0; p < 4; p++) {
                uint32_t r[4];
                LDSM_X4(r, sm_addr(stA + 8192, wn * 64 + p * 16 + b_ro, ks * 2 + b_co));
                bH[2 * p][0] = r[0]; bH[2 * p][1] = r[1];
                bH[2 * p + 1][0] = r[2]; bH[2 * p + 1][1] = r[3];
            }
#pragma unroll
            for (int mi = 0; mi < 2; mi++)
#pragma unroll
                for (int nj = 0; nj < 8; nj++)
                    MMA(c[mi][nj], aH[mi], bH[nj]);
        }
        stage = (stage + 1) % 3;
    }

    const int nbase = n0 + wn * 64;
    const int mbase = m0 + wm * 32;
    const int cph = (lid & 3) * 2;

    float2 bv[8];
#pragma unroll
    for (int nj = 0; nj < 8; nj++)
        bv[nj] = *(const float2*)(bias + nbase + nj * 8 + cph);

#pragma unroll
    for (int mi = 0; mi < 2; mi++) {
#pragma unroll
        for (int hf = 0; hf < 2; hf++) {
            const int m = mbase + mi * 16 + hf * 8 + (lid >> 2);
            const int t = m / Q_RGN;
            const int q = m - t * Q_RGN;
            const int i_img = t & (I_IMG - 1);
            const int cc = t >> 5;

            if (EPI == EPI_TANH) {
                size_t ob = (size_t)m * D_EMB + nbase + cph;
#pragma unroll
                for (int nj = 0; nj < 8; nj++) {
                    float x0 = tanhf(c[mi][nj][hf * 2 + 0] + bv[nj].x);
                    float x1 = tanhf(c[mi][nj][hf * 2 + 1] + bv[nj].y);
                    *(__half2*)(outH + ob + nj * 8) =
                        __halves2half2(__float2half_rn(x0), __float2half_rn(x1));
                }
            } else if (EPI == EPI_FILM) {
                const float* rp = rgn + ((size_t)(i_img * Q_RGN + q)) * D_EMB + nbase + cph;
                const __half* sp = scal + (size_t)m * D_EMB + nbase + cph;
                size_t ob = (size_t)m * D_EMB + nbase + cph;
#pragma unroll
                for (int nj = 0; nj < 8; nj++) {
                    float2 rv = *(const float2*)(rp + nj * 8);
                    float2 sv = __half22float2(*(const __half2*)(sp + nj * 8));
                    float x0 = rv.x * sv.x + (c[mi][nj][hf * 2 + 0] + bv[nj].x);
                    float x1 = rv.y * sv.y + (c[mi][nj][hf * 2 + 1] + bv[nj].y);
                    *(__half2*)(outH + ob + nj * 8) =
                        __halves2half2(__float2half_rn(x0), __float2half_rn(x1));
                }
            } else if (EPI == EPI_RELU) {
                size_t ob = (size_t)m * D_EMB + nbase + cph;
#pragma unroll
                for (int nj = 0; nj < 8; nj++) {
                    float x0 = fmaxf(c[mi][nj][hf * 2 + 0] + bv[nj].x, 0.f);
                    float x1 = fmaxf(c[mi][nj][hf * 2 + 1] + bv[nj].y, 0.f);
                    *(__half2*)(outH + ob + nj * 8) =
                        __halves2half2(__float2half_rn(x0), __float2half_rn(x1));
                }
            } else {
                const float* rp = rgn + ((size_t)(i_img * Q_RGN + q)) * D_EMB + nbase + cph;
                float* op = outF + (((size_t)(i_img * C_CAP + cc)) * Q_RGN + q) * D_EMB + nbase + cph;
#pragma unroll
                for (int nj = 0; nj < 8; nj++) {
                    float2 rv = *(const float2*)(rp + nj * 8);
                    float2 o;
                    o.x = c[mi][nj][hf * 2 + 0] + bv[nj].x + rv.x;
                    o.y = c[mi][nj][hf * 2 + 1] + bv[nj].y + rv.y;
                    *(float2*)(op + nj * 8) = o;
                }
            }
        }
    }
}

// ---------------------------------------------------------------------------
extern "C" void kernel_launch(void* const* d_in, const int* in_sizes, int n_in,
                              void* d_out, int out_size)
{
    const float* rgn     = (const float*)d_in[0];
    const float* wrd     = (const float*)d_in[2];
    const int*   lens    = (const int*)d_in[4];
    const float* w_scale = (const float*)d_in[5];
    const float* b_scale = (const float*)d_in[6];
    const float* w_shift = (const float*)d_in[7];
    const float* b_shift = (const float*)d_in[8];
    const float* w1      = (const float*)d_in[9];
    const float* b1      = (const float*)d_in[10];
    const float* w2      = (const float*)d_in[11];
    const float* b2      = (const float*)d_in[12];
    float* out = (float*)d_out;

    __half *weiH, *xH, *hH, *scalH, *wH, *rgnH, *rgnL, *wrdH, *wrdL, *wrdTH, *wrdTL, *attnH;
    float *S;
    cudaGetSymbolAddress((void**)&weiH,  g_weiH);
    cudaGetSymbolAddress((void**)&xH,    g_xH);
    cudaGetSymbolAddress((void**)&hH,    g_hH);
    cudaGetSymbolAddress((void**)&scalH, g_scalH);
    cudaGetSymbolAddress((void**)&wH,    g_wH);
    cudaGetSymbolAddress((void**)&rgnH,  g_rgnH);
    cudaGetSymbolAddress((void**)&rgnL,  g_rgnL);
    cudaGetSymbolAddress((void**)&wrdH,  g_wrdH);
    cudaGetSymbolAddress((void**)&wrdL,  g_wrdL);
    cudaGetSymbolAddress((void**)&wrdTH, g_wrdTH);
    cudaGetSymbolAddress((void**)&wrdTL, g_wrdTL);
    cudaGetSymbolAddress((void**)&attnH, g_attnH);
    cudaGetSymbolAddress((void**)&S,     g_S);

    cudaFuncSetAttribute(gemm_score, cudaFuncAttributeMaxDynamicSharedMemorySize, A1_SMEM);
    cudaFuncSetAttribute(gemm_wei,   cudaFuncAttributeMaxDynamicSharedMemorySize, A3_SMEM);
    cudaFuncSetAttribute(gemm_hmma<EPI_TANH>,  cudaFuncAttributeMaxDynamicSharedMemorySize, G_SMEM);
    cudaFuncSetAttribute(gemm_hmma<EPI_FILM>,  cudaFuncAttributeMaxDynamicSharedMemorySize, G_SMEM);
    cudaFuncSetAttribute(gemm_hmma<EPI_RELU>,  cudaFuncAttributeMaxDynamicSharedMemorySize, G_SMEM);
    cudaFuncSetAttribute(gemm_hmma<EPI_FINAL>, cudaFuncAttributeMaxDynamicSharedMemorySize, G_SMEM);

    // launch 0: all weight converts + rgn split (one kernel)
    prep_kernel<<<dim3((MIQ * D_EMB / 4 + 255) / 256, 5), 256>>>(
        w_scale, w_shift, w1, w2, rgn, wH, rgnH, rgnL);
    // launch 1: wrd pad/split/transpose
    wrd_prep_kernel<<<dim3(D_EMB / 64, C_CAP), 256>>>(wrd, wrdH, wrdL, wrdTH, wrdTL);

    // launches 2-4: attention on tensor cores
    gemm_score<<<dim3(MIQ / 128, C_CAP), 256, A1_SMEM>>>(rgnH, rgnL, wrdH, wrdL, S);
    attn_norm_kernel<<<dim3(I_IMG, C_CAP), 128>>>(S, lens, attnH);
    gemm_wei<<<dim3(D_EMB / 128, MIQ / 128, C_CAP), 256, A3_SMEM>>>(
        attnH, wrdTH, wrdTL, weiH);

    // launches 5-8: main GEMM chain (launch 5 = ncu capture target)
    dim3 ggrid(D_EMB / 128, M_TOT / 128);
    gemm_hmma<EPI_TANH><<<ggrid, 256, G_SMEM>>>(
        weiH, wH + 0 * (size_t)W_ELEMS, b_scale, nullptr, nullptr, nullptr, scalH);
    gemm_hmma<EPI_FILM><<<ggrid, 256, G_SMEM>>>(
        weiH, wH + 1 * (size_t)W_ELEMS, b_shift, scalH, rgn, nullptr, xH);
    gemm_hmma<EPI_RELU><<<ggrid, 256, G_SMEM>>>(
        xH, wH + 2 * (size_t)W_ELEMS, b1, nullptr, nullptr, nullptr, hH);
    gemm_hmma<EPI_FINAL><<<ggrid, 256, G_SMEM>>>(
        hH, wH + 3 * (size_t)W_ELEMS, b2, nullptr, rgn, out, nullptr);
}

// round 13
// speedup vs baseline: 4.1656x; 1.0617x over previous
#include <cuda_runtime.h>
#include <cuda_fp16.h>
#include <math.h>
#include <stdint.h>

// Problem dims
#define I_IMG 32
#define C_CAP 32
#define Q_RGN 36
#define L_MAX 50
#define LPAD 64
#define D_EMB 1024
#define MIQ (I_IMG * Q_RGN)                    // 1152
#define M_TOT (C_CAP * MIQ)                    // 36864
#define ELEMS ((size_t)M_TOT * D_EMB)
#define W_ELEMS (D_EMB * D_EMB)

// ---------------- scratch ----------------
__device__ __align__(256) __half g_weiH[ELEMS];
__device__ __align__(256) __half g_xH[ELEMS];
__device__ __align__(256) __half g_hH[ELEMS];
__device__ __align__(256) __half g_scalH[ELEMS];
__device__ __align__(256) __half g_wH[4][W_ELEMS];
__device__ __align__(256) __half g_rgnH[MIQ * D_EMB];
__device__ __align__(256) __half g_rgnL[MIQ * D_EMB];
__device__ __align__(256) __half g_wrdH[C_CAP * LPAD * D_EMB];
__device__ __align__(256) __half g_wrdL[C_CAP * LPAD * D_EMB];
__device__ __align__(256) __half g_wrdTH[C_CAP * D_EMB * LPAD];
__device__ __align__(256) __half g_wrdTL[C_CAP * D_EMB * LPAD];
__device__ __align__(256) float  g_S[(size_t)C_CAP * MIQ * LPAD];
__device__ __align__(256) __half g_attnH[(size_t)C_CAP * MIQ * LPAD];

__device__ __forceinline__ void split_h(float x, __half& h, __half& l) {
    h = __float2half_rn(x);
    l = __float2half_rn(x - __half2float(h));
}

// ---------------- common HMMA infrastructure ----------------
__device__ __forceinline__ uint32_t smem_u32(const void* p) {
    uint32_t a;
    asm("{ .reg .u64 t; cvta.to.shared.u64 t, %1; cvt.u32.u64 %0, t; }"
        : "=r"(a) : "l"(p));
    return a;
}
// 64B-row tiles (attention kernels)
__device__ __forceinline__ uint32_t sm_addr(uint32_t base, int row, int c16) {
    return base + row * 64 + (((uint32_t)(c16 ^ ((row >> 1) & 3))) << 4);
}
// 128B-row tiles (chain GEMM, BK=64)
__device__ __forceinline__ uint32_t sm_addr128(uint32_t base, int row, int c16) {
    return base + row * 128 + (((uint32_t)(c16 ^ (row & 7))) << 4);
}
__device__ __forceinline__ void load_t128(
    const __half* __restrict__ g, int ld, int row0, int kcol0, uint32_t sb, int tid)
{
#pragma unroll
    for (int j = 0; j < 2; j++) {
        int id = tid + 256 * j;
        int r = id >> 2, c = id & 3;
        const void* gp = g + (size_t)(row0 + r) * ld + kcol0 + c * 8;
        asm volatile("cp.async.cg.shared.global [%0], [%1], 16;"
                     :: "r"(sm_addr(sb, r, c)), "l"(gp));
    }
}
__device__ __forceinline__ void load_t64(
    const __half* __restrict__ g, int ld, int row0, int kcol0, uint32_t sb, int tid)
{
    int r = tid >> 2, c = tid & 3;
    const void* gp = g + (size_t)(row0 + r) * ld + kcol0 + c * 8;
    asm volatile("cp.async.cg.shared.global [%0], [%1], 16;"
                 :: "r"(sm_addr(sb, r, c)), "l"(gp));
}
// 128 rows x 64 cols (128B/row)
__device__ __forceinline__ void load_t128w(
    const __half* __restrict__ g, int ld, int row0, int kcol0, uint32_t sb, int tid)
{
#pragma unroll
    for (int j = 0; j < 4; j++) {
        int id = tid + 256 * j;         // 0..1023
        int r = id >> 3, c = id & 7;
        const void* gp = g + (size_t)(row0 + r) * ld + kcol0 + c * 8;
        asm volatile("cp.async.cg.shared.global [%0], [%1], 16;"
                     :: "r"(sm_addr128(sb, r, c)), "l"(gp));
    }
}

#define LDSM_X4(R, addr) \
    asm volatile("ldmatrix.sync.aligned.m8n8.x4.shared.b16 {%0,%1,%2,%3}, [%4];" \
        : "=r"((R)[0]), "=r"((R)[1]), "=r"((R)[2]), "=r"((R)[3]) : "r"(addr))
#define MMA(C, A, B) \
    asm volatile("mma.sync.aligned.m16n8k16.row.col.f32.f16.f16.f32 " \
        "{%0,%1,%2,%3}, {%4,%5,%6,%7}, {%8,%9}, {%0,%1,%2,%3};" \
        : "+f"((C)[0]), "+f"((C)[1]), "+f"((C)[2]), "+f"((C)[3]) \
        : "r"((A)[0]), "r"((A)[1]), "r"((A)[2]), "r"((A)[3]), "r"((B)[0]), "r"((B)[1]))

// ---------------------------------------------------------------------------
// Prep: 4 weight converts + rgn hi/lo split (task = blockIdx.y)
// ---------------------------------------------------------------------------
__global__ __launch_bounds__(256) void prep_kernel(
    const float* __restrict__ w0, const float* __restrict__ w1,
    const float* __restrict__ w2, const float* __restrict__ w3,
    const float* __restrict__ rgn,
    __half* __restrict__ wH, __half* __restrict__ rgnH, __half* __restrict__ rgnL)
{
    const int task = blockIdx.y;
    const int i = blockIdx.x * 256 + threadIdx.x;
    if (task < 4) {
        if (i < W_ELEMS / 4) {
            const float* s = (task == 0) ? w0 : (task == 1) ? w1 : (task == 2) ? w2 : w3;
            float4 v = ((const float4*)s)[i];
            union { uint2 u; __half h[4]; } o;
            o.h[0] = __float2half_rn(v.x); o.h[1] = __float2half_rn(v.y);
            o.h[2] = __float2half_rn(v.z); o.h[3] = __float2half_rn(v.w);
            ((uint2*)(wH + (size_t)task * W_ELEMS))[i] = o.u;
        }
    } else {
        if (i < MIQ * D_EMB / 4) {
            float4 v = ((const float4*)rgn)[i];
            union { uint2 u; __half h[4]; } oh, ol;
            split_h(v.x, oh.h[0], ol.h[0]); split_h(v.y, oh.h[1], ol.h[1]);
            split_h(v.z, oh.h[2], ol.h[2]); split_h(v.w, oh.h[3], ol.h[3]);
            ((uint2*)rgnH)[i] = oh.u;
            ((uint2*)rgnL)[i] = ol.u;
        }
    }
}

// wrd: (C,50,1024) fp32 -> wrdH/L (C,64,1024) zero-padded + wrdTH/L (C,1024,64)
__global__ __launch_bounds__(256) void wrd_prep_kernel(
    const float* __restrict__ wrd,
    __half* __restrict__ wh, __half* __restrict__ wl,
    __half* __restrict__ wth, __half* __restrict__ wtl)
{
    const int d0 = blockIdx.x * 64;
    const int c = blockIdx.y;
    const int tid = threadIdx.x;
    __shared__ __align__(16) float ts[64][65];

    for (int idx = tid; idx < 64 * 64; idx += 256) {
        int l = idx >> 6, dd = idx & 63;
        float v = (l < L_MAX) ? wrd[((size_t)c * L_MAX + l) * D_EMB + d0 + dd] : 0.f;
        ts[l][dd] = v;
        __half h, lo; split_h(v, h, lo);
        wh[((size_t)c * LPAD + l) * D_EMB + d0 + dd] = h;
        wl[((size_t)c * LPAD + l) * D_EMB + d0 + dd] = lo;
    }
    __syncthreads();
    for (int idx = tid; idx < 64 * 64; idx += 256) {
        int d = idx >> 6, l = idx & 63;
        float v = ts[l][d];
        __half h, lo; split_h(v, h, lo);
        wth[((size_t)c * D_EMB + d0 + d) * LPAD + l] = h;
        wtl[((size_t)c * D_EMB + d0 + d) * LPAD + l] = lo;
    }
}

// ---------------------------------------------------------------------------
// A1: scores  S[c, m=(i,q), l] = leaky( rgn[m,:] . wrd[c,l,:] ), 3-term HMMA.
// ---------------------------------------------------------------------------
#define A1_STAGE (2 * 8192 + 2 * 4096)
#define A1_SMEM (3 * A1_STAGE)             // 72 KB

__global__ __launch_bounds__(256, 1) void gemm_score(
    const __half* __restrict__ Rh, const __half* __restrict__ Rl,
    const __half* __restrict__ Wh, const __half* __restrict__ Wl,
    float* __restrict__ S)
{
    extern __shared__ __align__(1024) uint8_t dsm[];
    const uint32_t sb = smem_u32(dsm);
    const int tid = threadIdx.x;
    const int wid = tid >> 5, lid = tid & 31;
    const int wm = wid & 3, wn = wid >> 2;
    const int m0 = blockIdx.x * 128;
    const int c  = blockIdx.y;

    const __half* Bh = Wh + (size_t)c * LPAD * D_EMB;
    const __half* Bl = Wl + (size_t)c * LPAD * D_EMB;

    const int a_ro = lid & 15, a_co = lid >> 4;
    const int b_ro = ((lid >> 4) & 1) * 8 + (lid & 7);
    const int b_co = (lid >> 3) & 1;

    float acc[2][4][4];
#pragma unroll
    for (int a = 0; a < 2; a++)
#pragma unroll
        for (int b = 0; b < 4; b++)
#pragma unroll
            for (int d = 0; d < 4; d++) acc[a][b][d] = 0.f;

#pragma unroll
    for (int s = 0; s < 2; s++) {
        uint32_t st = sb + s * A1_STAGE;
        load_t128(Rh, D_EMB, m0, s * 32, st, tid);
        load_t128(Rl, D_EMB, m0, s * 32, st + 8192, tid);
        load_t64(Bh, D_EMB, 0, s * 32, st + 16384, tid);
        load_t64(Bl, D_EMB, 0, s * 32, st + 20480, tid);
        asm volatile("cp.async.commit_group;");
    }

    int stage = 0;
    for (int i = 0; i < 32; i++) {
        asm volatile("cp.async.wait_group 1;");
        __syncthreads();
        if (i + 2 < 32) {
            uint32_t st = sb + ((stage + 2) % 3) * A1_STAGE;
            int kc = (i + 2) * 32;
            load_t128(Rh, D_EMB, m0, kc, st, tid);
            load_t128(Rl, D_EMB, m0, kc, st + 8192, tid);
            load_t64(Bh, D_EMB, 0, kc, st + 16384, tid);
            load_t64(Bl, D_EMB, 0, kc, st + 20480, tid);
        }
        asm volatile("cp.async.commit_group;");

        uint32_t stA = sb + stage * A1_STAGE;
#pragma unroll
        for (int ks = 0; ks < 2; ks++) {
            uint32_t aH[2][4], aL[2][4], bH[4][2], bL[4][2];
#pragma unroll
            for (int mi = 0; mi < 2; mi++) {
                LDSM_X4(aH[mi], sm_addr(stA, wm * 32 + mi * 16 + a_ro, ks * 2 + a_co));
                LDSM_X4(aL[mi], sm_addr(stA + 8192, wm * 32 + mi * 16 + a_ro, ks * 2 + a_co));
            }
#pragma unroll
            for (int p = 0; p < 2; p++) {
                uint32_t r[4];
                LDSM_X4(r, sm_addr(stA + 16384, wn * 32 + p * 16 + b_ro, ks * 2 + b_co));
                bH[2 * p][0] = r[0]; bH[2 * p][1] = r[1];
                bH[2 * p + 1][0] = r[2]; bH[2 * p + 1][1] = r[3];
                LDSM_X4(r, sm_addr(stA + 20480, wn * 32 + p * 16 + b_ro, ks * 2 + b_co));
                bL[2 * p][0] = r[0]; bL[2 * p][1] = r[1];
                bL[2 * p + 1][0] = r[2]; bL[2 * p + 1][1] = r[3];
            }
#pragma unroll
            for (int mi = 0; mi < 2; mi++)
#pragma unroll
                for (int nj = 0; nj < 4; nj++) {
                    MMA(acc[mi][nj], aH[mi], bH[nj]);
                    MMA(acc[mi][nj], aH[mi], bL[nj]);
                    MMA(acc[mi][nj], aL[mi], bH[nj]);
                }
        }
        stage = (stage + 1) % 3;
    }

    const int cph = (lid & 3) * 2;
#pragma unroll
    for (int mi = 0; mi < 2; mi++)
#pragma unroll
        for (int hf = 0; hf < 2; hf++) {
            int m = m0 + wm * 32 + mi * 16 + hf * 8 + (lid >> 2);
            float* op = S + ((size_t)c * MIQ + m) * LPAD + wn * 32 + cph;
#pragma unroll
            for (int nj = 0; nj < 4; nj++) {
                float v0 = acc[mi][nj][hf * 2 + 0];
                float v1 = acc[mi][nj][hf * 2 + 1];
                float2 o;
                o.x = (v0 >= 0.f) ? v0 : 0.1f * v0;
                o.y = (v1 >= 0.f) ? v1 : 0.1f * v1;
                *(float2*)(op + nj * 8) = o;
            }
        }
}

// ---------------------------------------------------------------------------
// A2: per (c,i): L2-normalize over q, masked softmax over l -> attn fp16.
// All shuffles executed by ALL threads (no divergent shfl!).
// ---------------------------------------------------------------------------
__global__ __launch_bounds__(128) void attn_norm_kernel(
    const float* __restrict__ S, const int* __restrict__ lens,
    __half* __restrict__ attnH)
{
    const int i = blockIdx.x;
    const int c = blockIdx.y;
    const int tid = threadIdx.x;
    __shared__ __align__(16) float s[Q_RGN][68];
    __shared__ __align__(16) float sinv[LPAD];
    __shared__ __align__(16) __half ah[Q_RGN * LPAD];

    const size_t base = ((size_t)c * MIQ + i * Q_RGN) * LPAD;

    for (int idx = tid; idx < Q_RGN * 16; idx += 128) {
        int q = idx >> 4, f4 = idx & 15;
        float4 v = *(const float4*)(S + base + q * LPAD + f4 * 4);
        *(float4*)&s[q][f4 * 4] = v;
    }
    __syncthreads();

    // L2 norm over q per l: 2 threads per l (all 128 threads active)
    {
        const int l = tid >> 1, hf = tid & 1;
        float ss = 0.f;
        for (int q = hf * 18; q < hf * 18 + 18; q++) {
            float v = s[q][l]; ss += v * v;
        }
        ss += __shfl_xor_sync(0xffffffffu, ss, 1);
        if (hf == 0) sinv[l] = 1.f / fmaxf(sqrtf(ss), 1e-12f);
    }
    __syncthreads();

    const int len = lens[c];
    // softmax over l per q: 2 threads per q. Shuffles unconditional; only
    // smem accesses are guarded (threads with q >= Q_RGN compute garbage).
    {
        const int q = tid >> 1, hf = tid & 1;
        const bool act = (q < Q_RGN);
        const int l0 = hf * 32;
        const int l1 = min(len, l0 + 32);
        float mx = -1e30f;
        if (act)
            for (int l = l0; l < l1; l++) mx = fmaxf(mx, s[q][l] * sinv[l]);
        mx = fmaxf(mx, __shfl_xor_sync(0xffffffffu, mx, 1));
        float sum = 0.f;
        if (act)
            for (int l = l0; l < l1; l++) {
                float e = expf(9.f * (s[q][l] * sinv[l] - mx));
                s[q][l] = e;
                sum += e;
            }
        sum += __shfl_xor_sync(0xffffffffu, sum, 1);
        if (act) {
            float inv = 1.f / sum;
            for (int l = l0; l < l0 + 32; l++)
                ah[q * LPAD + l] = __float2half_rn((l < l1) ? s[q][l] * inv : 0.f);
        }
    }
    __syncthreads();

    for (int u = tid; u < Q_RGN * LPAD / 8; u += 128)
        *(uint4*)(attnH + base + u * 8) = *(const uint4*)(ah + u * 8);
}

// ---------------------------------------------------------------------------
// A3: wei[c,m,d] = sum_l attn[c,m,l]*wrdT[c,d,l]; attn fp16, wrdT hi/lo.
// ---------------------------------------------------------------------------
#define A3_STAGE (3 * 8192)
#define A3_SMEM (2 * A3_STAGE)             // 48 KB

__global__ __launch_bounds__(256, 2) void gemm_wei(
    const __half* __restrict__ AH,
    const __half* __restrict__ WTH, const __half* __restrict__ WTL,
    __half* __restrict__ weiH)
{
    extern __shared__ __align__(1024) uint8_t dsm[];
    const uint32_t sb = smem_u32(dsm);
    const int tid = threadIdx.x;
    const int wid = tid >> 5, lid = tid & 31;
    const int wm = wid & 3, wn = wid >> 2;
    const int n0 = blockIdx.x * 128;
    const int m0 = blockIdx.y * 128;
    const int c  = blockIdx.z;

    const __half* Ah = AH + (size_t)c * MIQ * LPAD;
    const __half* Bh = WTH + (size_t)c * D_EMB * LPAD;
    const __half* Bl = WTL + (size_t)c * D_EMB * LPAD;

    const int a_ro = lid & 15, a_co = lid >> 4;
    const int b_ro = ((lid >> 4) & 1) * 8 + (lid & 7);
    const int b_co = (lid >> 3) & 1;

    float acc[2][8][4];
#pragma unroll
    for (int a = 0; a < 2; a++)
#pragma unroll
        for (int b = 0; b < 8; b++)
#pragma unroll
            for (int d = 0; d < 4; d++) acc[a][b][d] = 0.f;

#pragma unroll
    for (int s = 0; s < 2; s++) {
        uint32_t st = sb + s * A3_STAGE;
        load_t128(Ah, LPAD, m0, s * 32, st, tid);
        load_t128(Bh, LPAD, n0, s * 32, st + 8192, tid);
        load_t128(Bl, LPAD, n0, s * 32, st + 16384, tid);
        asm volatile("cp.async.commit_group;");
    }

#pragma unroll
    for (int i = 0; i < 2; i++) {
        if (i == 0) asm volatile("cp.async.wait_group 1;");
        else        asm volatile("cp.async.wait_group 0;");
        __syncthreads();
        uint32_t stA = sb + i * A3_STAGE;
#pragma unroll
        for (int ks = 0; ks < 2; ks++) {
            uint32_t aH[2][4], bH[8][2], bL[8][2];
#pragma unroll
            for (int mi = 0; mi < 2; mi++)
                LDSM_X4(aH[mi], sm_addr(stA, wm * 32 + mi * 16 + a_ro, ks * 2 + a_co));
#pragma unroll
            for (int p = 0; p < 4; p++) {
                uint32_t r[4];
                LDSM_X4(r, sm_addr(stA + 8192, wn * 64 + p * 16 + b_ro, ks * 2 + b_co));
                bH[2 * p][0] = r[0]; bH[2 * p][1] = r[1];
                bH[2 * p + 1][0] = r[2]; bH[2 * p + 1][1] = r[3];
                LDSM_X4(r, sm_addr(stA + 16384, wn * 64 + p * 16 + b_ro, ks * 2 + b_co));
                bL[2 * p][0] = r[0]; bL[2 * p][1] = r[1];
                bL[2 * p + 1][0] = r[2]; bL[2 * p + 1][1] = r[3];
            }
#pragma unroll
            for (int mi = 0; mi < 2; mi++)
#pragma unroll
                for (int nj = 0; nj < 8; nj++) {
                    MMA(acc[mi][nj], aH[mi], bH[nj]);
                    MMA(acc[mi][nj], aH[mi], bL[nj]);
                }
        }
    }

    const int cph = (lid & 3) * 2;
    const int nbase = n0 + wn * 64;
#pragma unroll
    for (int mi = 0; mi < 2; mi++)
#pragma unroll
        for (int hf = 0; hf < 2; hf++) {
            int m = m0 + wm * 32 + mi * 16 + hf * 8 + (lid >> 2);
            __half* op = weiH + ((size_t)c * MIQ + m) * D_EMB + nbase + cph;
#pragma unroll
            for (int nj = 0; nj < 8; nj++)
                *(__half2*)(op + nj * 8) = __halves2half2(
                    __float2half_rn(acc[mi][nj][hf * 2 + 0]),
                    __float2half_rn(acc[mi][nj][hf * 2 + 1]));
        }
}

// ---------------------------------------------------------------------------
// Main HMMA GEMM (plain fp16, BK=64, 128B-row swizzle, 2 CTAs/SM)
// ---------------------------------------------------------------------------
#define EPI_TANH 0
#define EPI_FILM 1
#define EPI_RELU 2
#define EPI_FINAL 3

#define G_TILE 16384                       // 128 rows x 128 B
#define G_STAGE (2 * G_TILE)               // A, B = 32 KB
#define G_SMEM (3 * G_STAGE)               // 96 KB; 2 CTAs = 192 KB

template <int EPI>
__global__ __launch_bounds__(256, 2) void gemm_hmma(
    const __half* __restrict__ Ah, const __half* __restrict__ Bh,
    const float* __restrict__ bias,
    const __half* __restrict__ scal,
    const float* __restrict__ rgn,
    float* __restrict__ outF,
    __half* __restrict__ outH)
{
    extern __shared__ __align__(1024) uint8_t dsm[];
    const uint32_t sb = smem_u32(dsm);
    const int tid = threadIdx.x;
    const int wid = tid >> 5, lid = tid & 31;
    const int wm = wid & 3, wn = wid >> 2;
    const int m0 = blockIdx.y * 128;
    const int n0 = blockIdx.x * 128;

    const int a_ro = lid & 15, a_co = lid >> 4;
    const int b_ro = ((lid >> 4) & 1) * 8 + (lid & 7);
    const int b_co = (lid >> 3) & 1;

    float c[2][8][4];
#pragma unroll
    for (int a = 0; a < 2; a++)
#pragma unroll
        for (int b = 0; b < 8; b++)
#pragma unroll
            for (int d = 0; d < 4; d++) c[a][b][d] = 0.f;

#pragma unroll
    for (int s = 0; s < 2; s++) {
        uint32_t st = sb + s * G_STAGE;
        load_t128w(Ah, D_EMB, m0, s * 64, st, tid);
        load_t128w(Bh, D_EMB, n0, s * 64, st + G_TILE, tid);
        asm volatile("cp.async.commit_group;");
    }

    int stage = 0;
    for (int i = 0; i < 16; i++) {
        asm volatile("cp.async.wait_group 1;");
        __syncthreads();
        if (i + 2 < 16) {
            uint32_t st = sb + ((stage + 2) % 3) * G_STAGE;
            int kc = (i + 2) * 64;
            load_t128w(Ah, D_EMB, m0, kc, st, tid);
            load_t128w(Bh, D_EMB, n0, kc, st + G_TILE, tid);
        }
        asm volatile("cp.async.commit_group;");

        uint32_t stA = sb + stage * G_STAGE;
#pragma unroll
        for (int ks = 0; ks < 4; ks++) {
            uint32_t aH[2][4], bH[8][2];
#pragma unroll
            for (int mi = 0; mi < 2; mi++)
                LDSM_X4(aH[mi], sm_addr128(stA, wm * 32 + mi * 16 + a_ro, ks * 2 + a_co));
#pragma unroll
            for (int p = 0; p < 4; p++) {
                uint32_t r[4];
                LDSM_X4(r, sm_addr128(stA + G_TILE, wn * 64 + p * 16 + b_ro, ks * 2 + b_co));
                bH[2 * p][0] = r[0]; bH[2 * p][1] = r[1];
                bH[2 * p + 1][0] = r[2]; bH[2 * p + 1][1] = r[3];
            }
#pragma unroll
            for (int mi = 0; mi < 2; mi++)
#pragma unroll
                for (int nj = 0; nj < 8; nj++)
                    MMA(c[mi][nj], aH[mi], bH[nj]);
        }
        stage = (stage + 1) % 3;
    }

    const int nbase = n0 + wn * 64;
    const int mbase = m0 + wm * 32;
    const int cph = (lid & 3) * 2;

    float2 bv[8];
#pragma unroll
    for (int nj = 0; nj < 8; nj++)
        bv[nj] = *(const float2*)(bias + nbase + nj * 8 + cph);

#pragma unroll
    for (int mi = 0; mi < 2; mi++) {
#pragma unroll
        for (int hf = 0; hf < 2; hf++) {
            const int m = mbase + mi * 16 + hf * 8 + (lid >> 2);
            const int t = m / Q_RGN;
            const int q = m - t * Q_RGN;
            const int i_img = t & (I_IMG - 1);
            const int cc = t >> 5;

            if (EPI == EPI_TANH) {
                size_t ob = (size_t)m * D_EMB + nbase + cph;
#pragma unroll
                for (int nj = 0; nj < 8; nj++) {
                    float x0 = tanhf(c[mi][nj][hf * 2 + 0] + bv[nj].x);
                    float x1 = tanhf(c[mi][nj][hf * 2 + 1] + bv[nj].y);
                    *(__half2*)(outH + ob + nj * 8) =
                        __halves2half2(__float2half_rn(x0), __float2half_rn(x1));
                }
            } else if (EPI == EPI_FILM) {
                const float* rp = rgn + ((size_t)(i_img * Q_RGN + q)) * D_EMB + nbase + cph;
                const __half* sp = scal + (size_t)m * D_EMB + nbase + cph;
                size_t ob = (size_t)m * D_EMB + nbase + cph;
#pragma unroll
                for (int nj = 0; nj < 8; nj++) {
                    float2 rv = *(const float2*)(rp + nj * 8);
                    float2 sv = __half22float2(*(const __half2*)(sp + nj * 8));
                    float x0 = rv.x * sv.x + (c[mi][nj][hf * 2 + 0] + bv[nj].x);
                    float x1 = rv.y * sv.y + (c[mi][nj][hf * 2 + 1] + bv[nj].y);
                    *(__half2*)(outH + ob + nj * 8) =
                        __halves2half2(__float2half_rn(x0), __float2half_rn(x1));
                }
            } else if (EPI == EPI_RELU) {
                size_t ob = (size_t)m * D_EMB + nbase + cph;
#pragma unroll
                for (int nj = 0; nj < 8; nj++) {
                    float x0 = fmaxf(c[mi][nj][hf * 2 + 0] + bv[nj].x, 0.f);
                    float x1 = fmaxf(c[mi][nj][hf * 2 + 1] + bv[nj].y, 0.f);
                    *(__half2*)(outH + ob + nj * 8) =
                        __halves2half2(__float2half_rn(x0), __float2half_rn(x1));
                }
            } else {
                const float* rp = rgn + ((size_t)(i_img * Q_RGN + q)) * D_EMB + nbase + cph;
                float* op = outF + (((size_t)(i_img * C_CAP + cc)) * Q_RGN + q) * D_EMB + nbase + cph;
#pragma unroll
                for (int nj = 0; nj < 8; nj++) {
                    float2 rv = *(const float2*)(rp + nj * 8);
                    float2 o;
                    o.x = c[mi][nj][hf * 2 + 0] + bv[nj].x + rv.x;
                    o.y = c[mi][nj][hf * 2 + 1] + bv[nj].y + rv.y;
                    *(float2*)(op + nj * 8) = o;
                }
            }
        }
    }
}

// ---------------------------------------------------------------------------
extern "C" void kernel_launch(void* const* d_in, const int* in_sizes, int n_in,
                              void* d_out, int out_size)
{
    const float* rgn     = (const float*)d_in[0];
    const float* wrd     = (const float*)d_in[2];
    const int*   lens    = (const int*)d_in[4];
    const float* w_scale = (const float*)d_in[5];
    const float* b_scale = (const float*)d_in[6];
    const float* w_shift = (const float*)d_in[7];
    const float* b_shift = (const float*)d_in[8];
    const float* w1      = (const float*)d_in[9];
    const float* b1      = (const float*)d_in[10];
    const float* w2      = (const float*)d_in[11];
    const float* b2      = (const float*)d_in[12];
    float* out = (float*)d_out;

    __half *weiH, *xH, *hH, *scalH, *wH, *rgnH, *rgnL, *wrdH, *wrdL, *wrdTH, *wrdTL, *attnH;
    float *S;
    cudaGetSymbolAddress((void**)&weiH,  g_weiH);
    cudaGetSymbolAddress((void**)&xH,    g_xH);
    cudaGetSymbolAddress((void**)&hH,    g_hH);
    cudaGetSymbolAddress((void**)&scalH, g_scalH);
    cudaGetSymbolAddress((void**)&wH,    g_wH);
    cudaGetSymbolAddress((void**)&rgnH,  g_rgnH);
    cudaGetSymbolAddress((void**)&rgnL,  g_rgnL);
    cudaGetSymbolAddress((void**)&wrdH,  g_wrdH);
    cudaGetSymbolAddress((void**)&wrdL,  g_wrdL);
    cudaGetSymbolAddress((void**)&wrdTH, g_wrdTH);
    cudaGetSymbolAddress((void**)&wrdTL, g_wrdTL);
    cudaGetSymbolAddress((void**)&attnH, g_attnH);
    cudaGetSymbolAddress((void**)&S,     g_S);

    cudaFuncSetAttribute(gemm_score, cudaFuncAttributeMaxDynamicSharedMemorySize, A1_SMEM);
    cudaFuncSetAttribute(gemm_wei,   cudaFuncAttributeMaxDynamicSharedMemorySize, A3_SMEM);
    cudaFuncSetAttribute(gemm_hmma<EPI_TANH>,  cudaFuncAttributeMaxDynamicSharedMemorySize, G_SMEM);
    cudaFuncSetAttribute(gemm_hmma<EPI_FILM>,  cudaFuncAttributeMaxDynamicSharedMemorySize, G_SMEM);
    cudaFuncSetAttribute(gemm_hmma<EPI_RELU>,  cudaFuncAttributeMaxDynamicSharedMemorySize, G_SMEM);
    cudaFuncSetAttribute(gemm_hmma<EPI_FINAL>, cudaFuncAttributeMaxDynamicSharedMemorySize, G_SMEM);

    // launch 0: weight converts + rgn split
    prep_kernel<<<dim3((MIQ * D_EMB / 4 + 255) / 256, 5), 256>>>(
        w_scale, w_shift, w1, w2, rgn, wH, rgnH, rgnL);
    // launch 1: wrd pad/split/transpose
    wrd_prep_kernel<<<dim3(D_EMB / 64, C_CAP), 256>>>(wrd, wrdH, wrdL, wrdTH, wrdTL);

    // launches 2-4: attention on tensor cores
    gemm_score<<<dim3(MIQ / 128, C_CAP), 256, A1_SMEM>>>(rgnH, rgnL, wrdH, wrdL, S);
    attn_norm_kernel<<<dim3(I_IMG, C_CAP), 128>>>(S, lens, attnH);
    gemm_wei<<<dim3(D_EMB / 128, MIQ / 128, C_CAP), 256, A3_SMEM>>>(
        attnH, wrdTH, wrdTL, weiH);

    // launches 5-8: main GEMM chain
    dim3 ggrid(D_EMB / 128, M_TOT / 128);
    gemm_hmma<EPI_TANH><<<ggrid, 256, G_SMEM>>>(
        weiH, wH + 0 * (size_t)W_ELEMS, b_scale, nullptr, nullptr, nullptr, scalH);
    gemm_hmma<EPI_FILM><<<ggrid, 256, G_SMEM>>>(
        weiH, wH + 1 * (size_t)W_ELEMS, b_shift, scalH, rgn, nullptr, xH);
    gemm_hmma<EPI_RELU><<<ggrid, 256, G_SMEM>>>(
        xH, wH + 2 * (size_t)W_ELEMS, b1, nullptr, nullptr, nullptr, hH);
    gemm_hmma<EPI_FINAL><<<ggrid, 256, G_SMEM>>>(
        hH, wH + 3 * (size_t)W_ELEMS, b2, nullptr, rgn, out, nullptr);
}

// round 14
// speedup vs baseline: 4.1678x; 1.0005x over previous
#include <cuda_runtime.h>
#include <cuda_fp16.h>
#include <math.h>
#include <stdint.h>

// Problem dims
#define I_IMG 32
#define C_CAP 32
#define Q_RGN 36
#define L_MAX 50
#define LPAD 64
#define D_EMB 1024
#define MIQ (I_IMG * Q_RGN)                    // 1152
#define M_TOT (C_CAP * MIQ)                    // 36864
#define ELEMS ((size_t)M_TOT * D_EMB)
#define W_ELEMS (D_EMB * D_EMB)

// ---------------- scratch ----------------
__device__ __align__(256) __half g_weiH[ELEMS];
__device__ __align__(256) __half g_xH[ELEMS];
__device__ __align__(256) __half g_hH[ELEMS];
__device__ __align__(256) __half g_scalH[ELEMS];
__device__ __align__(256) __half g_wH[4][W_ELEMS];
__device__ __align__(256) __half g_rgnH[MIQ * D_EMB];
__device__ __align__(256) __half g_rgnL[MIQ * D_EMB];
__device__ __align__(256) __half g_wrdH[C_CAP * LPAD * D_EMB];
__device__ __align__(256) __half g_wrdL[C_CAP * LPAD * D_EMB];
__device__ __align__(256) __half g_wrdTH[C_CAP * D_EMB * LPAD];
__device__ __align__(256) __half g_wrdTL[C_CAP * D_EMB * LPAD];
__device__ __align__(256) float  g_S[(size_t)C_CAP * MIQ * LPAD];
__device__ __align__(256) __half g_attnH[(size_t)C_CAP * MIQ * LPAD];

__device__ __forceinline__ void split_h(float x, __half& h, __half& l) {
    h = __float2half_rn(x);
    l = __float2half_rn(x - __half2float(h));
}

// ---------------- common HMMA infrastructure ----------------
__device__ __forceinline__ uint32_t smem_u32(const void* p) {
    uint32_t a;
    asm("{ .reg .u64 t; cvta.to.shared.u64 t, %1; cvt.u32.u64 %0, t; }"
        : "=r"(a) : "l"(p));
    return a;
}
// 64B-row tiles (attention kernels)
__device__ __forceinline__ uint32_t sm_addr(uint32_t base, int row, int c16) {
    return base + row * 64 + (((uint32_t)(c16 ^ ((row >> 1) & 3))) << 4);
}
// 128B-row tiles (chain GEMM, BK=64)
__device__ __forceinline__ uint32_t sm_addr128(uint32_t base, int row, int c16) {
    return base + row * 128 + (((uint32_t)(c16 ^ (row & 7))) << 4);
}
__device__ __forceinline__ void load_t128(
    const __half* __restrict__ g, int ld, int row0, int kcol0, uint32_t sb, int tid)
{
#pragma unroll
    for (int j = 0; j < 2; j++) {
        int id = tid + 256 * j;
        int r = id >> 2, c = id & 3;
        const void* gp = g + (size_t)(row0 + r) * ld + kcol0 + c * 8;
        asm volatile("cp.async.cg.shared.global [%0], [%1], 16;"
                     :: "r"(sm_addr(sb, r, c)), "l"(gp));
    }
}
__device__ __forceinline__ void load_t64(
    const __half* __restrict__ g, int ld, int row0, int kcol0, uint32_t sb, int tid)
{
    int r = tid >> 2, c = tid & 3;
    const void* gp = g + (size_t)(row0 + r) * ld + kcol0 + c * 8;
    asm volatile("cp.async.cg.shared.global [%0], [%1], 16;"
                 :: "r"(sm_addr(sb, r, c)), "l"(gp));
}
// 128 rows x 64 cols (128B/row)
__device__ __forceinline__ void load_t128w(
    const __half* __restrict__ g, int ld, int row0, int kcol0, uint32_t sb, int tid)
{
#pragma unroll
    for (int j = 0; j < 4; j++) {
        int id = tid + 256 * j;         // 0..1023
        int r = id >> 3, c = id & 7;
        const void* gp = g + (size_t)(row0 + r) * ld + kcol0 + c * 8;
        asm volatile("cp.async.cg.shared.global [%0], [%1], 16;"
                     :: "r"(sm_addr128(sb, r, c)), "l"(gp));
    }
}

#define LDSM_X4(R, addr) \
    asm volatile("ldmatrix.sync.aligned.m8n8.x4.shared.b16 {%0,%1,%2,%3}, [%4];" \
        : "=r"((R)[0]), "=r"((R)[1]), "=r"((R)[2]), "=r"((R)[3]) : "r"(addr))
#define MMA(C, A, B) \
    asm volatile("mma.sync.aligned.m16n8k16.row.col.f32.f16.f16.f32 " \
        "{%0,%1,%2,%3}, {%4,%5,%6,%7}, {%8,%9}, {%0,%1,%2,%3};" \
        : "+f"((C)[0]), "+f"((C)[1]), "+f"((C)[2]), "+f"((C)[3]) \
        : "r"((A)[0]), "r"((A)[1]), "r"((A)[2]), "r"((A)[3]), "r"((B)[0]), "r"((B)[1]))

// ---------------------------------------------------------------------------
// Prep: 4 weight converts + rgn hi/lo split (task = blockIdx.y)
// ---------------------------------------------------------------------------
__global__ __launch_bounds__(256) void prep_kernel(
    const float* __restrict__ w0, const float* __restrict__ w1,
    const float* __restrict__ w2, const float* __restrict__ w3,
    const float* __restrict__ rgn,
    __half* __restrict__ wH, __half* __restrict__ rgnH, __half* __restrict__ rgnL)
{
    const int task = blockIdx.y;
    const int i = blockIdx.x * 256 + threadIdx.x;
    if (task < 4) {
        if (i < W_ELEMS / 4) {
            const float* s = (task == 0) ? w0 : (task == 1) ? w1 : (task == 2) ? w2 : w3;
            float4 v = ((const float4*)s)[i];
            union { uint2 u; __half h[4]; } o;
            o.h[0] = __float2half_rn(v.x); o.h[1] = __float2half_rn(v.y);
            o.h[2] = __float2half_rn(v.z); o.h[3] = __float2half_rn(v.w);
            ((uint2*)(wH + (size_t)task * W_ELEMS))[i] = o.u;
        }
    } else {
        if (i < MIQ * D_EMB / 4) {
            float4 v = ((const float4*)rgn)[i];
            union { uint2 u; __half h[4]; } oh, ol;
            split_h(v.x, oh.h[0], ol.h[0]); split_h(v.y, oh.h[1], ol.h[1]);
            split_h(v.z, oh.h[2], ol.h[2]); split_h(v.w, oh.h[3], ol.h[3]);
            ((uint2*)rgnH)[i] = oh.u;
            ((uint2*)rgnL)[i] = ol.u;
        }
    }
}

// wrd: (C,50,1024) fp32 -> wrdH/L (C,64,1024) zero-padded + wrdTH/L (C,1024,64)
__global__ __launch_bounds__(256) void wrd_prep_kernel(
    const float* __restrict__ wrd,
    __half* __restrict__ wh, __half* __restrict__ wl,
    __half* __restrict__ wth, __half* __restrict__ wtl)
{
    const int d0 = blockIdx.x * 64;
    const int c = blockIdx.y;
    const int tid = threadIdx.x;
    __shared__ __align__(16) float ts[64][65];

    for (int idx = tid; idx < 64 * 64; idx += 256) {
        int l = idx >> 6, dd = idx & 63;
        float v = (l < L_MAX) ? wrd[((size_t)c * L_MAX + l) * D_EMB + d0 + dd] : 0.f;
        ts[l][dd] = v;
        __half h, lo; split_h(v, h, lo);
        wh[((size_t)c * LPAD + l) * D_EMB + d0 + dd] = h;
        wl[((size_t)c * LPAD + l) * D_EMB + d0 + dd] = lo;
    }
    __syncthreads();
    for (int idx = tid; idx < 64 * 64; idx += 256) {
        int d = idx >> 6, l = idx & 63;
        float v = ts[l][d];
        __half h, lo; split_h(v, h, lo);
        wth[((size_t)c * D_EMB + d0 + d) * LPAD + l] = h;
        wtl[((size_t)c * D_EMB + d0 + d) * LPAD + l] = lo;
    }
}

// ---------------------------------------------------------------------------
// A1: scores  S[c, m=(i,q), l] = leaky( rgn[m,:] . wrd[c,l,:] ), 3-term HMMA.
// 2 CTAs/SM (144 KB smem) -> single wave for the 288-CTA grid.
// ---------------------------------------------------------------------------
#define A1_STAGE (2 * 8192 + 2 * 4096)
#define A1_SMEM (3 * A1_STAGE)             // 72 KB

__global__ __launch_bounds__(256, 2) void gemm_score(
    const __half* __restrict__ Rh, const __half* __restrict__ Rl,
    const __half* __restrict__ Wh, const __half* __restrict__ Wl,
    float* __restrict__ S)
{
    extern __shared__ __align__(1024) uint8_t dsm[];
    const uint32_t sb = smem_u32(dsm);
    const int tid = threadIdx.x;
    const int wid = tid >> 5, lid = tid & 31;
    const int wm = wid & 3, wn = wid >> 2;
    const int m0 = blockIdx.x * 128;
    const int c  = blockIdx.y;

    const __half* Bh = Wh + (size_t)c * LPAD * D_EMB;
    const __half* Bl = Wl + (size_t)c * LPAD * D_EMB;

    const int a_ro = lid & 15, a_co = lid >> 4;
    const int b_ro = ((lid >> 4) & 1) * 8 + (lid & 7);
    const int b_co = (lid >> 3) & 1;

    float acc[2][4][4];
#pragma unroll
    for (int a = 0; a < 2; a++)
#pragma unroll
        for (int b = 0; b < 4; b++)
#pragma unroll
            for (int d = 0; d < 4; d++) acc[a][b][d] = 0.f;

#pragma unroll
    for (int s = 0; s < 2; s++) {
        uint32_t st = sb + s * A1_STAGE;
        load_t128(Rh, D_EMB, m0, s * 32, st, tid);
        load_t128(Rl, D_EMB, m0, s * 32, st + 8192, tid);
        load_t64(Bh, D_EMB, 0, s * 32, st + 16384, tid);
        load_t64(Bl, D_EMB, 0, s * 32, st + 20480, tid);
        asm volatile("cp.async.commit_group;");
    }

    int stage = 0;
    for (int i = 0; i < 32; i++) {
        asm volatile("cp.async.wait_group 1;");
        __syncthreads();
        if (i + 2 < 32) {
            uint32_t st = sb + ((stage + 2) % 3) * A1_STAGE;
            int kc = (i + 2) * 32;
            load_t128(Rh, D_EMB, m0, kc, st, tid);
            load_t128(Rl, D_EMB, m0, kc, st + 8192, tid);
            load_t64(Bh, D_EMB, 0, kc, st + 16384, tid);
            load_t64(Bl, D_EMB, 0, kc, st + 20480, tid);
        }
        asm volatile("cp.async.commit_group;");

        uint32_t stA = sb + stage * A1_STAGE;
#pragma unroll
        for (int ks = 0; ks < 2; ks++) {
            uint32_t aH[2][4], aL[2][4], bH[4][2], bL[4][2];
#pragma unroll
            for (int mi = 0; mi < 2; mi++) {
                LDSM_X4(aH[mi], sm_addr(stA, wm * 32 + mi * 16 + a_ro, ks * 2 + a_co));
                LDSM_X4(aL[mi], sm_addr(stA + 8192, wm * 32 + mi * 16 + a_ro, ks * 2 + a_co));
            }
#pragma unroll
            for (int p = 0; p < 2; p++) {
                uint32_t r[4];
                LDSM_X4(r, sm_addr(stA + 16384, wn * 32 + p * 16 + b_ro, ks * 2 + b_co));
                bH[2 * p][0] = r[0]; bH[2 * p][1] = r[1];
                bH[2 * p + 1][0] = r[2]; bH[2 * p + 1][1] = r[3];
                LDSM_X4(r, sm_addr(stA + 20480, wn * 32 + p * 16 + b_ro, ks * 2 + b_co));
                bL[2 * p][0] = r[0]; bL[2 * p][1] = r[1];
                bL[2 * p + 1][0] = r[2]; bL[2 * p + 1][1] = r[3];
            }
#pragma unroll
            for (int mi = 0; mi < 2; mi++)
#pragma unroll
                for (int nj = 0; nj < 4; nj++) {
                    MMA(acc[mi][nj], aH[mi], bH[nj]);
                    MMA(acc[mi][nj], aH[mi], bL[nj]);
                    MMA(acc[mi][nj], aL[mi], bH[nj]);
                }
        }
        stage = (stage + 1) % 3;
    }

    const int cph = (lid & 3) * 2;
#pragma unroll
    for (int mi = 0; mi < 2; mi++)
#pragma unroll
        for (int hf = 0; hf < 2; hf++) {
            int m = m0 + wm * 32 + mi * 16 + hf * 8 + (lid >> 2);
            float* op = S + ((size_t)c * MIQ + m) * LPAD + wn * 32 + cph;
#pragma unroll
            for (int nj = 0; nj < 4; nj++) {
                float v0 = acc[mi][nj][hf * 2 + 0];
                float v1 = acc[mi][nj][hf * 2 + 1];
                float2 o;
                o.x = (v0 >= 0.f) ? v0 : 0.1f * v0;
                o.y = (v1 >= 0.f) ? v1 : 0.1f * v1;
                *(float2*)(op + nj * 8) = o;
            }
        }
}

// ---------------------------------------------------------------------------
// A2: per (c,i): L2-normalize over q, masked softmax over l -> attn fp16.
// ---------------------------------------------------------------------------
__global__ __launch_bounds__(128) void attn_norm_kernel(
    const float* __restrict__ S, const int* __restrict__ lens,
    __half* __restrict__ attnH)
{
    const int i = blockIdx.x;
    const int c = blockIdx.y;
    const int tid = threadIdx.x;
    __shared__ __align__(16) float s[Q_RGN][68];
    __shared__ __align__(16) float sinv[LPAD];
    __shared__ __align__(16) __half ah[Q_RGN * LPAD];

    const size_t base = ((size_t)c * MIQ + i * Q_RGN) * LPAD;

    for (int idx = tid; idx < Q_RGN * 16; idx += 128) {
        int q = idx >> 4, f4 = idx & 15;
        float4 v = *(const float4*)(S + base + q * LPAD + f4 * 4);
        *(float4*)&s[q][f4 * 4] = v;
    }
    __syncthreads();

    // L2 norm over q per l: 2 threads per l (all 128 threads active)
    {
        const int l = tid >> 1, hf = tid & 1;
        float ss = 0.f;
        for (int q = hf * 18; q < hf * 18 + 18; q++) {
            float v = s[q][l]; ss += v * v;
        }
        ss += __shfl_xor_sync(0xffffffffu, ss, 1);
        if (hf == 0) sinv[l] = 1.f / fmaxf(sqrtf(ss), 1e-12f);
    }
    __syncthreads();

    const int len = lens[c];
    // softmax over l per q: 2 threads per q; shuffles unconditional.
    {
        const int q = tid >> 1, hf = tid & 1;
        const bool act = (q < Q_RGN);
        const int l0 = hf * 32;
        const int l1 = min(len, l0 + 32);
        float mx = -1e30f;
        if (act)
            for (int l = l0; l < l1; l++) mx = fmaxf(mx, s[q][l] * sinv[l]);
        mx = fmaxf(mx, __shfl_xor_sync(0xffffffffu, mx, 1));
        float sum = 0.f;
        if (act)
            for (int l = l0; l < l1; l++) {
                float e = expf(9.f * (s[q][l] * sinv[l] - mx));
                s[q][l] = e;
                sum += e;
            }
        sum += __shfl_xor_sync(0xffffffffu, sum, 1);
        if (act) {
            float inv = 1.f / sum;
            for (int l = l0; l < l0 + 32; l++)
                ah[q * LPAD + l] = __float2half_rn((l < l1) ? s[q][l] * inv : 0.f);
        }
    }
    __syncthreads();

    for (int u = tid; u < Q_RGN * LPAD / 8; u += 128)
        *(uint4*)(attnH + base + u * 8) = *(const uint4*)(ah + u * 8);
}

// ---------------------------------------------------------------------------
// A3: wei[c,m,d] = sum_l attn[c,m,l]*wrdT[c,d,l]; attn fp16, wrdT hi/lo.
// ---------------------------------------------------------------------------
#define A3_STAGE (3 * 8192)
#define A3_SMEM (2 * A3_STAGE)             // 48 KB

__global__ __launch_bounds__(256, 2) void gemm_wei(
    const __half* __restrict__ AH,
    const __half* __restrict__ WTH, const __half* __restrict__ WTL,
    __half* __restrict__ weiH)
{
    extern __shared__ __align__(1024) uint8_t dsm[];
    const uint32_t sb = smem_u32(dsm);
    const int tid = threadIdx.x;
    const int wid = tid >> 5, lid = tid & 31;
    const int wm = wid & 3, wn = wid >> 2;
    const int n0 = blockIdx.x * 128;
    const int m0 = blockIdx.y * 128;
    const int c  = blockIdx.z;

    const __half* Ah = AH + (size_t)c * MIQ * LPAD;
    const __half* Bh = WTH + (size_t)c * D_EMB * LPAD;
    const __half* Bl = WTL + (size_t)c * D_EMB * LPAD;

    const int a_ro = lid & 15, a_co = lid >> 4;
    const int b_ro = ((lid >> 4) & 1) * 8 + (lid & 7);
    const int b_co = (lid >> 3) & 1;

    float acc[2][8][4];
#pragma unroll
    for (int a = 0; a < 2; a++)
#pragma unroll
        for (int b = 0; b < 8; b++)
#pragma unroll
            for (int d = 0; d < 4; d++) acc[a][b][d] = 0.f;

#pragma unroll
    for (int s = 0; s < 2; s++) {
        uint32_t st = sb + s * A3_STAGE;
        load_t128(Ah, LPAD, m0, s * 32, st, tid);
        load_t128(Bh, LPAD, n0, s * 32, st + 8192, tid);
        load_t128(Bl, LPAD, n0, s * 32, st + 16384, tid);
        asm volatile("cp.async.commit_group;");
    }

#pragma unroll
    for (int i = 0; i < 2; i++) {
        if (i == 0) asm volatile("cp.async.wait_group 1;");
        else        asm volatile("cp.async.wait_group 0;");
        __syncthreads();
        uint32_t stA = sb + i * A3_STAGE;
#pragma unroll
        for (int ks = 0; ks < 2; ks++) {
            uint32_t aH[2][4], bH[8][2], bL[8][2];
#pragma unroll
            for (int mi = 0; mi < 2; mi++)
                LDSM_X4(aH[mi], sm_addr(stA, wm * 32 + mi * 16 + a_ro, ks * 2 + a_co));
#pragma unroll
            for (int p = 0; p < 4; p++) {
                uint32_t r[4];
                LDSM_X4(r, sm_addr(stA + 8192, wn * 64 + p * 16 + b_ro, ks * 2 + b_co));
                bH[2 * p][0] = r[0]; bH[2 * p][1] = r[1];
                bH[2 * p + 1][0] = r[2]; bH[2 * p + 1][1] = r[3];
                LDSM_X4(r, sm_addr(stA + 16384, wn * 64 + p * 16 + b_ro, ks * 2 + b_co));
                bL[2 * p][0] = r[0]; bL[2 * p][1] = r[1];
                bL[2 * p + 1][0] = r[2]; bL[2 * p + 1][1] = r[3];
            }
#pragma unroll
            for (int mi = 0; mi < 2; mi++)
#pragma unroll
                for (int nj = 0; nj < 8; nj++) {
                    MMA(acc[mi][nj], aH[mi], bH[nj]);
                    MMA(acc[mi][nj], aH[mi], bL[nj]);
                }
        }
    }

    const int cph = (lid & 3) * 2;
    const int nbase = n0 + wn * 64;
#pragma unroll
    for (int mi = 0; mi < 2; mi++)
#pragma unroll
        for (int hf = 0; hf < 2; hf++) {
            int m = m0 + wm * 32 + mi * 16 + hf * 8 + (lid >> 2);
            __half* op = weiH + ((size_t)c * MIQ + m) * D_EMB + nbase + cph;
#pragma unroll
            for (int nj = 0; nj < 8; nj++)
                *(__half2*)(op + nj * 8) = __halves2half2(
                    __float2half_rn(acc[mi][nj][hf * 2 + 0]),
                    __float2half_rn(acc[mi][nj][hf * 2 + 1]));
        }
}

// ---------------------------------------------------------------------------
// Main HMMA GEMM (plain fp16, BK=64, 128B-row swizzle, 2 CTAs/SM)
// ---------------------------------------------------------------------------
#define EPI_TANH 0
#define EPI_FILM 1
#define EPI_RELU 2
#define EPI_FINAL 3

#define G_TILE 16384                       // 128 rows x 128 B
#define G_STAGE (2 * G_TILE)               // A, B = 32 KB
#define G_SMEM (3 * G_STAGE)               // 96 KB; 2 CTAs = 192 KB

template <int EPI>
__global__ __launch_bounds__(256, 2) void gemm_hmma(
    const __half* __restrict__ Ah, const __half* __restrict__ Bh,
    const float* __restrict__ bias,
    const __half* __restrict__ scal,
    const float* __restrict__ rgn,
    float* __restrict__ outF,
    __half* __restrict__ outH)
{
    extern __shared__ __align__(1024) uint8_t dsm[];
    const uint32_t sb = smem_u32(dsm);
    const int tid = threadIdx.x;
    const int wid = tid >> 5, lid = tid & 31;
    const int wm = wid & 3, wn = wid >> 2;
    const int m0 = blockIdx.y * 128;
    const int n0 = blockIdx.x * 128;

    const int a_ro = lid & 15, a_co = lid >> 4;
    const int b_ro = ((lid >> 4) & 1) * 8 + (lid & 7);
    const int b_co = (lid >> 3) & 1;

    float c[2][8][4];
#pragma unroll
    for (int a = 0; a < 2; a++)
#pragma unroll
        for (int b = 0; b < 8; b++)
#pragma unroll
            for (int d = 0; d < 4; d++) c[a][b][d] = 0.f;

#pragma unroll
    for (int s = 0; s < 2; s++) {
        uint32_t st = sb + s * G_STAGE;
        load_t128w(Ah, D_EMB, m0, s * 64, st, tid);
        load_t128w(Bh, D_EMB, n0, s * 64, st + G_TILE, tid);
        asm volatile("cp.async.commit_group;");
    }

    int stage = 0;
    for (int i = 0; i < 16; i++) {
        asm volatile("cp.async.wait_group 1;");
        __syncthreads();
        if (i + 2 < 16) {
            uint32_t st = sb + ((stage + 2) % 3) * G_STAGE;
            int kc = (i + 2) * 64;
            load_t128w(Ah, D_EMB, m0, kc, st, tid);
            load_t128w(Bh, D_EMB, n0, kc, st + G_TILE, tid);
        }
        asm volatile("cp.async.commit_group;");

        uint32_t stA = sb + stage * G_STAGE;
#pragma unroll
        for (int ks = 0; ks < 4; ks++) {
            uint32_t aH[2][4], bH[8][2];
#pragma unroll
            for (int mi = 0; mi < 2; mi++)
                LDSM_X4(aH[mi], sm_addr128(stA, wm * 32 + mi * 16 + a_ro, ks * 2 + a_co));
#pragma unroll
            for (int p = 0; p < 4; p++) {
                uint32_t r[4];
                LDSM_X4(r, sm_addr128(stA + G_TILE, wn * 64 + p * 16 + b_ro, ks * 2 + b_co));
                bH[2 * p][0] = r[0]; bH[2 * p][1] = r[1];
                bH[2 * p + 1][0] = r[2]; bH[2 * p + 1][1] = r[3];
            }
#pragma unroll
            for (int mi = 0; mi < 2; mi++)
#pragma unroll
                for (int nj = 0; nj < 8; nj++)
                    MMA(c[mi][nj], aH[mi], bH[nj]);
        }
        stage = (stage + 1) % 3;
    }

    const int nbase = n0 + wn * 64;
    const int mbase = m0 + wm * 32;
    const int cph = (lid & 3) * 2;

    float2 bv[8];
#pragma unroll
    for (int nj = 0; nj < 8; nj++)
        bv[nj] = *(const float2*)(bias + nbase + nj * 8 + cph);

#pragma unroll
    for (int mi = 0; mi < 2; mi++) {
#pragma unroll
        for (int hf = 0; hf < 2; hf++) {
            const int m = mbase + mi * 16 + hf * 8 + (lid >> 2);
            const int t = m / Q_RGN;
            const int q = m - t * Q_RGN;
            const int i_img = t & (I_IMG - 1);
            const int cc = t >> 5;

            if (EPI == EPI_TANH) {
                size_t ob = (size_t)m * D_EMB + nbase + cph;
#pragma unroll
                for (int nj = 0; nj < 8; nj++) {
                    float x0 = tanhf(c[mi][nj][hf * 2 + 0] + bv[nj].x);
                    float x1 = tanhf(c[mi][nj][hf * 2 + 1] + bv[nj].y);
                    *(__half2*)(outH + ob + nj * 8) =
                        __halves2half2(__float2half_rn(x0), __float2half_rn(x1));
                }
            } else if (EPI == EPI_FILM) {
                const float* rp = rgn + ((size_t)(i_img * Q_RGN + q)) * D_EMB + nbase + cph;
                const __half* sp = scal + (size_t)m * D_EMB + nbase + cph;
                size_t ob = (size_t)m * D_EMB + nbase + cph;
#pragma unroll
                for (int nj = 0; nj < 8; nj++) {
                    float2 rv = *(const float2*)(rp + nj * 8);
                    float2 sv = __half22float2(*(const __half2*)(sp + nj * 8));
                    float x0 = rv.x * sv.x + (c[mi][nj][hf * 2 + 0] + bv[nj].x);
                    float x1 = rv.y * sv.y + (c[mi][nj][hf * 2 + 1] + bv[nj].y);
                    *(__half2*)(outH + ob + nj * 8) =
                        __halves2half2(__float2half_rn(x0), __float2half_rn(x1));
                }
            } else if (EPI == EPI_RELU) {
                size_t ob = (size_t)m * D_EMB + nbase + cph;
#pragma unroll
                for (int nj = 0; nj < 8; nj++) {
                    float x0 = fmaxf(c[mi][nj][hf * 2 + 0] + bv[nj].x, 0.f);
                    float x1 = fmaxf(c[mi][nj][hf * 2 + 1] + bv[nj].y, 0.f);
                    *(__half2*)(outH + ob + nj * 8) =
                        __halves2half2(__float2half_rn(x0), __float2half_rn(x1));
                }
            } else {
                const float* rp = rgn + ((size_t)(i_img * Q_RGN + q)) * D_EMB + nbase + cph;
                float* op = outF + (((size_t)(i_img * C_CAP + cc)) * Q_RGN + q) * D_EMB + nbase + cph;
#pragma unroll
                for (int nj = 0; nj < 8; nj++) {
                    float2 rv = *(const float2*)(rp + nj * 8);
                    float2 o;
                    o.x = c[mi][nj][hf * 2 + 0] + bv[nj].x + rv.x;
                    o.y = c[mi][nj][hf * 2 + 1] + bv[nj].y + rv.y;
                    *(float2*)(op + nj * 8) = o;
                }
            }
        }
    }
}

// ---------------------------------------------------------------------------
extern "C" void kernel_launch(void* const* d_in, const int* in_sizes, int n_in,
                              void* d_out, int out_size)
{
    const float* rgn     = (const float*)d_in[0];
    const float* wrd     = (const float*)d_in[2];
    const int*   lens    = (const int*)d_in[4];
    const float* w_scale = (const float*)d_in[5];
    const float* b_scale = (const float*)d_in[6];
    const float* w_shift = (const float*)d_in[7];
    const float* b_shift = (const float*)d_in[8];
    const float* w1      = (const float*)d_in[9];
    const float* b1      = (const float*)d_in[10];
    const float* w2      = (const float*)d_in[11];
    const float* b2      = (const float*)d_in[12];
    float* out = (float*)d_out;

    __half *weiH, *xH, *hH, *scalH, *wH, *rgnH, *rgnL, *wrdH, *wrdL, *wrdTH, *wrdTL, *attnH;
    float *S;
    cudaGetSymbolAddress((void**)&weiH,  g_weiH);
    cudaGetSymbolAddress((void**)&xH,    g_xH);
    cudaGetSymbolAddress((void**)&hH,    g_hH);
    cudaGetSymbolAddress((void**)&scalH, g_scalH);
    cudaGetSymbolAddress((void**)&wH,    g_wH);
    cudaGetSymbolAddress((void**)&rgnH,  g_rgnH);
    cudaGetSymbolAddress((void**)&rgnL,  g_rgnL);
    cudaGetSymbolAddress((void**)&wrdH,  g_wrdH);
    cudaGetSymbolAddress((void**)&wrdL,  g_wrdL);
    cudaGetSymbolAddress((void**)&wrdTH, g_wrdTH);
    cudaGetSymbolAddress((void**)&wrdTL, g_wrdTL);
    cudaGetSymbolAddress((void**)&attnH, g_attnH);
    cudaGetSymbolAddress((void**)&S,     g_S);

    cudaFuncSetAttribute(gemm_score, cudaFuncAttributeMaxDynamicSharedMemorySize, A1_SMEM);
    cudaFuncSetAttribute(gemm_wei,   cudaFuncAttributeMaxDynamicSharedMemorySize, A3_SMEM);
    cudaFuncSetAttribute(gemm_hmma<EPI_TANH>,  cudaFuncAttributeMaxDynamicSharedMemorySize, G_SMEM);
    cudaFuncSetAttribute(gemm_hmma<EPI_FILM>,  cudaFuncAttributeMaxDynamicSharedMemorySize, G_SMEM);
    cudaFuncSetAttribute(gemm_hmma<EPI_RELU>,  cudaFuncAttributeMaxDynamicSharedMemorySize, G_SMEM);
    cudaFuncSetAttribute(gemm_hmma<EPI_FINAL>, cudaFuncAttributeMaxDynamicSharedMemorySize, G_SMEM);

    // launch 0: weight converts + rgn split
    prep_kernel<<<dim3((MIQ * D_EMB / 4 + 255) / 256, 5), 256>>>(
        w_scale, w_shift, w1, w2, rgn, wH, rgnH, rgnL);
    // launch 1: wrd pad/split/transpose
    wrd_prep_kernel<<<dim3(D_EMB / 64, C_CAP), 256>>>(wrd, wrdH, wrdL, wrdTH, wrdTL);

    // launches 2-4: attention on tensor cores
    gemm_score<<<dim3(MIQ / 128, C_CAP), 256, A1_SMEM>>>(rgnH, rgnL, wrdH, wrdL, S);
    attn_norm_kernel<<<dim3(I_IMG, C_CAP), 128>>>(S, lens, attnH);
    gemm_wei<<<dim3(D_EMB / 128, MIQ / 128, C_CAP), 256, A3_SMEM>>>(
        attnH, wrdTH, wrdTL, weiH);

    // launches 5-8: main GEMM chain
    dim3 ggrid(D_EMB / 128, M_TOT / 128);
    gemm_hmma<EPI_TANH><<<ggrid, 256, G_SMEM>>>(
        weiH, wH + 0 * (size_t)W_ELEMS, b_scale, nullptr, nullptr, nullptr, scalH);
    gemm_hmma<EPI_FILM><<<ggrid, 256, G_SMEM>>>(
        weiH, wH + 1 * (size_t)W_ELEMS, b_shift, scalH, rgn, nullptr, xH);
    gemm_hmma<EPI_RELU><<<ggrid, 256, G_SMEM>>>(
        xH, wH + 2 * (size_t)W_ELEMS, b1, nullptr, nullptr, nullptr, hH);
    gemm_hmma<EPI_FINAL><<<ggrid, 256, G_SMEM>>>(
        hH, wH + 3 * (size_t)W_ELEMS, b2, nullptr, rgn, out, nullptr);
}

// round 15
// speedup vs baseline: 4.2538x; 1.0206x over previous
#include <cuda_runtime.h>
#include <cuda_fp16.h>
#include <math.h>
#include <stdint.h>

// Problem dims
#define I_IMG 32
#define C_CAP 32
#define Q_RGN 36
#define L_MAX 50
#define LPAD 64
#define D_EMB 1024
#define MIQ (I_IMG * Q_RGN)                    // 1152
#define M_TOT (C_CAP * MIQ)                    // 36864
#define ELEMS ((size_t)M_TOT * D_EMB)
#define W_ELEMS (D_EMB * D_EMB)

// ---------------- scratch ----------------
__device__ __align__(256) __half g_weiH[ELEMS];
__device__ __align__(256) __half g_xH[ELEMS];
__device__ __align__(256) __half g_hH[ELEMS];
__device__ __align__(256) __half g_scalH[ELEMS];
__device__ __align__(256) __half g_wH[4][W_ELEMS];
__device__ __align__(256) __half g_rgnH[MIQ * D_EMB];
__device__ __align__(256) __half g_rgnL[MIQ * D_EMB];
__device__ __align__(256) __half g_wrdH[C_CAP * LPAD * D_EMB];
__device__ __align__(256) __half g_wrdL[C_CAP * LPAD * D_EMB];
__device__ __align__(256) __half g_wrdTH[C_CAP * D_EMB * LPAD];
__device__ __align__(256) float  g_S[(size_t)C_CAP * MIQ * LPAD];
__device__ __align__(256) __half g_attnH[(size_t)C_CAP * MIQ * LPAD];

__device__ __forceinline__ void split_h(float x, __half& h, __half& l) {
    h = __float2half_rn(x);
    l = __float2half_rn(x - __half2float(h));
}
__device__ __forceinline__ float tanh_hw(float x) {
    float y;
    asm("tanh.approx.f32 %0, %1;" : "=f"(y) : "f"(x));
    return y;
}

// ---------------- common HMMA infrastructure ----------------
__device__ __forceinline__ uint32_t smem_u32(const void* p) {
    uint32_t a;
    asm("{ .reg .u64 t; cvta.to.shared.u64 t, %1; cvt.u32.u64 %0, t; }"
        : "=r"(a) : "l"(p));
    return a;
}
// 64B-row tiles
__device__ __forceinline__ uint32_t sm_addr(uint32_t base, int row, int c16) {
    return base + row * 64 + (((uint32_t)(c16 ^ ((row >> 1) & 3))) << 4);
}
// 128B-row tiles (chain GEMM, BK=64)
__device__ __forceinline__ uint32_t sm_addr128(uint32_t base, int row, int c16) {
    return base + row * 128 + (((uint32_t)(c16 ^ (row & 7))) << 4);
}
__device__ __forceinline__ void load_t128(
    const __half* __restrict__ g, int ld, int row0, int kcol0, uint32_t sb, int tid)
{
#pragma unroll
    for (int j = 0; j < 2; j++) {
        int id = tid + 256 * j;
        int r = id >> 2, c = id & 3;
        const void* gp = g + (size_t)(row0 + r) * ld + kcol0 + c * 8;
        asm volatile("cp.async.cg.shared.global [%0], [%1], 16;"
                     :: "r"(sm_addr(sb, r, c)), "l"(gp));
    }
}
__device__ __forceinline__ void load_t64(
    const __half* __restrict__ g, int ld, int row0, int kcol0, uint32_t sb, int tid)
{
    int r = tid >> 2, c = tid & 3;
    const void* gp = g + (size_t)(row0 + r) * ld + kcol0 + c * 8;
    asm volatile("cp.async.cg.shared.global [%0], [%1], 16;"
                 :: "r"(sm_addr(sb, r, c)), "l"(gp));
}
__device__ __forceinline__ void load_t128w(
    const __half* __restrict__ g, int ld, int row0, int kcol0, uint32_t sb, int tid)
{
#pragma unroll
    for (int j = 0; j < 4; j++) {
        int id = tid + 256 * j;
        int r = id >> 3, c = id & 7;
        const void* gp = g + (size_t)(row0 + r) * ld + kcol0 + c * 8;
        asm volatile("cp.async.cg.shared.global [%0], [%1], 16;"
                     :: "r"(sm_addr128(sb, r, c)), "l"(gp));
    }
}

#define LDSM_X4(R, addr) \
    asm volatile("ldmatrix.sync.aligned.m8n8.x4.shared.b16 {%0,%1,%2,%3}, [%4];" \
        : "=r"((R)[0]), "=r"((R)[1]), "=r"((R)[2]), "=r"((R)[3]) : "r"(addr))
#define MMA(C, A, B) \
    asm volatile("mma.sync.aligned.m16n8k16.row.col.f32.f16.f16.f32 " \
        "{%0,%1,%2,%3}, {%4,%5,%6,%7}, {%8,%9}, {%0,%1,%2,%3};" \
        : "+f"((C)[0]), "+f"((C)[1]), "+f"((C)[2]), "+f"((C)[3]) \
        : "r"((A)[0]), "r"((A)[1]), "r"((A)[2]), "r"((A)[3]), "r"((B)[0]), "r"((B)[1]))

// ---------------------------------------------------------------------------
// prep_all: task 0-3 weight cvt, task 4 rgn split, task 5 wrd pad/split/transp
// grid = dim3(1152, 6)
// ---------------------------------------------------------------------------
__global__ __launch_bounds__(256) void prep_all_kernel(
    const float* __restrict__ w0, const float* __restrict__ w1,
    const float* __restrict__ w2, const float* __restrict__ w3,
    const float* __restrict__ rgn, const float* __restrict__ wrd,
    __half* __restrict__ wH, __half* __restrict__ rgnH, __half* __restrict__ rgnL,
    __half* __restrict__ wh, __half* __restrict__ wl, __half* __restrict__ wth)
{
    const int task = blockIdx.y;
    const int bx = blockIdx.x;
    const int tid = threadIdx.x;
    __shared__ __align__(16) float ts[64][65];

    if (task < 4) {
        int i = bx * 256 + tid;
        if (i < W_ELEMS / 4) {
            const float* s = (task == 0) ? w0 : (task == 1) ? w1 : (task == 2) ? w2 : w3;
            float4 v = ((const float4*)s)[i];
            union { uint2 u; __half h[4]; } o;
            o.h[0] = __float2half_rn(v.x); o.h[1] = __float2half_rn(v.y);
            o.h[2] = __float2half_rn(v.z); o.h[3] = __float2half_rn(v.w);
            ((uint2*)(wH + (size_t)task * W_ELEMS))[i] = o.u;
        }
    } else if (task == 4) {
        int i = bx * 256 + tid;
        if (i < MIQ * D_EMB / 4) {
            float4 v = ((const float4*)rgn)[i];
            union { uint2 u; __half h[4]; } oh, ol;
            split_h(v.x, oh.h[0], ol.h[0]); split_h(v.y, oh.h[1], ol.h[1]);
            split_h(v.z, oh.h[2], ol.h[2]); split_h(v.w, oh.h[3], ol.h[3]);
            ((uint2*)rgnH)[i] = oh.u;
            ((uint2*)rgnL)[i] = ol.u;
        }
    } else {
        if (bx >= (D_EMB / 64) * C_CAP) return;   // 512 active blocks
        const int d0 = (bx & 15) * 64;            // 16 d-tiles
        const int c  = bx >> 4;

        for (int idx = tid; idx < 64 * 64; idx += 256) {
            int l = idx >> 6, dd = idx & 63;
            float v = (l < L_MAX) ? wrd[((size_t)c * L_MAX + l) * D_EMB + d0 + dd] : 0.f;
            ts[l][dd] = v;
            __half h, lo; split_h(v, h, lo);
            wh[((size_t)c * LPAD + l) * D_EMB + d0 + dd] = h;
            wl[((size_t)c * LPAD + l) * D_EMB + d0 + dd] = lo;
        }
        __syncthreads();
        for (int idx = tid; idx < 64 * 64; idx += 256) {
            int d = idx >> 6, l = idx & 63;
            wth[((size_t)c * D_EMB + d0 + d) * LPAD + l] = __float2half_rn(ts[l][d]);
        }
    }
}

// ---------------------------------------------------------------------------
// A1: scores  S[c, m=(i,q), l] = leaky( rgn[m,:] . wrd[c,l,:] ), 3-term HMMA.
// ---------------------------------------------------------------------------
#define A1_STAGE (2 * 8192 + 2 * 4096)
#define A1_SMEM (3 * A1_STAGE)             // 72 KB

__global__ __launch_bounds__(256, 2) void gemm_score(
    const __half* __restrict__ Rh, const __half* __restrict__ Rl,
    const __half* __restrict__ Wh, const __half* __restrict__ Wl,
    float* __restrict__ S)
{
    extern __shared__ __align__(1024) uint8_t dsm[];
    const uint32_t sb = smem_u32(dsm);
    const int tid = threadIdx.x;
    const int wid = tid >> 5, lid = tid & 31;
    const int wm = wid & 3, wn = wid >> 2;
    const int m0 = blockIdx.x * 128;
    const int c  = blockIdx.y;

    const __half* Bh = Wh + (size_t)c * LPAD * D_EMB;
    const __half* Bl = Wl + (size_t)c * LPAD * D_EMB;

    const int a_ro = lid & 15, a_co = lid >> 4;
    const int b_ro = ((lid >> 4) & 1) * 8 + (lid & 7);
    const int b_co = (lid >> 3) & 1;

    float acc[2][4][4];
#pragma unroll
    for (int a = 0; a < 2; a++)
#pragma unroll
        for (int b = 0; b < 4; b++)
#pragma unroll
            for (int d = 0; d < 4; d++) acc[a][b][d] = 0.f;

#pragma unroll
    for (int s = 0; s < 2; s++) {
        uint32_t st = sb + s * A1_STAGE;
        load_t128(Rh, D_EMB, m0, s * 32, st, tid);
        load_t128(Rl, D_EMB, m0, s * 32, st + 8192, tid);
        load_t64(Bh, D_EMB, 0, s * 32, st + 16384, tid);
        load_t64(Bl, D_EMB, 0, s * 32, st + 20480, tid);
        asm volatile("cp.async.commit_group;");
    }

    int stage = 0;
    for (int i = 0; i < 32; i++) {
        asm volatile("cp.async.wait_group 1;");
        __syncthreads();
        if (i + 2 < 32) {
            uint32_t st = sb + ((stage + 2) % 3) * A1_STAGE;
            int kc = (i + 2) * 32;
            load_t128(Rh, D_EMB, m0, kc, st, tid);
            load_t128(Rl, D_EMB, m0, kc, st + 8192, tid);
            load_t64(Bh, D_EMB, 0, kc, st + 16384, tid);
            load_t64(Bl, D_EMB, 0, kc, st + 20480, tid);
        }
        asm volatile("cp.async.commit_group;");

        uint32_t stA = sb + stage * A1_STAGE;
#pragma unroll
        for (int ks = 0; ks < 2; ks++) {
            uint32_t aH[2][4], aL[2][4], bH[4][2], bL[4][2];
#pragma unroll
            for (int mi = 0; mi < 2; mi++) {
                LDSM_X4(aH[mi], sm_addr(stA, wm * 32 + mi * 16 + a_ro, ks * 2 + a_co));
                LDSM_X4(aL[mi], sm_addr(stA + 8192, wm * 32 + mi * 16 + a_ro, ks * 2 + a_co));
            }
#pragma unroll
            for (int p = 0; p < 2; p++) {
                uint32_t r[4];
                LDSM_X4(r, sm_addr(stA + 16384, wn * 32 + p * 16 + b_ro, ks * 2 + b_co));
                bH[2 * p][0] = r[0]; bH[2 * p][1] = r[1];
                bH[2 * p + 1][0] = r[2]; bH[2 * p + 1][1] = r[3];
                LDSM_X4(r, sm_addr(stA + 20480, wn * 32 + p * 16 + b_ro, ks * 2 + b_co));
                bL[2 * p][0] = r[0]; bL[2 * p][1] = r[1];
                bL[2 * p + 1][0] = r[2]; bL[2 * p + 1][1] = r[3];
            }
#pragma unroll
            for (int mi = 0; mi < 2; mi++)
#pragma unroll
                for (int nj = 0; nj < 4; nj++) {
                    MMA(acc[mi][nj], aH[mi], bH[nj]);
                    MMA(acc[mi][nj], aH[mi], bL[nj]);
                    MMA(acc[mi][nj], aL[mi], bH[nj]);
                }
        }
        stage = (stage + 1) % 3;
    }

    const int cph = (lid & 3) * 2;
#pragma unroll
    for (int mi = 0; mi < 2; mi++)
#pragma unroll
        for (int hf = 0; hf < 2; hf++) {
            int m = m0 + wm * 32 + mi * 16 + hf * 8 + (lid >> 2);
            float* op = S + ((size_t)c * MIQ + m) * LPAD + wn * 32 + cph;
#pragma unroll
            for (int nj = 0; nj < 4; nj++) {
                float v0 = acc[mi][nj][hf * 2 + 0];
                float v1 = acc[mi][nj][hf * 2 + 1];
                float2 o;
                o.x = (v0 >= 0.f) ? v0 : 0.1f * v0;
                o.y = (v1 >= 0.f) ? v1 : 0.1f * v1;
                *(float2*)(op + nj * 8) = o;
            }
        }
}

// ---------------------------------------------------------------------------
// A2: per (c,i): L2-normalize over q, masked softmax over l -> attn fp16.
// ---------------------------------------------------------------------------
__global__ __launch_bounds__(128) void attn_norm_kernel(
    const float* __restrict__ S, const int* __restrict__ lens,
    __half* __restrict__ attnH)
{
    const int i = blockIdx.x;
    const int c = blockIdx.y;
    const int tid = threadIdx.x;
    __shared__ __align__(16) float s[Q_RGN][68];
    __shared__ __align__(16) float sinv[LPAD];
    __shared__ __align__(16) __half ah[Q_RGN * LPAD];

    const size_t base = ((size_t)c * MIQ + i * Q_RGN) * LPAD;

    for (int idx = tid; idx < Q_RGN * 16; idx += 128) {
        int q = idx >> 4, f4 = idx & 15;
        float4 v = *(const float4*)(S + base + q * LPAD + f4 * 4);
        *(float4*)&s[q][f4 * 4] = v;
    }
    __syncthreads();

    {
        const int l = tid >> 1, hf = tid & 1;
        float ss = 0.f;
        for (int q = hf * 18; q < hf * 18 + 18; q++) {
            float v = s[q][l]; ss += v * v;
        }
        ss += __shfl_xor_sync(0xffffffffu, ss, 1);
        if (hf == 0) sinv[l] = 1.f / fmaxf(sqrtf(ss), 1e-12f);
    }
    __syncthreads();

    const int len = lens[c];
    {
        const int q = tid >> 1, hf = tid & 1;
        const bool act = (q < Q_RGN);
        const int l0 = hf * 32;
        const int l1 = min(len, l0 + 32);
        float mx = -1e30f;
        if (act)
            for (int l = l0; l < l1; l++) mx = fmaxf(mx, s[q][l] * sinv[l]);
        mx = fmaxf(mx, __shfl_xor_sync(0xffffffffu, mx, 1));
        float sum = 0.f;
        if (act)
            for (int l = l0; l < l1; l++) {
                float e = expf(9.f * (s[q][l] * sinv[l] - mx));
                s[q][l] = e;
                sum += e;
            }
        sum += __shfl_xor_sync(0xffffffffu, sum, 1);
        if (act) {
            float inv = 1.f / sum;
            for (int l = l0; l < l0 + 32; l++)
                ah[q * LPAD + l] = __float2half_rn((l < l1) ? s[q][l] * inv : 0.f);
        }
    }
    __syncthreads();

    for (int u = tid; u < Q_RGN * LPAD / 8; u += 128)
        *(uint4*)(attnH + base + u * 8) = *(const uint4*)(ah + u * 8);
}

// ---------------------------------------------------------------------------
// A3: wei[c,m,d] = sum_l attn[c,m,l]*wrdT[c,d,l]; 1-term fp16.
// ---------------------------------------------------------------------------
#define A3_STAGE (2 * 8192)                // A, B
#define A3_SMEM (2 * A3_STAGE)             // 32 KB

__global__ __launch_bounds__(256, 2) void gemm_wei(
    const __half* __restrict__ AH, const __half* __restrict__ WTH,
    __half* __restrict__ weiH)
{
    extern __shared__ __align__(1024) uint8_t dsm[];
    const uint32_t sb = smem_u32(dsm);
    const int tid = threadIdx.x;
    const int wid = tid >> 5, lid = tid & 31;
    const int wm = wid & 3, wn = wid >> 2;
    const int n0 = blockIdx.x * 128;
    const int m0 = blockIdx.y * 128;
    const int c  = blockIdx.z;

    const __half* Ah = AH + (size_t)c * MIQ * LPAD;
    const __half* Bh = WTH + (size_t)c * D_EMB * LPAD;

    const int a_ro = lid & 15, a_co = lid >> 4;
    const int b_ro = ((lid >> 4) & 1) * 8 + (lid & 7);
    const int b_co = (lid >> 3) & 1;

    float acc[2][8][4];
#pragma unroll
    for (int a = 0; a < 2; a++)
#pragma unroll
        for (int b = 0; b < 8; b++)
#pragma unroll
            for (int d = 0; d < 4; d++) acc[a][b][d] = 0.f;

#pragma unroll
    for (int s = 0; s < 2; s++) {
        uint32_t st = sb + s * A3_STAGE;
        load_t128(Ah, LPAD, m0, s * 32, st, tid);
        load_t128(Bh, LPAD, n0, s * 32, st + 8192, tid);
        asm volatile("cp.async.commit_group;");
    }

#pragma unroll
    for (int i = 0; i < 2; i++) {
        if (i == 0) asm volatile("cp.async.wait_group 1;");
        else        asm volatile("cp.async.wait_group 0;");
        __syncthreads();
        uint32_t stA = sb + i * A3_STAGE;
#pragma unroll
        for (int ks = 0; ks < 2; ks++) {
            uint32_t aH[2][4], bH[8][2];
#pragma unroll
            for (int mi = 0; mi < 2; mi++)
                LDSM_X4(aH[mi], sm_addr(stA, wm * 32 + mi * 16 + a_ro, ks * 2 + a_co));
#pragma unroll
            for (int p = 0; p < 4; p++) {
                uint32_t r[4];
                LDSM_X4(r, sm_addr(stA + 8192, wn * 64 + p * 16 + b_ro, ks * 2 + b_co));
                bH[2 * p][0] = r[0]; bH[2 * p][1] = r[1];
                bH[2 * p + 1][0] = r[2]; bH[2 * p + 1][1] = r[3];
            }
#pragma unroll
            for (int mi = 0; mi < 2; mi++)
#pragma unroll
                for (int nj = 0; nj < 8; nj++)
                    MMA(acc[mi][nj], aH[mi], bH[nj]);
        }
    }

    const int cph = (lid & 3) * 2;
    const int nbase = n0 + wn * 64;
#pragma unroll
    for (int mi = 0; mi < 2; mi++)
#pragma unroll
        for (int hf = 0; hf < 2; hf++) {
            int m = m0 + wm * 32 + mi * 16 + hf * 8 + (lid >> 2);
            __half* op = weiH + ((size_t)c * MIQ + m) * D_EMB + nbase + cph;
#pragma unroll
            for (int nj = 0; nj < 8; nj++)
                *(__half2*)(op + nj * 8) = __halves2half2(
                    __float2half_rn(acc[mi][nj][hf * 2 + 0]),
                    __float2half_rn(acc[mi][nj][hf * 2 + 1]));
        }
}

// ---------------------------------------------------------------------------
// Main HMMA GEMM (plain fp16, BK=64, 128B-row swizzle, 2 CTAs/SM)
// ---------------------------------------------------------------------------
#define EPI_TANH 0
#define EPI_FILM 1
#define EPI_RELU 2
#define EPI_FINAL 3

#define G_TILE 16384
#define G_STAGE (2 * G_TILE)
#define G_SMEM (3 * G_STAGE)               // 96 KB; 2 CTAs = 192 KB

template <int EPI>
__global__ __launch_bounds__(256, 2) void gemm_hmma(
    const __half* __restrict__ Ah, const __half* __restrict__ Bh,
    const float* __restrict__ bias,
    const __half* __restrict__ scal,
    const float* __restrict__ rgn,
    float* __restrict__ outF,
    __half* __restrict__ outH)
{
    extern __shared__ __align__(1024) uint8_t dsm[];
    const uint32_t sb = smem_u32(dsm);
    const int tid = threadIdx.x;
    const int wid = tid >> 5, lid = tid & 31;
    const int wm = wid & 3, wn = wid >> 2;
    const int m0 = blockIdx.y * 128;
    const int n0 = blockIdx.x * 128;

    const int a_ro = lid & 15, a_co = lid >> 4;
    const int b_ro = ((lid >> 4) & 1) * 8 + (lid & 7);
    const int b_co = (lid >> 3) & 1;

    float c[2][8][4];
#pragma unroll
    for (int a = 0; a < 2; a++)
#pragma unroll
        for (int b = 0; b < 8; b++)
#pragma unroll
            for (int d = 0; d < 4; d++) c[a][b][d] = 0.f;

#pragma unroll
    for (int s = 0; s < 2; s++) {
        uint32_t st = sb + s * G_STAGE;
        load_t128w(Ah, D_EMB, m0, s * 64, st, tid);
        load_t128w(Bh, D_EMB, n0, s * 64, st + G_TILE, tid);
        asm volatile("cp.async.commit_group;");
    }

    int stage = 0;
    for (int i = 0; i < 16; i++) {
        asm volatile("cp.async.wait_group 1;");
        __syncthreads();
        if (i + 2 < 16) {
            uint32_t st = sb + ((stage + 2) % 3) * G_STAGE;
            int kc = (i + 2) * 64;
            load_t128w(Ah, D_EMB, m0, kc, st, tid);
            load_t128w(Bh, D_EMB, n0, kc, st + G_TILE, tid);
        }
        asm volatile("cp.async.commit_group;");

        uint32_t stA = sb + stage * G_STAGE;
#pragma unroll
        for (int ks = 0; ks < 4; ks++) {
            uint32_t aH[2][4], bH[8][2];
#pragma unroll
            for (int mi = 0; mi < 2; mi++)
                LDSM_X4(aH[mi], sm_addr128(stA, wm * 32 + mi * 16 + a_ro, ks * 2 + a_co));
#pragma unroll
            for (int p = 0; p < 4; p++) {
                uint32_t r[4];
                LDSM_X4(r, sm_addr128(stA + G_TILE, wn * 64 + p * 16 + b_ro, ks * 2 + b_co));
                bH[2 * p][0] = r[0]; bH[2 * p][1] = r[1];
                bH[2 * p + 1][0] = r[2]; bH[2 * p + 1][1] = r[3];
            }
#pragma unroll
            for (int mi = 0; mi < 2; mi++)
#pragma unroll
                for (int nj = 0; nj < 8; nj++)
                    MMA(c[mi][nj], aH[mi], bH[nj]);
        }
        stage = (stage + 1) % 3;
    }

    const int nbase = n0 + wn * 64;
    const int mbase = m0 + wm * 32;
    const int cph = (lid & 3) * 2;

    float2 bv[8];
#pragma unroll
    for (int nj = 0; nj < 8; nj++)
        bv[nj] = *(const float2*)(bias + nbase + nj * 8 + cph);

#pragma unroll
    for (int mi = 0; mi < 2; mi++) {
#pragma unroll
        for (int hf = 0; hf < 2; hf++) {
            const int m = mbase + mi * 16 + hf * 8 + (lid >> 2);
            const int t = m / Q_RGN;
            const int q = m - t * Q_RGN;
            const int i_img = t & (I_IMG - 1);
            const int cc = t >> 5;

            if (EPI == EPI_TANH) {
                size_t ob = (size_t)m * D_EMB + nbase + cph;
#pragma unroll
                for (int nj = 0; nj < 8; nj++) {
                    float x0 = tanh_hw(c[mi][nj][hf * 2 + 0] + bv[nj].x);
                    float x1 = tanh_hw(c[mi][nj][hf * 2 + 1] + bv[nj].y);
                    *(__half2*)(outH + ob + nj * 8) =
                        __halves2half2(__float2half_rn(x0), __float2half_rn(x1));
                }
            } else if (EPI == EPI_FILM) {
                const float* rp = rgn + ((size_t)(i_img * Q_RGN + q)) * D_EMB + nbase + cph;
                const __half* sp = scal + (size_t)m * D_EMB + nbase + cph;
                size_t ob = (size_t)m * D_EMB + nbase + cph;
#pragma unroll
                for (int nj = 0; nj < 8; nj++) {
                    float2 rv = *(const float2*)(rp + nj * 8);
                    float2 sv = __half22float2(*(const __half2*)(sp + nj * 8));
                    float x0 = rv.x * sv.x + (c[mi][nj][hf * 2 + 0] + bv[nj].x);
                    float x1 = rv.y * sv.y + (c[mi][nj][hf * 2 + 1] + bv[nj].y);
                    *(__half2*)(outH + ob + nj * 8) =
                        __halves2half2(__float2half_rn(x0), __float2half_rn(x1));
                }
            } else if (EPI == EPI_RELU) {
                size_t ob = (size_t)m * D_EMB + nbase + cph;
#pragma unroll
                for (int nj = 0; nj < 8; nj++) {
                    float x0 = fmaxf(c[mi][nj][hf * 2 + 0] + bv[nj].x, 0.f);
                    float x1 = fmaxf(c[mi][nj][hf * 2 + 1] + bv[nj].y, 0.f);
                    *(__half2*)(outH + ob + nj * 8) =
                        __halves2half2(__float2half_rn(x0), __float2half_rn(x1));
                }
            } else {
                const float* rp = rgn + ((size_t)(i_img * Q_RGN + q)) * D_EMB + nbase + cph;
                float* op = outF + (((size_t)(i_img * C_CAP + cc)) * Q_RGN + q) * D_EMB + nbase + cph;
#pragma unroll
                for (int nj = 0; nj < 8; nj++) {
                    float2 rv = *(const float2*)(rp + nj * 8);
                    float2 o;
                    o.x = c[mi][nj][hf * 2 + 0] + bv[nj].x + rv.x;
                    o.y = c[mi][nj][hf * 2 + 1] + bv[nj].y + rv.y;
                    *(float2*)(op + nj * 8) = o;
                }
            }
        }
    }
}

// ---------------------------------------------------------------------------
extern "C" void kernel_launch(void* const* d_in, const int* in_sizes, int n_in,
                              void* d_out, int out_size)
{
    const float* rgn     = (const float*)d_in[0];
    const float* wrd     = (const float*)d_in[2];
    const int*   lens    = (const int*)d_in[4];
    const float* w_scale = (const float*)d_in[5];
    const float* b_scale = (const float*)d_in[6];
    const float* w_shift = (const float*)d_in[7];
    const float* b_shift = (const float*)d_in[8];
    const float* w1      = (const float*)d_in[9];
    const float* b1      = (const float*)d_in[10];
    const float* w2      = (const float*)d_in[11];
    const float* b2      = (const float*)d_in[12];
    float* out = (float*)d_out;

    __half *weiH, *xH, *hH, *scalH, *wH, *rgnH, *rgnL, *wrdH, *wrdL, *wrdTH, *attnH;
    float *S;
    cudaGetSymbolAddress((void**)&weiH,  g_weiH);
    cudaGetSymbolAddress((void**)&xH,    g_xH);
    cudaGetSymbolAddress((void**)&hH,    g_hH);
    cudaGetSymbolAddress((void**)&scalH, g_scalH);
    cudaGetSymbolAddress((void**)&wH,    g_wH);
    cudaGetSymbolAddress((void**)&rgnH,  g_rgnH);
    cudaGetSymbolAddress((void**)&rgnL,  g_rgnL);
    cudaGetSymbolAddress((void**)&wrdH,  g_wrdH);
    cudaGetSymbolAddress((void**)&wrdL,  g_wrdL);
    cudaGetSymbolAddress((void**)&wrdTH, g_wrdTH);
    cudaGetSymbolAddress((void**)&attnH, g_attnH);
    cudaGetSymbolAddress((void**)&S,     g_S);

    cudaFuncSetAttribute(gemm_score, cudaFuncAttributeMaxDynamicSharedMemorySize, A1_SMEM);
    cudaFuncSetAttribute(gemm_wei,   cudaFuncAttributeMaxDynamicSharedMemorySize, A3_SMEM);
    cudaFuncSetAttribute(gemm_hmma<EPI_TANH>,  cudaFuncAttributeMaxDynamicSharedMemorySize, G_SMEM);
    cudaFuncSetAttribute(gemm_hmma<EPI_FILM>,  cudaFuncAttributeMaxDynamicSharedMemorySize, G_SMEM);
    cudaFuncSetAttribute(gemm_hmma<EPI_RELU>,  cudaFuncAttributeMaxDynamicSharedMemorySize, G_SMEM);
    cudaFuncSetAttribute(gemm_hmma<EPI_FINAL>, cudaFuncAttributeMaxDynamicSharedMemorySize, G_SMEM);

    // launch 0: all preps fused (weights, rgn split, wrd pad/split/transpose)
    prep_all_kernel<<<dim3(1152, 6), 256>>>(
        w_scale, w_shift, w1, w2, rgn, wrd, wH, rgnH, rgnL, wrdH, wrdL, wrdTH);

    // launches 1-3: attention on tensor cores
    gemm_score<<<dim3(MIQ / 128, C_CAP), 256, A1_SMEM>>>(rgnH, rgnL, wrdH, wrdL, S);
    attn_norm_kernel<<<dim3(I_IMG, C_CAP), 128>>>(S, lens, attnH);
    gemm_wei<<<dim3(D_EMB / 128, MIQ / 128, C_CAP), 256, A3_SMEM>>>(attnH, wrdTH, weiH);

    // launches 4-7: main GEMM chain
    dim3 ggrid(D_EMB / 128, M_TOT / 128);
    gemm_hmma<EPI_TANH><<<ggrid, 256, G_SMEM>>>(
        weiH, wH + 0 * (size_t)W_ELEMS, b_scale, nullptr, nullptr, nullptr, scalH);
    gemm_hmma<EPI_FILM><<<ggrid, 256, G_SMEM>>>(
        weiH, wH + 1 * (size_t)W_ELEMS, b_shift, scalH, rgn, nullptr, xH);
    gemm_hmma<EPI_RELU><<<ggrid, 256, G_SMEM>>>(
        xH, wH + 2 * (size_t)W_ELEMS, b1, nullptr, nullptr, nullptr, hH);
    gemm_hmma<EPI_FINAL><<<ggrid, 256, G_SMEM>>>(
        hH, wH + 3 * (size_t)W_ELEMS, b2, nullptr, rgn, out, nullptr);
}

// round 16
// speedup vs baseline: 4.4774x; 1.0526x over previous
#include <cuda_runtime.h>
#include <cuda_fp16.h>
#include <math.h>
#include <stdint.h>

// Problem dims
#define I_IMG 32
#define C_CAP 32
#define Q_RGN 36
#define L_MAX 50
#define LPAD 64
#define D_EMB 1024
#define MIQ (I_IMG * Q_RGN)                    // 1152
#define M_TOT (C_CAP * MIQ)                    // 36864
#define ELEMS ((size_t)M_TOT * D_EMB)
#define W_ELEMS (D_EMB * D_EMB)

// ---------------- scratch ----------------
__device__ __align__(256) __half g_weiH[ELEMS];
__device__ __align__(256) __half g_xH[ELEMS];
__device__ __align__(256) __half g_hH[ELEMS];
__device__ __align__(256) __half g_wH[4][W_ELEMS];
__device__ __align__(256) __half g_rgnH[MIQ * D_EMB];
__device__ __align__(256) __half g_rgnL[MIQ * D_EMB];
__device__ __align__(256) __half g_wrdH[C_CAP * LPAD * D_EMB];
__device__ __align__(256) __half g_wrdL[C_CAP * LPAD * D_EMB];
__device__ __align__(256) __half g_wrdTH[C_CAP * D_EMB * LPAD];
__device__ __align__(256) float  g_S[(size_t)C_CAP * MIQ * LPAD];
__device__ __align__(256) __half g_attnH[(size_t)C_CAP * MIQ * LPAD];

__device__ __forceinline__ void split_h(float x, __half& h, __half& l) {
    h = __float2half_rn(x);
    l = __float2half_rn(x - __half2float(h));
}
__device__ __forceinline__ float tanh_hw(float x) {
    float y;
    asm("tanh.approx.f32 %0, %1;" : "=f"(y) : "f"(x));
    return y;
}

// ---------------- common HMMA infrastructure ----------------
__device__ __forceinline__ uint32_t smem_u32(const void* p) {
    uint32_t a;
    asm("{ .reg .u64 t; cvta.to.shared.u64 t, %1; cvt.u32.u64 %0, t; }"
        : "=r"(a) : "l"(p));
    return a;
}
// 64B-row tiles
__device__ __forceinline__ uint32_t sm_addr(uint32_t base, int row, int c16) {
    return base + row * 64 + (((uint32_t)(c16 ^ ((row >> 1) & 3))) << 4);
}
// 128B-row tiles
__device__ __forceinline__ uint32_t sm_addr128(uint32_t base, int row, int c16) {
    return base + row * 128 + (((uint32_t)(c16 ^ (row & 7))) << 4);
}
__device__ __forceinline__ void load_t128(
    const __half* __restrict__ g, int ld, int row0, int kcol0, uint32_t sb, int tid)
{
#pragma unroll
    for (int j = 0; j < 2; j++) {
        int id = tid + 256 * j;
        int r = id >> 2, c = id & 3;
        const void* gp = g + (size_t)(row0 + r) * ld + kcol0 + c * 8;
        asm volatile("cp.async.cg.shared.global [%0], [%1], 16;"
                     :: "r"(sm_addr(sb, r, c)), "l"(gp));
    }
}
__device__ __forceinline__ void load_t64(
    const __half* __restrict__ g, int ld, int row0, int kcol0, uint32_t sb, int tid)
{
    int r = tid >> 2, c = tid & 3;
    const void* gp = g + (size_t)(row0 + r) * ld + kcol0 + c * 8;
    asm volatile("cp.async.cg.shared.global [%0], [%1], 16;"
                 :: "r"(sm_addr(sb, r, c)), "l"(gp));
}
// 128 rows x 64 cols (128B/row)
__device__ __forceinline__ void load_t128w(
    const __half* __restrict__ g, int ld, int row0, int kcol0, uint32_t sb, int tid)
{
#pragma unroll
    for (int j = 0; j < 4; j++) {
        int id = tid + 256 * j;
        int r = id >> 3, c = id & 7;
        const void* gp = g + (size_t)(row0 + r) * ld + kcol0 + c * 8;
        asm volatile("cp.async.cg.shared.global [%0], [%1], 16;"
                     :: "r"(sm_addr128(sb, r, c)), "l"(gp));
    }
}
// 64 rows x 64 cols (128B/row)
__device__ __forceinline__ void load_t64w(
    const __half* __restrict__ g, int ld, int row0, int kcol0, uint32_t sb, int tid)
{
#pragma unroll
    for (int j = 0; j < 2; j++) {
        int id = tid + 256 * j;       // 0..511
        int r = id >> 3, c = id & 7;
        const void* gp = g + (size_t)(row0 + r) * ld + kcol0 + c * 8;
        asm volatile("cp.async.cg.shared.global [%0], [%1], 16;"
                     :: "r"(sm_addr128(sb, r, c)), "l"(gp));
    }
}

#define LDSM_X4(R, addr) \
    asm volatile("ldmatrix.sync.aligned.m8n8.x4.shared.b16 {%0,%1,%2,%3}, [%4];" \
        : "=r"((R)[0]), "=r"((R)[1]), "=r"((R)[2]), "=r"((R)[3]) : "r"(addr))
#define MMA(C, A, B) \
    asm volatile("mma.sync.aligned.m16n8k16.row.col.f32.f16.f16.f32 " \
        "{%0,%1,%2,%3}, {%4,%5,%6,%7}, {%8,%9}, {%0,%1,%2,%3};" \
        : "+f"((C)[0]), "+f"((C)[1]), "+f"((C)[2]), "+f"((C)[3]) \
        : "r"((A)[0]), "r"((A)[1]), "r"((A)[2]), "r"((A)[3]), "r"((B)[0]), "r"((B)[1]))

// ---------------------------------------------------------------------------
// prep_all: task 0-3 weight cvt, task 4 rgn split, task 5 wrd pad/split/transp
// ---------------------------------------------------------------------------
__global__ __launch_bounds__(256) void prep_all_kernel(
    const float* __restrict__ w0, const float* __restrict__ w1,
    const float* __restrict__ w2, const float* __restrict__ w3,
    const float* __restrict__ rgn, const float* __restrict__ wrd,
    __half* __restrict__ wH, __half* __restrict__ rgnH, __half* __restrict__ rgnL,
    __half* __restrict__ wh, __half* __restrict__ wl, __half* __restrict__ wth)
{
    const int task = blockIdx.y;
    const int bx = blockIdx.x;
    const int tid = threadIdx.x;
    __shared__ __align__(16) float ts[64][65];

    if (task < 4) {
        int i = bx * 256 + tid;
        if (i < W_ELEMS / 4) {
            const float* s = (task == 0) ? w0 : (task == 1) ? w1 : (task == 2) ? w2 : w3;
            float4 v = ((const float4*)s)[i];
            union { uint2 u; __half h[4]; } o;
            o.h[0] = __float2half_rn(v.x); o.h[1] = __float2half_rn(v.y);
            o.h[2] = __float2half_rn(v.z); o.h[3] = __float2half_rn(v.w);
            ((uint2*)(wH + (size_t)task * W_ELEMS))[i] = o.u;
        }
    } else if (task == 4) {
        int i = bx * 256 + tid;
        if (i < MIQ * D_EMB / 4) {
            float4 v = ((const float4*)rgn)[i];
            union { uint2 u; __half h[4]; } oh, ol;
            split_h(v.x, oh.h[0], ol.h[0]); split_h(v.y, oh.h[1], ol.h[1]);
            split_h(v.z, oh.h[2], ol.h[2]); split_h(v.w, oh.h[3], ol.h[3]);
            ((uint2*)rgnH)[i] = oh.u;
            ((uint2*)rgnL)[i] = ol.u;
        }
    } else {
        if (bx >= (D_EMB / 64) * C_CAP) return;
        const int d0 = (bx & 15) * 64;
        const int c  = bx >> 4;

        for (int idx = tid; idx < 64 * 64; idx += 256) {
            int l = idx >> 6, dd = idx & 63;
            float v = (l < L_MAX) ? wrd[((size_t)c * L_MAX + l) * D_EMB + d0 + dd] : 0.f;
            ts[l][dd] = v;
            __half h, lo; split_h(v, h, lo);
            wh[((size_t)c * LPAD + l) * D_EMB + d0 + dd] = h;
            wl[((size_t)c * LPAD + l) * D_EMB + d0 + dd] = lo;
        }
        __syncthreads();
        for (int idx = tid; idx < 64 * 64; idx += 256) {
            int d = idx >> 6, l = idx & 63;
            wth[((size_t)c * D_EMB + d0 + d) * LPAD + l] = __float2half_rn(ts[l][d]);
        }
    }
}

// ---------------------------------------------------------------------------
// A1: scores  S[c, m=(i,q), l] = leaky( rgn[m,:] . wrd[c,l,:] ), 3-term HMMA.
// ---------------------------------------------------------------------------
#define A1_STAGE (2 * 8192 + 2 * 4096)
#define A1_SMEM (3 * A1_STAGE)             // 72 KB

__global__ __launch_bounds__(256, 2) void gemm_score(
    const __half* __restrict__ Rh, const __half* __restrict__ Rl,
    const __half* __restrict__ Wh, const __half* __restrict__ Wl,
    float* __restrict__ S)
{
    extern __shared__ __align__(1024) uint8_t dsm[];
    const uint32_t sb = smem_u32(dsm);
    const int tid = threadIdx.x;
    const int wid = tid >> 5, lid = tid & 31;
    const int wm = wid & 3, wn = wid >> 2;
    const int m0 = blockIdx.x * 128;
    const int c  = blockIdx.y;

    const __half* Bh = Wh + (size_t)c * LPAD * D_EMB;
    const __half* Bl = Wl + (size_t)c * LPAD * D_EMB;

    const int a_ro = lid & 15, a_co = lid >> 4;
    const int b_ro = ((lid >> 4) & 1) * 8 + (lid & 7);
    const int b_co = (lid >> 3) & 1;

    float acc[2][4][4];
#pragma unroll
    for (int a = 0; a < 2; a++)
#pragma unroll
        for (int b = 0; b < 4; b++)
#pragma unroll
            for (int d = 0; d < 4; d++) acc[a][b][d] = 0.f;

#pragma unroll
    for (int s = 0; s < 2; s++) {
        uint32_t st = sb + s * A1_STAGE;
        load_t128(Rh, D_EMB, m0, s * 32, st, tid);
        load_t128(Rl, D_EMB, m0, s * 32, st + 8192, tid);
        load_t64(Bh, D_EMB, 0, s * 32, st + 16384, tid);
        load_t64(Bl, D_EMB, 0, s * 32, st + 20480, tid);
        asm volatile("cp.async.commit_group;");
    }

    int stage = 0;
    for (int i = 0; i < 32; i++) {
        asm volatile("cp.async.wait_group 1;");
        __syncthreads();
        if (i + 2 < 32) {
            uint32_t st = sb + ((stage + 2) % 3) * A1_STAGE;
            int kc = (i + 2) * 32;
            load_t128(Rh, D_EMB, m0, kc, st, tid);
            load_t128(Rl, D_EMB, m0, kc, st + 8192, tid);
            load_t64(Bh, D_EMB, 0, kc, st + 16384, tid);
            load_t64(Bl, D_EMB, 0, kc, st + 20480, tid);
        }
        asm volatile("cp.async.commit_group;");

        uint32_t stA = sb + stage * A1_STAGE;
#pragma unroll
        for (int ks = 0; ks < 2; ks++) {
            uint32_t aH[2][4], aL[2][4], bH[4][2], bL[4][2];
#pragma unroll
            for (int mi = 0; mi < 2; mi++) {
                LDSM_X4(aH[mi], sm_addr(stA, wm * 32 + mi * 16 + a_ro, ks * 2 + a_co));
                LDSM_X4(aL[mi], sm_addr(stA + 8192, wm * 32 + mi * 16 + a_ro, ks * 2 + a_co));
            }
#pragma unroll
            for (int p = 0; p < 2; p++) {
                uint32_t r[4];
                LDSM_X4(r, sm_addr(stA + 16384, wn * 32 + p * 16 + b_ro, ks * 2 + b_co));
                bH[2 * p][0] = r[0]; bH[2 * p][1] = r[1];
                bH[2 * p + 1][0] = r[2]; bH[2 * p + 1][1] = r[3];
                LDSM_X4(r, sm_addr(stA + 20480, wn * 32 + p * 16 + b_ro, ks * 2 + b_co));
                bL[2 * p][0] = r[0]; bL[2 * p][1] = r[1];
                bL[2 * p + 1][0] = r[2]; bL[2 * p + 1][1] = r[3];
            }
#pragma unroll
            for (int mi = 0; mi < 2; mi++)
#pragma unroll
                for (int nj = 0; nj < 4; nj++) {
                    MMA(acc[mi][nj], aH[mi], bH[nj]);
                    MMA(acc[mi][nj], aH[mi], bL[nj]);
                    MMA(acc[mi][nj], aL[mi], bH[nj]);
                }
        }
        stage = (stage + 1) % 3;
    }

    const int cph = (lid & 3) * 2;
#pragma unroll
    for (int mi = 0; mi < 2; mi++)
#pragma unroll
        for (int hf = 0; hf < 2; hf++) {
            int m = m0 + wm * 32 + mi * 16 + hf * 8 + (lid >> 2);
            float* op = S + ((size_t)c * MIQ + m) * LPAD + wn * 32 + cph;
#pragma unroll
            for (int nj = 0; nj < 4; nj++) {
                float v0 = acc[mi][nj][hf * 2 + 0];
                float v1 = acc[mi][nj][hf * 2 + 1];
                float2 o;
                o.x = (v0 >= 0.f) ? v0 : 0.1f * v0;
                o.y = (v1 >= 0.f) ? v1 : 0.1f * v1;
                *(float2*)(op + nj * 8) = o;
            }
        }
}

// ---------------------------------------------------------------------------
// A2: per (c,i): L2-normalize over q, masked softmax over l -> attn fp16.
// ---------------------------------------------------------------------------
__global__ __launch_bounds__(128) void attn_norm_kernel(
    const float* __restrict__ S, const int* __restrict__ lens,
    __half* __restrict__ attnH)
{
    const int i = blockIdx.x;
    const int c = blockIdx.y;
    const int tid = threadIdx.x;
    __shared__ __align__(16) float s[Q_RGN][68];
    __shared__ __align__(16) float sinv[LPAD];
    __shared__ __align__(16) __half ah[Q_RGN * LPAD];

    const size_t base = ((size_t)c * MIQ + i * Q_RGN) * LPAD;

    for (int idx = tid; idx < Q_RGN * 16; idx += 128) {
        int q = idx >> 4, f4 = idx & 15;
        float4 v = *(const float4*)(S + base + q * LPAD + f4 * 4);
        *(float4*)&s[q][f4 * 4] = v;
    }
    __syncthreads();

    {
        const int l = tid >> 1, hf = tid & 1;
        float ss = 0.f;
        for (int q = hf * 18; q < hf * 18 + 18; q++) {
            float v = s[q][l]; ss += v * v;
        }
        ss += __shfl_xor_sync(0xffffffffu, ss, 1);
        if (hf == 0) sinv[l] = 1.f / fmaxf(sqrtf(ss), 1e-12f);
    }
    __syncthreads();

    const int len = lens[c];
    {
        const int q = tid >> 1, hf = tid & 1;
        const bool act = (q < Q_RGN);
        const int l0 = hf * 32;
        const int l1 = min(len, l0 + 32);
        float mx = -1e30f;
        if (act)
            for (int l = l0; l < l1; l++) mx = fmaxf(mx, s[q][l] * sinv[l]);
        mx = fmaxf(mx, __shfl_xor_sync(0xffffffffu, mx, 1));
        float sum = 0.f;
        if (act)
            for (int l = l0; l < l1; l++) {
                float e = expf(9.f * (s[q][l] * sinv[l] - mx));
                s[q][l] = e;
                sum += e;
            }
        sum += __shfl_xor_sync(0xffffffffu, sum, 1);
        if (act) {
            float inv = 1.f / sum;
            for (int l = l0; l < l0 + 32; l++)
                ah[q * LPAD + l] = __float2half_rn((l < l1) ? s[q][l] * inv : 0.f);
        }
    }
    __syncthreads();

    for (int u = tid; u < Q_RGN * LPAD / 8; u += 128)
        *(uint4*)(attnH + base + u * 8) = *(const uint4*)(ah + u * 8);
}

// ---------------------------------------------------------------------------
// A3: wei = attn @ wrdT^T; 1-term fp16, SINGLE-STAGE (K=64, 128B-row tiles)
// ---------------------------------------------------------------------------
#define A3_SMEM (2 * 16384)                // A 16 KB + B 16 KB

__global__ __launch_bounds__(256, 2) void gemm_wei(
    const __half* __restrict__ AH, const __half* __restrict__ WTH,
    __half* __restrict__ weiH)
{
    extern __shared__ __align__(1024) uint8_t dsm[];
    const uint32_t sb = smem_u32(dsm);
    const int tid = threadIdx.x;
    const int wid = tid >> 5, lid = tid & 31;
    const int wm = wid & 3, wn = wid >> 2;
    const int n0 = blockIdx.x * 128;
    const int m0 = blockIdx.y * 128;
    const int c  = blockIdx.z;

    const __half* Ah = AH + (size_t)c * MIQ * LPAD;
    const __half* Bh = WTH + (size_t)c * D_EMB * LPAD;

    const int a_ro = lid & 15, a_co = lid >> 4;
    const int b_ro = ((lid >> 4) & 1) * 8 + (lid & 7);
    const int b_co = (lid >> 3) & 1;

    float acc[2][8][4];
#pragma unroll
    for (int a = 0; a < 2; a++)
#pragma unroll
        for (int b = 0; b < 8; b++)
#pragma unroll
            for (int d = 0; d < 4; d++) acc[a][b][d] = 0.f;

    // one-shot load of full K=64 (128B rows, 128B swizzle)
    load_t128w(Ah, LPAD, m0, 0, sb, tid);
    load_t128w(Bh, LPAD, n0, 0, sb + 16384, tid);
    asm volatile("cp.async.commit_group;");
    asm volatile("cp.async.wait_group 0;");
    __syncthreads();

#pragma unroll
    for (int ks = 0; ks < 4; ks++) {
        uint32_t aH[2][4], bH[8][2];
#pragma unroll
        for (int mi = 0; mi < 2; mi++)
            LDSM_X4(aH[mi], sm_addr128(sb, wm * 32 + mi * 16 + a_ro, ks * 2 + a_co));
#pragma unroll
        for (int p = 0; p < 4; p++) {
            uint32_t r[4];
            LDSM_X4(r, sm_addr128(sb + 16384, wn * 64 + p * 16 + b_ro, ks * 2 + b_co));
            bH[2 * p][0] = r[0]; bH[2 * p][1] = r[1];
            bH[2 * p + 1][0] = r[2]; bH[2 * p + 1][1] = r[3];
        }
#pragma unroll
        for (int mi = 0; mi < 2; mi++)
#pragma unroll
            for (int nj = 0; nj < 8; nj++)
                MMA(acc[mi][nj], aH[mi], bH[nj]);
    }

    const int cph = (lid & 3) * 2;
    const int nbase = n0 + wn * 64;
#pragma unroll
    for (int mi = 0; mi < 2; mi++)
#pragma unroll
        for (int hf = 0; hf < 2; hf++) {
            int m = m0 + wm * 32 + mi * 16 + hf * 8 + (lid >> 2);
            __half* op = weiH + ((size_t)c * MIQ + m) * D_EMB + nbase + cph;
#pragma unroll
            for (int nj = 0; nj < 8; nj++)
                *(__half2*)(op + nj * 8) = __halves2half2(
                    __float2half_rn(acc[mi][nj][hf * 2 + 0]),
                    __float2half_rn(acc[mi][nj][hf * 2 + 1]));
        }
}

// ---------------------------------------------------------------------------
// Dual GEMM + FiLM: x = rgn*tanh(wei@w_sc^T + b_sc) + (wei@w_sh^T + b_sh)
// CTA tile 128x64 (warp tile 32x32), BK=64, 2 CTAs/SM.
// ---------------------------------------------------------------------------
#define DF_STAGE (16384 + 2 * 8192)        // A 16 KB + Bsc 8 KB + Bsh 8 KB
#define DF_SMEM (3 * DF_STAGE)             // 96 KB

__global__ __launch_bounds__(256, 2) void gemm_dual_film(
    const __half* __restrict__ Ah,
    const __half* __restrict__ Bsc, const __half* __restrict__ Bsh,
    const float* __restrict__ bias_sc, const float* __restrict__ bias_sh,
    const float* __restrict__ rgn,
    __half* __restrict__ outH)
{
    extern __shared__ __align__(1024) uint8_t dsm[];
    const uint32_t sb = smem_u32(dsm);
    const int tid = threadIdx.x;
    const int wid = tid >> 5, lid = tid & 31;
    const int wm = wid & 3, wn = wid >> 2;       // 4x32 m, 2x32 n
    const int m0 = blockIdx.y * 128;
    const int n0 = blockIdx.x * 64;

    const int a_ro = lid & 15, a_co = lid >> 4;
    const int b_ro = ((lid >> 4) & 1) * 8 + (lid & 7);
    const int b_co = (lid >> 3) & 1;

    float asc[2][4][4], ash[2][4][4];
#pragma unroll
    for (int a = 0; a < 2; a++)
#pragma unroll
        for (int b = 0; b < 4; b++)
#pragma unroll
            for (int d = 0; d < 4; d++) { asc[a][b][d] = 0.f; ash[a][b][d] = 0.f; }

#pragma unroll
    for (int s = 0; s < 2; s++) {
        uint32_t st = sb + s * DF_STAGE;
        load_t128w(Ah,  D_EMB, m0, s * 64, st, tid);
        load_t64w(Bsc, D_EMB, n0, s * 64, st + 16384, tid);
        load_t64w(Bsh, D_EMB, n0, s * 64, st + 24576, tid);
        asm volatile("cp.async.commit_group;");
    }

    int stage = 0;
    for (int i = 0; i < 16; i++) {
        asm volatile("cp.async.wait_group 1;");
        __syncthreads();
        if (i + 2 < 16) {
            uint32_t st = sb + ((stage + 2) % 3) * DF_STAGE;
            int kc = (i + 2) * 64;
            load_t128w(Ah,  D_EMB, m0, kc, st, tid);
            load_t64w(Bsc, D_EMB, n0, kc, st + 16384, tid);
            load_t64w(Bsh, D_EMB, n0, kc, st + 24576, tid);
        }
        asm volatile("cp.async.commit_group;");

        uint32_t stA = sb + stage * DF_STAGE;
#pragma unroll
        for (int ks = 0; ks < 4; ks++) {
            uint32_t aH[2][4], bc[4][2], bs[4][2];
#pragma unroll
            for (int mi = 0; mi < 2; mi++)
                LDSM_X4(aH[mi], sm_addr128(stA, wm * 32 + mi * 16 + a_ro, ks * 2 + a_co));
#pragma unroll
            for (int p = 0; p < 2; p++) {
                uint32_t r[4];
                LDSM_X4(r, sm_addr128(stA + 16384, wn * 32 + p * 16 + b_ro, ks * 2 + b_co));
                bc[2 * p][0] = r[0]; bc[2 * p][1] = r[1];
                bc[2 * p + 1][0] = r[2]; bc[2 * p + 1][1] = r[3];
                LDSM_X4(r, sm_addr128(stA + 24576, wn * 32 + p * 16 + b_ro, ks * 2 + b_co));
                bs[2 * p][0] = r[0]; bs[2 * p][1] = r[1];
                bs[2 * p + 1][0] = r[2]; bs[2 * p + 1][1] = r[3];
            }
#pragma unroll
            for (int mi = 0; mi < 2; mi++)
#pragma unroll
                for (int nj = 0; nj < 4; nj++) {
                    MMA(asc[mi][nj], aH[mi], bc[nj]);
                    MMA(ash[mi][nj], aH[mi], bs[nj]);
                }
        }
        stage = (stage + 1) % 3;
    }

    const int nbase = n0 + wn * 32;
    const int mbase = m0 + wm * 32;
    const int cph = (lid & 3) * 2;

    float2 bcv[4], bsv[4];
#pragma unroll
    for (int nj = 0; nj < 4; nj++) {
        bcv[nj] = *(const float2*)(bias_sc + nbase + nj * 8 + cph);
        bsv[nj] = *(const float2*)(bias_sh + nbase + nj * 8 + cph);
    }

#pragma unroll
    for (int mi = 0; mi < 2; mi++) {
#pragma unroll
        for (int hf = 0; hf < 2; hf++) {
            const int m = mbase + mi * 16 + hf * 8 + (lid >> 2);
            const int t = m / Q_RGN;
            const int q = m - t * Q_RGN;
            const int i_img = t & (I_IMG - 1);
            const float* rp = rgn + ((size_t)(i_img * Q_RGN + q)) * D_EMB + nbase + cph;
            size_t ob = (size_t)m * D_EMB + nbase + cph;
#pragma unroll
            for (int nj = 0; nj < 4; nj++) {
                float2 rv = *(const float2*)(rp + nj * 8);
                float sc0 = tanh_hw(asc[mi][nj][hf * 2 + 0] + bcv[nj].x);
                float sc1 = tanh_hw(asc[mi][nj][hf * 2 + 1] + bcv[nj].y);
                float x0 = rv.x * sc0 + (ash[mi][nj][hf * 2 + 0] + bsv[nj].x);
                float x1 = rv.y * sc1 + (ash[mi][nj][hf * 2 + 1] + bsv[nj].y);
                *(__half2*)(outH + ob + nj * 8) =
                    __halves2half2(__float2half_rn(x0), __float2half_rn(x1));
            }
        }
    }
}

// ---------------------------------------------------------------------------
// Main HMMA GEMM (plain fp16, BK=64, 128B-row swizzle, 2 CTAs/SM)
// ---------------------------------------------------------------------------
#define EPI_RELU 2
#define EPI_FINAL 3

#define G_TILE 16384
#define G_STAGE (2 * G_TILE)
#define G_SMEM (3 * G_STAGE)               // 96 KB

template <int EPI>
__global__ __launch_bounds__(256, 2) void gemm_hmma(
    const __half* __restrict__ Ah, const __half* __restrict__ Bh,
    const float* __restrict__ bias,
    const float* __restrict__ rgn,
    float* __restrict__ outF,
    __half* __restrict__ outH)
{
    extern __shared__ __align__(1024) uint8_t dsm[];
    const uint32_t sb = smem_u32(dsm);
    const int tid = threadIdx.x;
    const int wid = tid >> 5, lid = tid & 31;
    const int wm = wid & 3, wn = wid >> 2;
    const int m0 = blockIdx.y * 128;
    const int n0 = blockIdx.x * 128;

    const int a_ro = lid & 15, a_co = lid >> 4;
    const int b_ro = ((lid >> 4) & 1) * 8 + (lid & 7);
    const int b_co = (lid >> 3) & 1;

    float c[2][8][4];
#pragma unroll
    for (int a = 0; a < 2; a++)
#pragma unroll
        for (int b = 0; b < 8; b++)
#pragma unroll
            for (int d = 0; d < 4; d++) c[a][b][d] = 0.f;

#pragma unroll
    for (int s = 0; s < 2; s++) {
        uint32_t st = sb + s * G_STAGE;
        load_t128w(Ah, D_EMB, m0, s * 64, st, tid);
        load_t128w(Bh, D_EMB, n0, s * 64, st + G_TILE, tid);
        asm volatile("cp.async.commit_group;");
    }

    int stage = 0;
    for (int i = 0; i < 16; i++) {
        asm volatile("cp.async.wait_group 1;");
        __syncthreads();
        if (i + 2 < 16) {
            uint32_t st = sb + ((stage + 2) % 3) * G_STAGE;
            int kc = (i + 2) * 64;
            load_t128w(Ah, D_EMB, m0, kc, st, tid);
            load_t128w(Bh, D_EMB, n0, kc, st + G_TILE, tid);
        }
        asm volatile("cp.async.commit_group;");

        uint32_t stA = sb + stage * G_STAGE;
#pragma unroll
        for (int ks = 0; ks < 4; ks++) {
            uint32_t aH[2][4], bH[8][2];
#pragma unroll
            for (int mi = 0; mi < 2; mi++)
                LDSM_X4(aH[mi], sm_addr128(stA, wm * 32 + mi * 16 + a_ro, ks * 2 + a_co));
#pragma unroll
            for (int p = 0; p < 4; p++) {
                uint32_t r[4];
                LDSM_X4(r, sm_addr128(stA + G_TILE, wn * 64 + p * 16 + b_ro, ks * 2 + b_co));
                bH[2 * p][0] = r[0]; bH[2 * p][1] = r[1];
                bH[2 * p + 1][0] = r[2]; bH[2 * p + 1][1] = r[3];
            }
#pragma unroll
            for (int mi = 0; mi < 2; mi++)
#pragma unroll
                for (int nj = 0; nj < 8; nj++)
                    MMA(c[mi][nj], aH[mi], bH[nj]);
        }
        stage = (stage + 1) % 3;
    }

    const int nbase = n0 + wn * 64;
    const int mbase = m0 + wm * 32;
    const int cph = (lid & 3) * 2;

    float2 bv[8];
#pragma unroll
    for (int nj = 0; nj < 8; nj++)
        bv[nj] = *(const float2*)(bias + nbase + nj * 8 + cph);

#pragma unroll
    for (int mi = 0; mi < 2; mi++) {
#pragma unroll
        for (int hf = 0; hf < 2; hf++) {
            const int m = mbase + mi * 16 + hf * 8 + (lid >> 2);
            const int t = m / Q_RGN;
            const int q = m - t * Q_RGN;
            const int i_img = t & (I_IMG - 1);
            const int cc = t >> 5;

            if (EPI == EPI_RELU) {
                size_t ob = (size_t)m * D_EMB + nbase + cph;
#pragma unroll
                for (int nj = 0; nj < 8; nj++) {
                    float x0 = fmaxf(c[mi][nj][hf * 2 + 0] + bv[nj].x, 0.f);
                    float x1 = fmaxf(c[mi][nj][hf * 2 + 1] + bv[nj].y, 0.f);
                    *(__half2*)(outH + ob + nj * 8) =
                        __halves2half2(__float2half_rn(x0), __float2half_rn(x1));
                }
            } else {
                const float* rp = rgn + ((size_t)(i_img * Q_RGN + q)) * D_EMB + nbase + cph;
                float* op = outF + (((size_t)(i_img * C_CAP + cc)) * Q_RGN + q) * D_EMB + nbase + cph;
#pragma unroll
                for (int nj = 0; nj < 8; nj++) {
                    float2 rv = *(const float2*)(rp + nj * 8);
                    float2 o;
                    o.x = c[mi][nj][hf * 2 + 0] + bv[nj].x + rv.x;
                    o.y = c[mi][nj][hf * 2 + 1] + bv[nj].y + rv.y;
                    *(float2*)(op + nj * 8) = o;
                }
            }
        }
    }
}

// ---------------------------------------------------------------------------
extern "C" void kernel_launch(void* const* d_in, const int* in_sizes, int n_in,
                              void* d_out, int out_size)
{
    const float* rgn     = (const float*)d_in[0];
    const float* wrd     = (const float*)d_in[2];
    const int*   lens    = (const int*)d_in[4];
    const float* w_scale = (const float*)d_in[5];
    const float* b_scale = (const float*)d_in[6];
    const float* w_shift = (const float*)d_in[7];
    const float* b_shift = (const float*)d_in[8];
    const float* w1      = (const float*)d_in[9];
    const float* b1      = (const float*)d_in[10];
    const float* w2      = (const float*)d_in[11];
    const float* b2      = (const float*)d_in[12];
    float* out = (float*)d_out;

    __half *weiH, *xH, *hH, *wH, *rgnH, *rgnL, *wrdH, *wrdL, *wrdTH, *attnH;
    float *S;
    cudaGetSymbolAddress((void**)&weiH,  g_weiH);
    cudaGetSymbolAddress((void**)&xH,    g_xH);
    cudaGetSymbolAddress((void**)&hH,    g_hH);
    cudaGetSymbolAddress((void**)&wH,    g_wH);
    cudaGetSymbolAddress((void**)&rgnH,  g_rgnH);
    cudaGetSymbolAddress((void**)&rgnL,  g_rgnL);
    cudaGetSymbolAddress((void**)&wrdH,  g_wrdH);
    cudaGetSymbolAddress((void**)&wrdL,  g_wrdL);
    cudaGetSymbolAddress((void**)&wrdTH, g_wrdTH);
    cudaGetSymbolAddress((void**)&attnH, g_attnH);
    cudaGetSymbolAddress((void**)&S,     g_S);

    cudaFuncSetAttribute(gemm_score, cudaFuncAttributeMaxDynamicSharedMemorySize, A1_SMEM);
    cudaFuncSetAttribute(gemm_wei,   cudaFuncAttributeMaxDynamicSharedMemorySize, A3_SMEM);
    cudaFuncSetAttribute(gemm_dual_film, cudaFuncAttributeMaxDynamicSharedMemorySize, DF_SMEM);
    cudaFuncSetAttribute(gemm_hmma<EPI_RELU>,  cudaFuncAttributeMaxDynamicSharedMemorySize, G_SMEM);
    cudaFuncSetAttribute(gemm_hmma<EPI_FINAL>, cudaFuncAttributeMaxDynamicSharedMemorySize, G_SMEM);

    // launch 0: all preps
    prep_all_kernel<<<dim3(1152, 6), 256>>>(
        w_scale, w_shift, w1, w2, rgn, wrd, wH, rgnH, rgnL, wrdH, wrdL, wrdTH);

    // launches 1-3: attention
    gemm_score<<<dim3(MIQ / 128, C_CAP), 256, A1_SMEM>>>(rgnH, rgnL, wrdH, wrdL, S);
    attn_norm_kernel<<<dim3(I_IMG, C_CAP), 128>>>(S, lens, attnH);
    gemm_wei<<<dim3(D_EMB / 128, MIQ / 128, C_CAP), 256, A3_SMEM>>>(attnH, wrdTH, weiH);

    // launch 4: dual GEMM (scale+shift) + FiLM -> xH
    gemm_dual_film<<<dim3(D_EMB / 64, M_TOT / 128), 256, DF_SMEM>>>(
        weiH, wH + 0 * (size_t)W_ELEMS, wH + 1 * (size_t)W_ELEMS,
        b_scale, b_shift, rgn, xH);
    // launch 5: h = relu(x @ w1^T + b1) -> hH
    gemm_hmma<EPI_RELU><<<dim3(D_EMB / 128, M_TOT / 128), 256, G_SMEM>>>(
        xH, wH + 2 * (size_t)W_ELEMS, b1, nullptr, nullptr, hH);
    // launch 6: out = (h @ w2^T + b2) + rgn, transposed
    gemm_hmma<EPI_FINAL><<<dim3(D_EMB / 128, M_TOT / 128), 256, G_SMEM>>>(
        hH, wH + 3 * (size_t)W_ELEMS, b2, rgn, out, nullptr);
}

// round 17
// speedup vs baseline: 4.4824x; 1.0011x over previous
#include <cuda_runtime.h>
#include <cuda_fp16.h>
#include <math.h>
#include <stdint.h>

// Problem dims
#define I_IMG 32
#define C_CAP 32
#define Q_RGN 36
#define L_MAX 50
#define LPAD 64
#define D_EMB 1024
#define MIQ (I_IMG * Q_RGN)                    // 1152
#define M_TOT (C_CAP * MIQ)                    // 36864
#define ELEMS ((size_t)M_TOT * D_EMB)
#define W_ELEMS (D_EMB * D_EMB)

// ---------------- scratch ----------------
__device__ __align__(256) __half g_weiH[ELEMS];
__device__ __align__(256) __half g_xH[ELEMS];
__device__ __align__(256) __half g_hH[ELEMS];
__device__ __align__(256) __half g_wH[4][W_ELEMS];
__device__ __align__(256) __half g_rgnH[MIQ * D_EMB];
__device__ __align__(256) __half g_rgnL[MIQ * D_EMB];
__device__ __align__(256) __half g_wrdH[C_CAP * LPAD * D_EMB];
__device__ __align__(256) __half g_wrdL[C_CAP * LPAD * D_EMB];
__device__ __align__(256) __half g_wrdTH[C_CAP * D_EMB * LPAD];
__device__ __align__(256) float  g_S[(size_t)C_CAP * MIQ * LPAD];
__device__ __align__(256) __half g_attnH[(size_t)C_CAP * MIQ * LPAD];

__device__ __forceinline__ void split_h(float x, __half& h, __half& l) {
    h = __float2half_rn(x);
    l = __float2half_rn(x - __half2float(h));
}
__device__ __forceinline__ float tanh_hw(float x) {
    float y;
    asm("tanh.approx.f32 %0, %1;" : "=f"(y) : "f"(x));
    return y;
}

// ---------------- common HMMA infrastructure ----------------
__device__ __forceinline__ uint32_t smem_u32(const void* p) {
    uint32_t a;
    asm("{ .reg .u64 t; cvta.to.shared.u64 t, %1; cvt.u32.u64 %0, t; }"
        : "=r"(a) : "l"(p));
    return a;
}
// 64B-row tiles
__device__ __forceinline__ uint32_t sm_addr(uint32_t base, int row, int c16) {
    return base + row * 64 + (((uint32_t)(c16 ^ ((row >> 1) & 3))) << 4);
}
// 128B-row tiles
__device__ __forceinline__ uint32_t sm_addr128(uint32_t base, int row, int c16) {
    return base + row * 128 + (((uint32_t)(c16 ^ (row & 7))) << 4);
}
__device__ __forceinline__ void load_t128(
    const __half* __restrict__ g, int ld, int row0, int kcol0, uint32_t sb, int tid)
{
#pragma unroll
    for (int j = 0; j < 2; j++) {
        int id = tid + 256 * j;
        int r = id >> 2, c = id & 3;
        const void* gp = g + (size_t)(row0 + r) * ld + kcol0 + c * 8;
        asm volatile("cp.async.cg.shared.global [%0], [%1], 16;"
                     :: "r"(sm_addr(sb, r, c)), "l"(gp));
    }
}
__device__ __forceinline__ void load_t64(
    const __half* __restrict__ g, int ld, int row0, int kcol0, uint32_t sb, int tid)
{
    int r = tid >> 2, c = tid & 3;
    const void* gp = g + (size_t)(row0 + r) * ld + kcol0 + c * 8;
    asm volatile("cp.async.cg.shared.global [%0], [%1], 16;"
                 :: "r"(sm_addr(sb, r, c)), "l"(gp));
}
// 128 rows x 64 cols (128B/row)
__device__ __forceinline__ void load_t128w(
    const __half* __restrict__ g, int ld, int row0, int kcol0, uint32_t sb, int tid)
{
#pragma unroll
    for (int j = 0; j < 4; j++) {
        int id = tid + 256 * j;
        int r = id >> 3, c = id & 7;
        const void* gp = g + (size_t)(row0 + r) * ld + kcol0 + c * 8;
        asm volatile("cp.async.cg.shared.global [%0], [%1], 16;"
                     :: "r"(sm_addr128(sb, r, c)), "l"(gp));
    }
}
// 64 rows x 64 cols (128B/row)
__device__ __forceinline__ void load_t64w(
    const __half* __restrict__ g, int ld, int row0, int kcol0, uint32_t sb, int tid)
{
#pragma unroll
    for (int j = 0; j < 2; j++) {
        int id = tid + 256 * j;       // 0..511
        int r = id >> 3, c = id & 7;
        const void* gp = g + (size_t)(row0 + r) * ld + kcol0 + c * 8;
        asm volatile("cp.async.cg.shared.global [%0], [%1], 16;"
                     :: "r"(sm_addr128(sb, r, c)), "l"(gp));
    }
}

#define LDSM_X4(R, addr) \
    asm volatile("ldmatrix.sync.aligned.m8n8.x4.shared.b16 {%0,%1,%2,%3}, [%4];" \
        : "=r"((R)[0]), "=r"((R)[1]), "=r"((R)[2]), "=r"((R)[3]) : "r"(addr))
#define MMA(C, A, B) \
    asm volatile("mma.sync.aligned.m16n8k16.row.col.f32.f16.f16.f32 " \
        "{%0,%1,%2,%3}, {%4,%5,%6,%7}, {%8,%9}, {%0,%1,%2,%3};" \
        : "+f"((C)[0]), "+f"((C)[1]), "+f"((C)[2]), "+f"((C)[3]) \
        : "r"((A)[0]), "r"((A)[1]), "r"((A)[2]), "r"((A)[3]), "r"((B)[0]), "r"((B)[1]))

// ---------------------------------------------------------------------------
// prep_all: task 0-3 weight cvt, task 4 rgn split, task 5 wrd pad/split/transp
// ---------------------------------------------------------------------------
__global__ __launch_bounds__(256) void prep_all_kernel(
    const float* __restrict__ w0, const float* __restrict__ w1,
    const float* __restrict__ w2, const float* __restrict__ w3,
    const float* __restrict__ rgn, const float* __restrict__ wrd,
    __half* __restrict__ wH, __half* __restrict__ rgnH, __half* __restrict__ rgnL,
    __half* __restrict__ wh, __half* __restrict__ wl, __half* __restrict__ wth)
{
    const int task = blockIdx.y;
    const int bx = blockIdx.x;
    const int tid = threadIdx.x;
    __shared__ __align__(16) float ts[64][65];

    if (task < 4) {
        int i = bx * 256 + tid;
        if (i < W_ELEMS / 4) {
            const float* s = (task == 0) ? w0 : (task == 1) ? w1 : (task == 2) ? w2 : w3;
            float4 v = ((const float4*)s)[i];
            union { uint2 u; __half h[4]; } o;
            o.h[0] = __float2half_rn(v.x); o.h[1] = __float2half_rn(v.y);
            o.h[2] = __float2half_rn(v.z); o.h[3] = __float2half_rn(v.w);
            ((uint2*)(wH + (size_t)task * W_ELEMS))[i] = o.u;
        }
    } else if (task == 4) {
        int i = bx * 256 + tid;
        if (i < MIQ * D_EMB / 4) {
            float4 v = ((const float4*)rgn)[i];
            union { uint2 u; __half h[4]; } oh, ol;
            split_h(v.x, oh.h[0], ol.h[0]); split_h(v.y, oh.h[1], ol.h[1]);
            split_h(v.z, oh.h[2], ol.h[2]); split_h(v.w, oh.h[3], ol.h[3]);
            ((uint2*)rgnH)[i] = oh.u;
            ((uint2*)rgnL)[i] = ol.u;
        }
    } else {
        if (bx >= (D_EMB / 64) * C_CAP) return;
        const int d0 = (bx & 15) * 64;
        const int c  = bx >> 4;

        for (int idx = tid; idx < 64 * 64; idx += 256) {
            int l = idx >> 6, dd = idx & 63;
            float v = (l < L_MAX) ? wrd[((size_t)c * L_MAX + l) * D_EMB + d0 + dd] : 0.f;
            ts[l][dd] = v;
            __half h, lo; split_h(v, h, lo);
            wh[((size_t)c * LPAD + l) * D_EMB + d0 + dd] = h;
            wl[((size_t)c * LPAD + l) * D_EMB + d0 + dd] = lo;
        }
        __syncthreads();
        for (int idx = tid; idx < 64 * 64; idx += 256) {
            int d = idx >> 6, l = idx & 63;
            wth[((size_t)c * D_EMB + d0 + d) * LPAD + l] = __float2half_rn(ts[l][d]);
        }
    }
}

// ---------------------------------------------------------------------------
// A1: scores  S[c, m=(i,q), l] = leaky( rgn[m,:] . wrd[c,l,:] ), 3-term HMMA.
// ---------------------------------------------------------------------------
#define A1_STAGE (2 * 8192 + 2 * 4096)
#define A1_SMEM (3 * A1_STAGE)             // 72 KB

__global__ __launch_bounds__(256, 2) void gemm_score(
    const __half* __restrict__ Rh, const __half* __restrict__ Rl,
    const __half* __restrict__ Wh, const __half* __restrict__ Wl,
    float* __restrict__ S)
{
    extern __shared__ __align__(1024) uint8_t dsm[];
    const uint32_t sb = smem_u32(dsm);
    const int tid = threadIdx.x;
    const int wid = tid >> 5, lid = tid & 31;
    const int wm = wid & 3, wn = wid >> 2;
    const int m0 = blockIdx.x * 128;
    const int c  = blockIdx.y;

    const __half* Bh = Wh + (size_t)c * LPAD * D_EMB;
    const __half* Bl = Wl + (size_t)c * LPAD * D_EMB;

    const int a_ro = lid & 15, a_co = lid >> 4;
    const int b_ro = ((lid >> 4) & 1) * 8 + (lid & 7);
    const int b_co = (lid >> 3) & 1;

    float acc[2][4][4];
#pragma unroll
    for (int a = 0; a < 2; a++)
#pragma unroll
        for (int b = 0; b < 4; b++)
#pragma unroll
            for (int d = 0; d < 4; d++) acc[a][b][d] = 0.f;

#pragma unroll
    for (int s = 0; s < 2; s++) {
        uint32_t st = sb + s * A1_STAGE;
        load_t128(Rh, D_EMB, m0, s * 32, st, tid);
        load_t128(Rl, D_EMB, m0, s * 32, st + 8192, tid);
        load_t64(Bh, D_EMB, 0, s * 32, st + 16384, tid);
        load_t64(Bl, D_EMB, 0, s * 32, st + 20480, tid);
        asm volatile("cp.async.commit_group;");
    }

    int stage = 0;
    for (int i = 0; i < 32; i++) {
        asm volatile("cp.async.wait_group 1;");
        __syncthreads();
        if (i + 2 < 32) {
            uint32_t st = sb + ((stage + 2) % 3) * A1_STAGE;
            int kc = (i + 2) * 32;
            load_t128(Rh, D_EMB, m0, kc, st, tid);
            load_t128(Rl, D_EMB, m0, kc, st + 8192, tid);
            load_t64(Bh, D_EMB, 0, kc, st + 16384, tid);
            load_t64(Bl, D_EMB, 0, kc, st + 20480, tid);
        }
        asm volatile("cp.async.commit_group;");

        uint32_t stA = sb + stage * A1_STAGE;
#pragma unroll
        for (int ks = 0; ks < 2; ks++) {
            uint32_t aH[2][4], aL[2][4], bH[4][2], bL[4][2];
#pragma unroll
            for (int mi = 0; mi < 2; mi++) {
                LDSM_X4(aH[mi], sm_addr(stA, wm * 32 + mi * 16 + a_ro, ks * 2 + a_co));
                LDSM_X4(aL[mi], sm_addr(stA + 8192, wm * 32 + mi * 16 + a_ro, ks * 2 + a_co));
            }
#pragma unroll
            for (int p = 0; p < 2; p++) {
                uint32_t r[4];
                LDSM_X4(r, sm_addr(stA + 16384, wn * 32 + p * 16 + b_ro, ks * 2 + b_co));
                bH[2 * p][0] = r[0]; bH[2 * p][1] = r[1];
                bH[2 * p + 1][0] = r[2]; bH[2 * p + 1][1] = r[3];
                LDSM_X4(r, sm_addr(stA + 20480, wn * 32 + p * 16 + b_ro, ks * 2 + b_co));
                bL[2 * p][0] = r[0]; bL[2 * p][1] = r[1];
                bL[2 * p + 1][0] = r[2]; bL[2 * p + 1][1] = r[3];
            }
#pragma unroll
            for (int mi = 0; mi < 2; mi++)
#pragma unroll
                for (int nj = 0; nj < 4; nj++) {
                    MMA(acc[mi][nj], aH[mi], bH[nj]);
                    MMA(acc[mi][nj], aH[mi], bL[nj]);
                    MMA(acc[mi][nj], aL[mi], bH[nj]);
                }
        }
        stage = (stage + 1) % 3;
    }

    const int cph = (lid & 3) * 2;
#pragma unroll
    for (int mi = 0; mi < 2; mi++)
#pragma unroll
        for (int hf = 0; hf < 2; hf++) {
            int m = m0 + wm * 32 + mi * 16 + hf * 8 + (lid >> 2);
            float* op = S + ((size_t)c * MIQ + m) * LPAD + wn * 32 + cph;
#pragma unroll
            for (int nj = 0; nj < 4; nj++) {
                float v0 = acc[mi][nj][hf * 2 + 0];
                float v1 = acc[mi][nj][hf * 2 + 1];
                float2 o;
                o.x = (v0 >= 0.f) ? v0 : 0.1f * v0;
                o.y = (v1 >= 0.f) ? v1 : 0.1f * v1;
                *(float2*)(op + nj * 8) = o;
            }
        }
}

// ---------------------------------------------------------------------------
// A2: per (c,i): L2-normalize over q, masked softmax over l -> attn fp16.
// ---------------------------------------------------------------------------
__global__ __launch_bounds__(128) void attn_norm_kernel(
    const float* __restrict__ S, const int* __restrict__ lens,
    __half* __restrict__ attnH)
{
    const int i = blockIdx.x;
    const int c = blockIdx.y;
    const int tid = threadIdx.x;
    __shared__ __align__(16) float s[Q_RGN][68];
    __shared__ __align__(16) float sinv[LPAD];
    __shared__ __align__(16) __half ah[Q_RGN * LPAD];

    const size_t base = ((size_t)c * MIQ + i * Q_RGN) * LPAD;

    for (int idx = tid; idx < Q_RGN * 16; idx += 128) {
        int q = idx >> 4, f4 = idx & 15;
        float4 v = *(const float4*)(S + base + q * LPAD + f4 * 4);
        *(float4*)&s[q][f4 * 4] = v;
    }
    __syncthreads();

    {
        const int l = tid >> 1, hf = tid & 1;
        float ss = 0.f;
        for (int q = hf * 18; q < hf * 18 + 18; q++) {
            float v = s[q][l]; ss += v * v;
        }
        ss += __shfl_xor_sync(0xffffffffu, ss, 1);
        if (hf == 0) sinv[l] = 1.f / fmaxf(sqrtf(ss), 1e-12f);
    }
    __syncthreads();

    const int len = lens[c];
    {
        const int q = tid >> 1, hf = tid & 1;
        const bool act = (q < Q_RGN);
        const int l0 = hf * 32;
        const int l1 = min(len, l0 + 32);
        float mx = -1e30f;
        if (act)
            for (int l = l0; l < l1; l++) mx = fmaxf(mx, s[q][l] * sinv[l]);
        mx = fmaxf(mx, __shfl_xor_sync(0xffffffffu, mx, 1));
        float sum = 0.f;
        if (act)
            for (int l = l0; l < l1; l++) {
                float e = expf(9.f * (s[q][l] * sinv[l] - mx));
                s[q][l] = e;
                sum += e;
            }
        sum += __shfl_xor_sync(0xffffffffu, sum, 1);
        if (act) {
            float inv = 1.f / sum;
            for (int l = l0; l < l0 + 32; l++)
                ah[q * LPAD + l] = __float2half_rn((l < l1) ? s[q][l] * inv : 0.f);
        }
    }
    __syncthreads();

    for (int u = tid; u < Q_RGN * LPAD / 8; u += 128)
        *(uint4*)(attnH + base + u * 8) = *(const uint4*)(ah + u * 8);
}

// ---------------------------------------------------------------------------
// A3: wei = attn @ wrdT^T; 1-term fp16, single-stage K=64.
// CTA tile 128x64, warp tile 32x32, low regs -> 3 CTAs/SM.
// ---------------------------------------------------------------------------
#define A3_SMEM (16384 + 8192)             // A 16 KB + B 8 KB

__global__ __launch_bounds__(256, 3) void gemm_wei(
    const __half* __restrict__ AH, const __half* __restrict__ WTH,
    __half* __restrict__ weiH)
{
    extern __shared__ __align__(1024) uint8_t dsm[];
    const uint32_t sb = smem_u32(dsm);
    const int tid = threadIdx.x;
    const int wid = tid >> 5, lid = tid & 31;
    const int wm = wid & 3, wn = wid >> 2;      // 4x32 m, 2x32 n
    const int n0 = blockIdx.x * 64;
    const int m0 = blockIdx.y * 128;
    const int c  = blockIdx.z;

    const __half* Ah = AH + (size_t)c * MIQ * LPAD;
    const __half* Bh = WTH + (size_t)c * D_EMB * LPAD;

    const int a_ro = lid & 15, a_co = lid >> 4;
    const int b_ro = ((lid >> 4) & 1) * 8 + (lid & 7);
    const int b_co = (lid >> 3) & 1;

    float acc[2][4][4];
#pragma unroll
    for (int a = 0; a < 2; a++)
#pragma unroll
        for (int b = 0; b < 4; b++)
#pragma unroll
            for (int d = 0; d < 4; d++) acc[a][b][d] = 0.f;

    // one-shot load: A 128x64, B 64x64 (128B rows, 128B swizzle)
    load_t128w(Ah, LPAD, m0, 0, sb, tid);
    load_t64w(Bh, LPAD, n0, 0, sb + 16384, tid);
    asm volatile("cp.async.commit_group;");
    asm volatile("cp.async.wait_group 0;");
    __syncthreads();

#pragma unroll
    for (int ks = 0; ks < 4; ks++) {
        uint32_t aH[2][4], bH[4][2];
#pragma unroll
        for (int mi = 0; mi < 2; mi++)
            LDSM_X4(aH[mi], sm_addr128(sb, wm * 32 + mi * 16 + a_ro, ks * 2 + a_co));
#pragma unroll
        for (int p = 0; p < 2; p++) {
            uint32_t r[4];
            LDSM_X4(r, sm_addr128(sb + 16384, wn * 32 + p * 16 + b_ro, ks * 2 + b_co));
            bH[2 * p][0] = r[0]; bH[2 * p][1] = r[1];
            bH[2 * p + 1][0] = r[2]; bH[2 * p + 1][1] = r[3];
        }
#pragma unroll
        for (int mi = 0; mi < 2; mi++)
#pragma unroll
            for (int nj = 0; nj < 4; nj++)
                MMA(acc[mi][nj], aH[mi], bH[nj]);
    }

    const int cph = (lid & 3) * 2;
    const int nbase = n0 + wn * 32;
#pragma unroll
    for (int mi = 0; mi < 2; mi++)
#pragma unroll
        for (int hf = 0; hf < 2; hf++) {
            int m = m0 + wm * 32 + mi * 16 + hf * 8 + (lid >> 2);
            __half* op = weiH + ((size_t)c * MIQ + m) * D_EMB + nbase + cph;
#pragma unroll
            for (int nj = 0; nj < 4; nj++)
                *(__half2*)(op + nj * 8) = __halves2half2(
                    __float2half_rn(acc[mi][nj][hf * 2 + 0]),
                    __float2half_rn(acc[mi][nj][hf * 2 + 1]));
        }
}

// ---------------------------------------------------------------------------
// Dual GEMM + FiLM: x = rgn*tanh(wei@w_sc^T + b_sc) + (wei@w_sh^T + b_sh)
// CTA tile 128x64 (warp tile 32x32), BK=64, 2 CTAs/SM.
// ---------------------------------------------------------------------------
#define DF_STAGE (16384 + 2 * 8192)        // A 16 KB + Bsc 8 KB + Bsh 8 KB
#define DF_SMEM (3 * DF_STAGE)             // 96 KB

__global__ __launch_bounds__(256, 2) void gemm_dual_film(
    const __half* __restrict__ Ah,
    const __half* __restrict__ Bsc, const __half* __restrict__ Bsh,
    const float* __restrict__ bias_sc, const float* __restrict__ bias_sh,
    const float* __restrict__ rgn,
    __half* __restrict__ outH)
{
    extern __shared__ __align__(1024) uint8_t dsm[];
    const uint32_t sb = smem_u32(dsm);
    const int tid = threadIdx.x;
    const int wid = tid >> 5, lid = tid & 31;
    const int wm = wid & 3, wn = wid >> 2;
    const int m0 = blockIdx.y * 128;
    const int n0 = blockIdx.x * 64;

    const int a_ro = lid & 15, a_co = lid >> 4;
    const int b_ro = ((lid >> 4) & 1) * 8 + (lid & 7);
    const int b_co = (lid >> 3) & 1;

    float asc[2][4][4], ash[2][4][4];
#pragma unroll
    for (int a = 0; a < 2; a++)
#pragma unroll
        for (int b = 0; b < 4; b++)
#pragma unroll
            for (int d = 0; d < 4; d++) { asc[a][b][d] = 0.f; ash[a][b][d] = 0.f; }

#pragma unroll
    for (int s = 0; s < 2; s++) {
        uint32_t st = sb + s * DF_STAGE;
        load_t128w(Ah,  D_EMB, m0, s * 64, st, tid);
        load_t64w(Bsc, D_EMB, n0, s * 64, st + 16384, tid);
        load_t64w(Bsh, D_EMB, n0, s * 64, st + 24576, tid);
        asm volatile("cp.async.commit_group;");
    }

    int stage = 0;
    for (int i = 0; i < 16; i++) {
        asm volatile("cp.async.wait_group 1;");
        __syncthreads();
        if (i + 2 < 16) {
            uint32_t st = sb + ((stage + 2) % 3) * DF_STAGE;
            int kc = (i + 2) * 64;
            load_t128w(Ah,  D_EMB, m0, kc, st, tid);
            load_t64w(Bsc, D_EMB, n0, kc, st + 16384, tid);
            load_t64w(Bsh, D_EMB, n0, kc, st + 24576, tid);
        }
        asm volatile("cp.async.commit_group;");

        uint32_t stA = sb + stage * DF_STAGE;
#pragma unroll
        for (int ks = 0; ks < 4; ks++) {
            uint32_t aH[2][4], bc[4][2], bs[4][2];
#pragma unroll
            for (int mi = 0; mi < 2; mi++)
                LDSM_X4(aH[mi], sm_addr128(stA, wm * 32 + mi * 16 + a_ro, ks * 2 + a_co));
#pragma unroll
            for (int p = 0; p < 2; p++) {
                uint32_t r[4];
                LDSM_X4(r, sm_addr128(stA + 16384, wn * 32 + p * 16 + b_ro, ks * 2 + b_co));
                bc[2 * p][0] = r[0]; bc[2 * p][1] = r[1];
                bc[2 * p + 1][0] = r[2]; bc[2 * p + 1][1] = r[3];
                LDSM_X4(r, sm_addr128(stA + 24576, wn * 32 + p * 16 + b_ro, ks * 2 + b_co));
                bs[2 * p][0] = r[0]; bs[2 * p][1] = r[1];
                bs[2 * p + 1][0] = r[2]; bs[2 * p + 1][1] = r[3];
            }
#pragma unroll
            for (int mi = 0; mi < 2; mi++)
#pragma unroll
                for (int nj = 0; nj < 4; nj++) {
                    MMA(asc[mi][nj], aH[mi], bc[nj]);
                    MMA(ash[mi][nj], aH[mi], bs[nj]);
                }
        }
        stage = (stage + 1) % 3;
    }

    const int nbase = n0 + wn * 32;
    const int mbase = m0 + wm * 32;
    const int cph = (lid & 3) * 2;

    float2 bcv[4], bsv[4];
#pragma unroll
    for (int nj = 0; nj < 4; nj++) {
        bcv[nj] = *(const float2*)(bias_sc + nbase + nj * 8 + cph);
        bsv[nj] = *(const float2*)(bias_sh + nbase + nj * 8 + cph);
    }

#pragma unroll
    for (int mi = 0; mi < 2; mi++) {
#pragma unroll
        for (int hf = 0; hf < 2; hf++) {
            const int m = mbase + mi * 16 + hf * 8 + (lid >> 2);
            const int t = m / Q_RGN;
            const int q = m - t * Q_RGN;
            const int i_img = t & (I_IMG - 1);
            const float* rp = rgn + ((size_t)(i_img * Q_RGN + q)) * D_EMB + nbase + cph;
            size_t ob = (size_t)m * D_EMB + nbase + cph;
#pragma unroll
            for (int nj = 0; nj < 4; nj++) {
                float2 rv = *(const float2*)(rp + nj * 8);
                float sc0 = tanh_hw(asc[mi][nj][hf * 2 + 0] + bcv[nj].x);
                float sc1 = tanh_hw(asc[mi][nj][hf * 2 + 1] + bcv[nj].y);
                float x0 = rv.x * sc0 + (ash[mi][nj][hf * 2 + 0] + bsv[nj].x);
                float x1 = rv.y * sc1 + (ash[mi][nj][hf * 2 + 1] + bsv[nj].y);
                *(__half2*)(outH + ob + nj * 8) =
                    __halves2half2(__float2half_rn(x0), __float2half_rn(x1));
            }
        }
    }
}

// ---------------------------------------------------------------------------
// Main HMMA GEMM (plain fp16, BK=64, 128B-row swizzle, 2 CTAs/SM)
// ---------------------------------------------------------------------------
#define EPI_RELU 2
#define EPI_FINAL 3

#define G_TILE 16384
#define G_STAGE (2 * G_TILE)
#define G_SMEM (3 * G_STAGE)               // 96 KB

template <int EPI>
__global__ __launch_bounds__(256, 2) void gemm_hmma(
    const __half* __restrict__ Ah, const __half* __restrict__ Bh,
    const float* __restrict__ bias,
    const float* __restrict__ rgn,
    float* __restrict__ outF,
    __half* __restrict__ outH)
{
    extern __shared__ __align__(1024) uint8_t dsm[];
    const uint32_t sb = smem_u32(dsm);
    const int tid = threadIdx.x;
    const int wid = tid >> 5, lid = tid & 31;
    const int wm = wid & 3, wn = wid >> 2;
    const int m0 = blockIdx.y * 128;
    const int n0 = blockIdx.x * 128;

    const int a_ro = lid & 15, a_co = lid >> 4;
    const int b_ro = ((lid >> 4) & 1) * 8 + (lid & 7);
    const int b_co = (lid >> 3) & 1;

    float c[2][8][4];
#pragma unroll
    for (int a = 0; a < 2; a++)
#pragma unroll
        for (int b = 0; b < 8; b++)
#pragma unroll
            for (int d = 0; d < 4; d++) c[a][b][d] = 0.f;

#pragma unroll
    for (int s = 0; s < 2; s++) {
        uint32_t st = sb + s * G_STAGE;
        load_t128w(Ah, D_EMB, m0, s * 64, st, tid);
        load_t128w(Bh, D_EMB, n0, s * 64, st + G_TILE, tid);
        asm volatile("cp.async.commit_group;");
    }

    int stage = 0;
    for (int i = 0; i < 16; i++) {
        asm volatile("cp.async.wait_group 1;");
        __syncthreads();
        if (i + 2 < 16) {
            uint32_t st = sb + ((stage + 2) % 3) * G_STAGE;
            int kc = (i + 2) * 64;
            load_t128w(Ah, D_EMB, m0, kc, st, tid);
            load_t128w(Bh, D_EMB, n0, kc, st + G_TILE, tid);
        }
        asm volatile("cp.async.commit_group;");

        uint32_t stA = sb + stage * G_STAGE;
#pragma unroll
        for (int ks = 0; ks < 4; ks++) {
            uint32_t aH[2][4], bH[8][2];
#pragma unroll
            for (int mi = 0; mi < 2; mi++)
                LDSM_X4(aH[mi], sm_addr128(stA, wm * 32 + mi * 16 + a_ro, ks * 2 + a_co));
#pragma unroll
            for (int p = 0; p < 4; p++) {
                uint32_t r[4];
                LDSM_X4(r, sm_addr128(stA + G_TILE, wn * 64 + p * 16 + b_ro, ks * 2 + b_co));
                bH[2 * p][0] = r[0]; bH[2 * p][1] = r[1];
                bH[2 * p + 1][0] = r[2]; bH[2 * p + 1][1] = r[3];
            }
#pragma unroll
            for (int mi = 0; mi < 2; mi++)
#pragma unroll
                for (int nj = 0; nj < 8; nj++)
                    MMA(c[mi][nj], aH[mi], bH[nj]);
        }
        stage = (stage + 1) % 3;
    }

    const int nbase = n0 + wn * 64;
    const int mbase = m0 + wm * 32;
    const int cph = (lid & 3) * 2;

    float2 bv[8];
#pragma unroll
    for (int nj = 0; nj < 8; nj++)
        bv[nj] = *(const float2*)(bias + nbase + nj * 8 + cph);

#pragma unroll
    for (int mi = 0; mi < 2; mi++) {
#pragma unroll
        for (int hf = 0; hf < 2; hf++) {
            const int m = mbase + mi * 16 + hf * 8 + (lid >> 2);
            const int t = m / Q_RGN;
            const int q = m - t * Q_RGN;
            const int i_img = t & (I_IMG - 1);
            const int cc = t >> 5;

            if (EPI == EPI_RELU) {
                size_t ob = (size_t)m * D_EMB + nbase + cph;
#pragma unroll
                for (int nj = 0; nj < 8; nj++) {
                    float x0 = fmaxf(c[mi][nj][hf * 2 + 0] + bv[nj].x, 0.f);
                    float x1 = fmaxf(c[mi][nj][hf * 2 + 1] + bv[nj].y, 0.f);
                    *(__half2*)(outH + ob + nj * 8) =
                        __halves2half2(__float2half_rn(x0), __float2half_rn(x1));
                }
            } else {
                const float* rp = rgn + ((size_t)(i_img * Q_RGN + q)) * D_EMB + nbase + cph;
                float* op = outF + (((size_t)(i_img * C_CAP + cc)) * Q_RGN + q) * D_EMB + nbase + cph;
#pragma unroll
                for (int nj = 0; nj < 8; nj++) {
                    float2 rv = *(const float2*)(rp + nj * 8);
                    float2 o;
                    o.x = c[mi][nj][hf * 2 + 0] + bv[nj].x + rv.x;
                    o.y = c[mi][nj][hf * 2 + 1] + bv[nj].y + rv.y;
                    *(float2*)(op + nj * 8) = o;
                }
            }
        }
    }
}

// ---------------------------------------------------------------------------
extern "C" void kernel_launch(void* const* d_in, const int* in_sizes, int n_in,
                              void* d_out, int out_size)
{
    const float* rgn     = (const float*)d_in[0];
    const float* wrd     = (const float*)d_in[2];
    const int*   lens    = (const int*)d_in[4];
    const float* w_scale = (const float*)d_in[5];
    const float* b_scale = (const float*)d_in[6];
    const float* w_shift = (const float*)d_in[7];
    const float* b_shift = (const float*)d_in[8];
    const float* w1      = (const float*)d_in[9];
    const float* b1      = (const float*)d_in[10];
    const float* w2      = (const float*)d_in[11];
    const float* b2      = (const float*)d_in[12];
    float* out = (float*)d_out;

    __half *weiH, *xH, *hH, *wH, *rgnH, *rgnL, *wrdH, *wrdL, *wrdTH, *attnH;
    float *S;
    cudaGetSymbolAddress((void**)&weiH,  g_weiH);
    cudaGetSymbolAddress((void**)&xH,    g_xH);
    cudaGetSymbolAddress((void**)&hH,    g_hH);
    cudaGetSymbolAddress((void**)&wH,    g_wH);
    cudaGetSymbolAddress((void**)&rgnH,  g_rgnH);
    cudaGetSymbolAddress((void**)&rgnL,  g_rgnL);
    cudaGetSymbolAddress((void**)&wrdH,  g_wrdH);
    cudaGetSymbolAddress((void**)&wrdL,  g_wrdL);
    cudaGetSymbolAddress((void**)&wrdTH, g_wrdTH);
    cudaGetSymbolAddress((void**)&attnH, g_attnH);
    cudaGetSymbolAddress((void**)&S,     g_S);

    cudaFuncSetAttribute(gemm_score, cudaFuncAttributeMaxDynamicSharedMemorySize, A1_SMEM);
    cudaFuncSetAttribute(gemm_wei,   cudaFuncAttributeMaxDynamicSharedMemorySize, A3_SMEM);
    cudaFuncSetAttribute(gemm_dual_film, cudaFuncAttributeMaxDynamicSharedMemorySize, DF_SMEM);
    cudaFuncSetAttribute(gemm_hmma<EPI_RELU>,  cudaFuncAttributeMaxDynamicSharedMemorySize, G_SMEM);
    cudaFuncSetAttribute(gemm_hmma<EPI_FINAL>, cudaFuncAttributeMaxDynamicSharedMemorySize, G_SMEM);

    // launch 0: all preps
    prep_all_kernel<<<dim3(1152, 6), 256>>>(
        w_scale, w_shift, w1, w2, rgn, wrd, wH, rgnH, rgnL, wrdH, wrdL, wrdTH);

    // launches 1-3: attention
    gemm_score<<<dim3(MIQ / 128, C_CAP), 256, A1_SMEM>>>(rgnH, rgnL, wrdH, wrdL, S);
    attn_norm_kernel<<<dim3(I_IMG, C_CAP), 128>>>(S, lens, attnH);
    gemm_wei<<<dim3(D_EMB / 64, MIQ / 128, C_CAP), 256, A3_SMEM>>>(attnH, wrdTH, weiH);

    // launch 4: dual GEMM (scale+shift) + FiLM -> xH
    gemm_dual_film<<<dim3(D_EMB / 64, M_TOT / 128), 256, DF_SMEM>>>(
        weiH, wH + 0 * (size_t)W_ELEMS, wH + 1 * (size_t)W_ELEMS,
        b_scale, b_shift, rgn, xH);
    // launch 5: h = relu(x @ w1^T + b1) -> hH
    gemm_hmma<EPI_RELU><<<dim3(D_EMB / 128, M_TOT / 128), 256, G_SMEM>>>(
        xH, wH + 2 * (size_t)W_ELEMS, b1, nullptr, nullptr, hH);
    // launch 6: out = (h @ w2^T + b2) + rgn, transposed
    gemm_hmma<EPI_FINAL><<<dim3(D_EMB / 128, M_TOT / 128), 256, G_SMEM>>>(
        hH, wH + 3 * (size_t)W_ELEMS, b2, rgn, out, nullptr);
}